// round 2
// baseline (speedup 1.0000x reference)
#include <cuda_runtime.h>
#include <math.h>

#define NEGV (-10000.0f)

// ---------------- device scratch ----------------
__device__ float g_q[16*128*128];
__device__ float g_k[16*128*128];
__device__ float g_v[16*128*128];
__device__ float g_w1T[128*128];
__device__ float g_w2T[128*128];
__device__ float g_pe2T[32*128];
__device__ float g_e2T[32*128];
__device__ float g_x1T[128*32];
__device__ float g_wqT[64*128];
__device__ float g_wkT[64*128];
__device__ float g_wvT[64*128];
__device__ float g_avec[16*128*32];
__device__ float g_bvec[16*128*32];

// ---------------- helpers ----------------
__device__ __forceinline__ float wsum(float v){
#pragma unroll
    for (int k = 16; k > 0; k >>= 1) v += __shfl_xor_sync(0xffffffffu, v, k);
    return v;
}
__device__ __forceinline__ float hsum16(float v){
#pragma unroll
    for (int k = 8; k > 0; k >>= 1) v += __shfl_xor_sync(0xffffffffu, v, k);
    return v;
}
__device__ __forceinline__ unsigned long long pk2(float x, float y){
    unsigned long long r;
    asm("mov.b64 %0, {%1, %2};" : "=l"(r) : "f"(x), "f"(y));
    return r;
}
__device__ __forceinline__ void fma2(unsigned long long &d, unsigned long long a, unsigned long long b){
    asm("fma.rn.f32x2 %0, %1, %2, %0;" : "+l"(d) : "l"(a), "l"(b));
}
__device__ __forceinline__ float2 upk2(unsigned long long v){
    float2 f;
    asm("mov.b64 {%0, %1}, %2;" : "=f"(f.x), "=f"(f.y) : "l"(v));
    return f;
}

// 128x128x128 GEMM from shared: OUT[j][c] = sum_m IN[j][m] * WT[m][c]
// 256 threads, each computes an 8x8 tile via f32x2 packed FMAs.
__device__ __forceinline__ void gemm_tile(const float* __restrict__ sIn,
                                          const float* __restrict__ sWt,
                                          int j0, int c0,
                                          unsigned long long acc[8][4]){
#pragma unroll
    for (int r = 0; r < 8; r++)
#pragma unroll
        for (int s = 0; s < 4; s++) acc[r][s] = 0ull;

#pragma unroll 2
    for (int m = 0; m < 128; m += 4){
        float4 av[8];
#pragma unroll
        for (int r = 0; r < 8; r++)
            av[r] = *(const float4*)(sIn + (j0 + r)*128 + m);
#pragma unroll
        for (int mm = 0; mm < 4; mm++){
            const ulonglong2* bp = (const ulonglong2*)(sWt + (m + mm)*128 + c0);
            ulonglong2 b0 = bp[0];
            ulonglong2 b1 = bp[1];
#pragma unroll
            for (int r = 0; r < 8; r++){
                float a = (mm == 0) ? av[r].x : (mm == 1) ? av[r].y : (mm == 2) ? av[r].z : av[r].w;
                unsigned long long a2 = pk2(a, a);
                fma2(acc[r][0], a2, b0.x);
                fma2(acc[r][1], a2, b0.y);
                fma2(acc[r][2], a2, b1.x);
                fma2(acc[r][3], a2, b1.y);
            }
        }
    }
}

// ---------------- K0: weight transposes ----------------
__global__ void k0_prep(const float* __restrict__ wq, const float* __restrict__ wk,
                        const float* __restrict__ wv, const float* __restrict__ w1,
                        const float* __restrict__ w2, const float* __restrict__ pe2,
                        const float* __restrict__ e2, const float* __restrict__ x1){
    int idx = blockIdx.x * blockDim.x + threadIdx.x;
    int stride = gridDim.x * blockDim.x;
    for (int t = idx; t < 16384; t += stride){
        int c = t >> 7, m = t & 127;
        g_w1T[m*128 + c] = w1[t];
        g_w2T[m*128 + c] = w2[t];
    }
    for (int t = idx; t < 4096; t += stride){
        int c = t >> 5, m = t & 31;
        g_pe2T[m*128 + c] = pe2[t];  // pe2 [128][32] -> [32][128]
        g_e2T [m*128 + c] = e2[t];   // e2  [128][32] -> [32][128]
        int m2 = t >> 7, c2 = t & 127;
        g_x1T[c2*32 + m2] = x1[t];   // x1 [32][128] -> [128][32]
    }
    for (int t = idx; t < 8192; t += stride){
        int c = t >> 6, d = t & 63;
        g_wqT[d*128 + c] = wq[t];
        g_wkT[d*128 + c] = wk[t];
        g_wvT[d*128 + c] = wv[t];
    }
}

// ---------------- K1: q,k,v projections ----------------
__global__ void __launch_bounds__(128) k1_qkv(const float* __restrict__ x,
                                              const float* __restrict__ bq,
                                              const float* __restrict__ bk,
                                              const float* __restrict__ bv){
    __shared__ float sx[64];
    int row = blockIdx.x;
    int c = threadIdx.x;
    if (c < 64) sx[c] = x[(size_t)row*64 + c];
    __syncthreads();
    float aq = bq[c], ak = bk[c], av = bv[c];
#pragma unroll 8
    for (int d = 0; d < 64; d++){
        float xv = sx[d];
        aq = fmaf(xv, g_wqT[d*128 + c], aq);
        ak = fmaf(xv, g_wkT[d*128 + c], ak);
        av = fmaf(xv, g_wvT[d*128 + c], av);
    }
    g_q[(size_t)row*128 + c] = aq;
    g_k[(size_t)row*128 + c] = ak;
    g_v[(size_t)row*128 + c] = av;
}

// ---------------- K2: fused attention per (n,i) ----------------
__global__ void __launch_bounds__(256) k2_attn(
    const float* __restrict__ U, const float* __restrict__ p,
    const float* __restrict__ ln1_g, const float* __restrict__ ln1_b,
    const float* __restrict__ b1,
    const float* __restrict__ ln2_g, const float* __restrict__ ln2_b,
    const float* __restrict__ b2,
    const float* __restrict__ pe1,
    float* __restrict__ xout)
{
    extern __shared__ float sm[];
    float* sA   = sm;            // 16384: U + eqpe
    float* sH   = sm + 16384;    // 16384: activations / logits
    float* sW   = sm + 32768;    // 16384: current weight (pe2T -> w1T -> w2T)
    float* sk   = sm + 49152;    // 128
    float* sg1  = sm + 49280;
    float* sb1v = sm + 49408;
    float* sg2  = sm + 49536;
    float* sb2v = sm + 49664;
    float* sbi1 = sm + 49792;
    float* sbi2 = sm + 49920;
    float* spe1 = sm + 50048;
    float* spij = sm + 50176;    // 512
    float* sred = sm + 50688;    // 512

    const int tid = threadIdx.x;
    const int lane = tid & 31, warp = tid >> 5;
    const int n = blockIdx.x >> 7, i = blockIdx.x & 127;

    // ----- stage 0: small loads -----
    if (tid < 128){
        size_t rowk = (size_t)(n*128 + i);
        sk[tid]   = g_k[rowk*128 + tid];
        sg1[tid]  = ln1_g[tid];  sb1v[tid] = ln1_b[tid];
        sg2[tid]  = ln2_g[tid];  sb2v[tid] = ln2_b[tid];
        sbi1[tid] = b1[tid];     sbi2[tid] = b2[tid];
        spe1[tid] = pe1[tid];
        int j = tid;
        float4 pi = *(const float4*)(p + (size_t)(n*128 + i)*4);
        float4 pj = *(const float4*)(p + (size_t)(n*128 + j)*4);
        spij[j*4+0] = pi.x - pj.x;
        spij[j*4+1] = pi.y - pj.y;
        spij[j*4+2] = pi.z - pj.z;
        spij[j*4+3] = pi.w - pj.w;
    }
    for (int t = tid; t < 4096; t += 256) sW[t] = g_pe2T[t];
    const bool pad_i = (p[(size_t)(n*128 + i)*4] == 0.0f);
    __syncthreads();

    // ----- stage 1: eqpe -> sA = U + eqpe -----
    const float* Ub = U + (size_t)blockIdx.x * 128 * 128;
    float4 pe1r = ((const float4*)spe1)[lane];
    for (int jj = warp; jj < 128; jj += 8){
        float4 pd = *(const float4*)(spij + jj*4);
        float t = pd.x*pe1r.x + pd.y*pe1r.y + pd.z*pe1r.z + pd.w*pe1r.w;
        float mu = wsum(t) * (1.0f/32.0f);
        float dd = t - mu;
        float var = wsum(dd*dd) * (1.0f/32.0f);
        float tn = fmaxf(dd * rsqrtf(var + 1e-5f), 0.0f);
        float e0 = 0, e1v = 0, e2v = 0, e3v = 0;
#pragma unroll
        for (int m = 0; m < 32; m++){
            float tm = __shfl_sync(0xffffffffu, tn, m);
            const float* pr = sW + m*128 + lane;
            e0  = fmaf(tm, pr[0],  e0);
            e1v = fmaf(tm, pr[32], e1v);
            e2v = fmaf(tm, pr[64], e2v);
            e3v = fmaf(tm, pr[96], e3v);
        }
        float mu2 = wsum(e0 + e1v + e2v + e3v) * (1.0f/128.0f);
        float d0 = e0 - mu2, d1 = e1v - mu2, d2 = e2v - mu2, d3 = e3v - mu2;
        float v2 = wsum(d0*d0 + d1*d1 + d2*d2 + d3*d3) * (1.0f/128.0f);
        float rs = rsqrtf(v2 + 1e-5f);
        const float* Up = Ub + jj*128;
        sA[jj*128 + lane]      = Up[lane]      + fmaxf(d0*rs, 0.0f);
        sA[jj*128 + lane + 32] = Up[lane + 32] + fmaxf(d1*rs, 0.0f);
        sA[jj*128 + lane + 64] = Up[lane + 64] + fmaxf(d2*rs, 0.0f);
        sA[jj*128 + lane + 96] = Up[lane + 96] + fmaxf(d3*rs, 0.0f);
    }
    __syncthreads();

    // ----- stage 2: h1 = relu(ln(k_i - q_j + A, g1,b1)) -> sH ; load w1T -> sW -----
    const float* qb = g_q + (size_t)n*128*128;
    for (int jj = warp; jj < 128; jj += 8){
        const float* qp = qb + jj*128;
        float r0 = sk[lane]      - qp[lane]      + sA[jj*128 + lane];
        float r1 = sk[lane + 32] - qp[lane + 32] + sA[jj*128 + lane + 32];
        float r2 = sk[lane + 64] - qp[lane + 64] + sA[jj*128 + lane + 64];
        float r3 = sk[lane + 96] - qp[lane + 96] + sA[jj*128 + lane + 96];
        float mu = wsum(r0 + r1 + r2 + r3) * (1.0f/128.0f);
        float d0 = r0 - mu, d1 = r1 - mu, d2 = r2 - mu, d3 = r3 - mu;
        float var = wsum(d0*d0 + d1*d1 + d2*d2 + d3*d3) * (1.0f/128.0f);
        float rs = rsqrtf(var + 1e-5f);
        sH[jj*128 + lane]      = fmaxf(fmaf(d0*rs, sg1[lane],      sb1v[lane]),      0.0f);
        sH[jj*128 + lane + 32] = fmaxf(fmaf(d1*rs, sg1[lane + 32], sb1v[lane + 32]), 0.0f);
        sH[jj*128 + lane + 64] = fmaxf(fmaf(d2*rs, sg1[lane + 64], sb1v[lane + 64]), 0.0f);
        sH[jj*128 + lane + 96] = fmaxf(fmaf(d3*rs, sg1[lane + 96], sb1v[lane + 96]), 0.0f);
    }
    for (int t = tid; t < 16384; t += 256) sW[t] = g_w1T[t];
    __syncthreads();

    const int ty = tid >> 4, tx = tid & 15;
    const int j0 = ty*8, c0 = tx*8;
    unsigned long long acc[8][4];

    // ----- GEMM1 + epilogue: +b1, LN(g2,b2), relu -> sH -----
    gemm_tile(sH, sW, j0, c0, acc);
    __syncthreads();
    {
        float h[8][8];
#pragma unroll
        for (int r = 0; r < 8; r++)
#pragma unroll
            for (int s = 0; s < 4; s++){
                float2 f = upk2(acc[r][s]);
                h[r][2*s]   = f.x + sbi1[c0 + 2*s];
                h[r][2*s+1] = f.y + sbi1[c0 + 2*s + 1];
            }
        float gg[8], bb[8];
#pragma unroll
        for (int s = 0; s < 8; s++){ gg[s] = sg2[c0 + s]; bb[s] = sb2v[c0 + s]; }
#pragma unroll
        for (int r = 0; r < 8; r++){
            float s8 = 0;
#pragma unroll
            for (int s = 0; s < 8; s++) s8 += h[r][s];
            float mu = hsum16(s8) * (1.0f/128.0f);
            float q8 = 0;
#pragma unroll
            for (int s = 0; s < 8; s++){ float dd = h[r][s] - mu; q8 += dd*dd; }
            float rs = rsqrtf(hsum16(q8) * (1.0f/128.0f) + 1e-5f);
#pragma unroll
            for (int s = 0; s < 8; s++)
                h[r][s] = fmaxf(fmaf((h[r][s] - mu)*rs, gg[s], bb[s]), 0.0f);
            *(float4*)(sH + (j0+r)*128 + c0)     = make_float4(h[r][0], h[r][1], h[r][2], h[r][3]);
            *(float4*)(sH + (j0+r)*128 + c0 + 4) = make_float4(h[r][4], h[r][5], h[r][6], h[r][7]);
        }
    }
    for (int t = tid; t < 16384; t += 256) sW[t] = g_w2T[t];
    __syncthreads();

    // ----- GEMM2 + epilogue: +b2, mask -> logits in sH -----
    gemm_tile(sH, sW, j0, c0, acc);
    __syncthreads();
    {
#pragma unroll
        for (int r = 0; r < 8; r++){
            float o[8];
#pragma unroll
            for (int s = 0; s < 4; s++){
                float2 f = upk2(acc[r][s]);
                o[2*s]   = f.x + sbi2[c0 + 2*s];
                o[2*s+1] = f.y + sbi2[c0 + 2*s + 1];
            }
            if (pad_i){
#pragma unroll
                for (int s = 0; s < 8; s++) o[s] = NEGV;
            }
            *(float4*)(sH + (j0+r)*128 + c0)     = make_float4(o[0], o[1], o[2], o[3]);
            *(float4*)(sH + (j0+r)*128 + c0 + 4) = make_float4(o[4], o[5], o[6], o[7]);
        }
    }
    __syncthreads();

    // ----- softmax over j (per c) + weighted sum of xv = v_j + A -----
    {
        const int c = tid & 127, half = tid >> 7;
        const int jb = half * 64;
        float M = -3.4e38f;
        for (int j = jb; j < jb + 64; j++) M = fmaxf(M, sH[j*128 + c]);
        sred[half*128 + c] = M;
        __syncthreads();
        M = fmaxf(sred[c], sred[128 + c]);
        __syncthreads();
        float den = 0, num = 0;
        const float* vp = g_v + (size_t)n*128*128;
        for (int j = jb; j < jb + 64; j++){
            float w = __expf(sH[j*128 + c] - M);
            den += w;
            num = fmaf(w, vp[j*128 + c] + sA[j*128 + c], num);
        }
        sred[half*128 + c]       = den;
        sred[256 + half*128 + c] = num;
        __syncthreads();
        if (half == 0){
            float dtot = sred[c] + sred[128 + c];
            float ntot = sred[256 + c] + sred[384 + c];
            xout[(size_t)blockIdx.x*128 + c] = ntot / dtot;
        }
    }
}

// ---------------- K2b: avec/bvec = e1 row projections of x_out ----------------
__global__ void __launch_bounds__(64) k2b_vec(const float* __restrict__ xout,
                                              const float* __restrict__ e1){
    __shared__ float sx[128];
    int row = blockIdx.x;
    int tid = threadIdx.x;
    sx[tid]      = xout[(size_t)row*128 + tid];
    sx[tid + 64] = xout[(size_t)row*128 + tid + 64];
    __syncthreads();
    int lane = tid & 31;
    const float* er = e1 + lane*257 + ((tid >= 32) ? 128 : 0);
    float a = 0;
#pragma unroll 8
    for (int c2 = 0; c2 < 128; c2++) a = fmaf(sx[c2], er[c2], a);
    if (tid < 32) g_avec[(size_t)row*32 + lane] = a;
    else          g_bvec[(size_t)row*32 + lane] = a;
}

// ---------------- K3: message MLP + position update per (n,i) ----------------
__global__ void __launch_bounds__(256) k3_msg(
    const float* __restrict__ p, const float* __restrict__ e1,
    const float* __restrict__ x1b, const float* __restrict__ x2,
    const float* __restrict__ x2b,
    float* __restrict__ outp)
{
    extern __shared__ float sm[];
    float* sb   = sm;            // 4096: bvec[b][m]
    float* se2  = sm + 4096;     // 4096: e2T [m][c]
    float* sx1  = sm + 8192;     // 4096: x1T [c][m2]
    float* sy   = sm + 12288;    // 1024: per-warp y buffer
    float* spij = sm + 13312;    // 512
    float* ss   = sm + 13824;    // 128: scores
    float* spad = sm + 13952;    // 128
    float* sa   = sm + 14080;    // 32
    float* se1c = sm + 14112;    // 32
    float* sx1b = sm + 14144;    // 32
    float* sx2v = sm + 14176;    // 32

    int tid = threadIdx.x, lane = tid & 31, warp = tid >> 5;
    int n = blockIdx.x >> 7, i = blockIdx.x & 127;
    bool pad_i = (p[(size_t)(n*128 + i)*4] == 0.0f);

    for (int t = tid; t < 4096; t += 256){
        sb[t]  = g_bvec[(size_t)n*4096 + t];
        se2[t] = g_e2T[t];
        sx1[t] = g_x1T[t];
    }
    if (tid < 32){
        sa[tid]   = g_avec[(size_t)(n*128 + i)*32 + tid];
        se1c[tid] = e1[tid*257 + 256];
        sx1b[tid] = x1b[tid];
        sx2v[tid] = x2[tid];
    }
    if (tid < 128){
        int j = tid;
        float4 pi = *(const float4*)(p + (size_t)(n*128 + i)*4);
        float4 pj = *(const float4*)(p + (size_t)(n*128 + j)*4);
        spij[j*4+0] = pi.x - pj.x;
        spij[j*4+1] = pi.y - pj.y;
        spij[j*4+2] = pi.z - pj.z;
        spij[j*4+3] = pi.w - pj.w;
        spad[j] = (pj.x != 0.0f) ? 1.0f : 0.0f;
    }
    __syncthreads();

    float x2bv = x2b[0];
    float* syw = sy + warp*128;
    for (int b = warp; b < 128; b += 8){
        float4 pd = *(const float4*)(spij + b*4);
        float normb = pad_i ? 0.0f : (pd.w*pd.w - pd.x*pd.x - pd.y*pd.y - pd.z*pd.z);
        // h32[m] per lane
        float hm = fmaxf(sa[lane] + sb[b*32 + lane] + normb*se1c[lane], 0.0f);
        // mij[c] = relu(sum_m h32[m] * e2T[m][c]) across 4 c per lane
        float mc0 = 0, mc1 = 0, mc2 = 0, mc3 = 0;
#pragma unroll
        for (int m = 0; m < 32; m++){
            float hv = __shfl_sync(0xffffffffu, hm, m);
            const float* er = se2 + m*128 + lane;
            mc0 = fmaf(hv, er[0],  mc0);
            mc1 = fmaf(hv, er[32], mc1);
            mc2 = fmaf(hv, er[64], mc2);
            mc3 = fmaf(hv, er[96], mc3);
        }
        mc0 = fmaxf(mc0, 0.f); mc1 = fmaxf(mc1, 0.f);
        mc2 = fmaxf(mc2, 0.f); mc3 = fmaxf(mc3, 0.f);
        if (pad_i){ mc0 = NEGV; mc1 = NEGV; mc2 = NEGV; mc3 = NEGV; }
        // LN over 128
        float mu = wsum(mc0 + mc1 + mc2 + mc3) * (1.0f/128.0f);
        float d0 = mc0 - mu, d1 = mc1 - mu, d2 = mc2 - mu, d3 = mc3 - mu;
        float var = wsum(d0*d0 + d1*d1 + d2*d2 + d3*d3) * (1.0f/128.0f);
        float rs = rsqrtf(var + 1e-5f);
        syw[lane]      = d0 * rs;
        syw[lane + 32] = d1 * rs;
        syw[lane + 64] = d2 * rs;
        syw[lane + 96] = d3 * rs;
        __syncwarp();
        // t[m2] = relu(sum_c y[c]*x1[m2][c] + x1b[m2]); lane = m2
        float acc = sx1b[lane];
#pragma unroll 8
        for (int c = 0; c < 128; c++)
            acc = fmaf(syw[c], sx1[c*32 + lane], acc);
        __syncwarp();
        float prod = fmaxf(acc, 0.0f) * sx2v[lane];
        float sv = wsum(prod) + x2bv;
        if (lane == 0) ss[b] = fmaxf(sv, 0.0f);
    }
    __syncthreads();

    if (warp == 0){
        float m0 = fmaxf(fmaxf(ss[lane], ss[lane+32]), fmaxf(ss[lane+64], ss[lane+96]));
#pragma unroll
        for (int k = 16; k > 0; k >>= 1) m0 = fmaxf(m0, __shfl_xor_sync(0xffffffffu, m0, k));
        float den = 0, dx = 0, dy = 0, dz = 0, dw = 0, cnt = 0;
#pragma unroll
        for (int q2 = 0; q2 < 4; q2++){
            int b = lane + 32*q2;
            float w = __expf(ss[b] - m0);
            den += w;
            dx = fmaf(w, spij[b*4+0], dx);
            dy = fmaf(w, spij[b*4+1], dy);
            dz = fmaf(w, spij[b*4+2], dz);
            dw = fmaf(w, spij[b*4+3], dw);
            cnt += spad[b];
        }
        den = wsum(den); dx = wsum(dx); dy = wsum(dy);
        dz = wsum(dz);   dw = wsum(dw); cnt = wsum(cnt);
        if (lane == 0){
            float inv = 1.0f / (den * cnt);
            const float* pr = p + (size_t)(n*128 + i)*4;
            float* o = outp + (size_t)(n*128 + i)*4;
            float d4[4] = {dx, dy, dz, dw};
#pragma unroll
            for (int d = 0; d < 4; d++){
                float pv = pr[d];
                o[d] = (pv == 0.0f) ? 0.0f : pv + d4[d]*inv;
            }
        }
    }
}

extern "C" void kernel_launch(void* const* d_in, const int* in_sizes, int n_in,
                              void* d_out, int out_size){
    const float* x     = (const float*)d_in[0];
    const float* p     = (const float*)d_in[1];
    const float* U     = (const float*)d_in[2];
    const float* wq    = (const float*)d_in[3];
    const float* bq    = (const float*)d_in[4];
    const float* wk    = (const float*)d_in[5];
    const float* bk    = (const float*)d_in[6];
    const float* wv    = (const float*)d_in[7];
    const float* bv    = (const float*)d_in[8];
    const float* ln1_g = (const float*)d_in[9];
    const float* ln1_b = (const float*)d_in[10];
    const float* w1    = (const float*)d_in[11];
    const float* b1    = (const float*)d_in[12];
    const float* ln2_g = (const float*)d_in[13];
    const float* ln2_b = (const float*)d_in[14];
    const float* w2    = (const float*)d_in[15];
    const float* b2    = (const float*)d_in[16];
    const float* pe1   = (const float*)d_in[17];
    const float* pe2   = (const float*)d_in[18];
    const float* e1    = (const float*)d_in[19];
    const float* e2    = (const float*)d_in[20];
    const float* x1    = (const float*)d_in[21];
    const float* x1b   = (const float*)d_in[22];
    const float* x2    = (const float*)d_in[23];
    const float* x2b   = (const float*)d_in[24];
    float* out  = (float*)d_out;
    float* xout = out;                 // (16,128,128)
    float* newp = out + 16*128*128;    // (16,128,4)

    cudaFuncSetAttribute(k2_attn, cudaFuncAttributeMaxDynamicSharedMemorySize, 204800);
    cudaFuncSetAttribute(k3_msg,  cudaFuncAttributeMaxDynamicSharedMemorySize, 57344);

    k0_prep<<<64, 256>>>(wq, wk, wv, w1, w2, pe2, e2, x1);
    k1_qkv<<<2048, 128>>>(x, bq, bk, bv);
    k2_attn<<<2048, 256, 204800>>>(U, p, ln1_g, ln1_b, b1, ln2_g, ln2_b, b2, pe1, xout);
    k2b_vec<<<2048, 64>>>(xout, e1);
    k3_msg<<<2048, 256, 57344>>>(p, e1, x1b, x2, x2b, newp);
}

// round 4
// speedup vs baseline: 1.1730x; 1.1730x over previous
#include <cuda_runtime.h>
#include <cuda_bf16.h>
#include <math.h>
#include <stdint.h>

#define NEGV (-10000.0f)

// ---------------- smem byte-offset map for k2 ----------------
#define SA_B     0          // fp32 [128][128] U+eqpe (64KB)
#define ABF_HI_B 65536      // bf16 A tile hi (32KB, swizzled)
#define ABF_LO_B 98304      // bf16 A tile lo (32KB)
#define LOG_B    65536      // fp32 logits [128][130] (aliases A tiles + 1KB of W_HI)
#define W_HI_B   131072     // bf16 W tile hi (32KB)
#define W_LO_B   163840     // bf16 W tile lo (32KB)
#define PE2T_B   131072     // fp32 pe2T [32][128] (16KB, overwritten by W1 later)
#define SK_B     196608
#define SG1_B    197120
#define SB1_B    197632
#define SG2_B    198144
#define SB2_B    198656
#define SBI1_B   199168
#define SBI2_B   199680
#define SPE1_B   200192
#define SPIJ_B   200704     // 2048
#define SRED_B   202752     // 2048
#define K2_SMEM  204800

// ---------------- device scratch ----------------
__device__ float g_q[16*128*128];
__device__ float g_k[16*128*128];
__device__ float g_v[16*128*128];
__device__ float g_pe2T[32*128];
__device__ float g_e2T[32*128];
__device__ float g_x1T[128*32];
__device__ float g_wqT[64*128];
__device__ float g_wkT[64*128];
__device__ float g_wvT[64*128];
__device__ float g_avec[16*128*32];
__device__ float g_bvec[16*128*32];
// bf16 hi/lo weight tiles, row-major [c][k] with 16B XOR swizzle (ldmatrix-ready)
__device__ uint32_t g_w1hi[8192];
__device__ uint32_t g_w1lo[8192];
__device__ uint32_t g_w2hi[8192];
__device__ uint32_t g_w2lo[8192];

// ---------------- generic helpers ----------------
__device__ __forceinline__ float wsum(float v){
#pragma unroll
    for (int k = 16; k > 0; k >>= 1) v += __shfl_xor_sync(0xffffffffu, v, k);
    return v;
}
__device__ __forceinline__ uint32_t smem_u32(const void* p){
    uint32_t a;
    asm("{ .reg .u64 t; cvta.to.shared.u64 t, %1; cvt.u32.u64 %0, t; }" : "=r"(a) : "l"(p));
    return a;
}
// 16B-granular XOR swizzle inside a [rows][128] bf16 tile (256B per row)
__device__ __forceinline__ uint32_t swz(int row, int kb){
    return (uint32_t)(row*256 + ((kb & 0xF0) ^ ((row & 7) << 4)) + (kb & 15));
}
__device__ __forceinline__ void split2(float x, float y, uint32_t &hi, uint32_t &lo){
    __nv_bfloat16 hx = __float2bfloat16(x), hy = __float2bfloat16(y);
    __nv_bfloat16 lx = __float2bfloat16(x - __bfloat162float(hx));
    __nv_bfloat16 ly = __float2bfloat16(y - __bfloat162float(hy));
    hi = (uint32_t)__bfloat16_as_ushort(hx) | ((uint32_t)__bfloat16_as_ushort(hy) << 16);
    lo = (uint32_t)__bfloat16_as_ushort(lx) | ((uint32_t)__bfloat16_as_ushort(ly) << 16);
}
__device__ __forceinline__ void ldsm4(uint32_t a[4], uint32_t addr){
    asm volatile("ldmatrix.sync.aligned.m8n8.x4.shared.b16 {%0,%1,%2,%3}, [%4];"
        : "=r"(a[0]), "=r"(a[1]), "=r"(a[2]), "=r"(a[3]) : "r"(addr));
}
__device__ __forceinline__ void ldsm2(uint32_t b[2], uint32_t addr){
    asm volatile("ldmatrix.sync.aligned.m8n8.x2.shared.b16 {%0,%1}, [%2];"
        : "=r"(b[0]), "=r"(b[1]) : "r"(addr));
}
__device__ __forceinline__ void mma16816(float d[4], const uint32_t a[4], const uint32_t b[2]){
    asm volatile("mma.sync.aligned.m16n8k16.row.col.f32.bf16.bf16.f32 "
        "{%0,%1,%2,%3}, {%4,%5,%6,%7}, {%8,%9}, {%0,%1,%2,%3};"
        : "+f"(d[0]), "+f"(d[1]), "+f"(d[2]), "+f"(d[3])
        : "r"(a[0]), "r"(a[1]), "r"(a[2]), "r"(a[3]), "r"(b[0]), "r"(b[1]));
}

// 128x128x128: warp w computes rows w*16..w*16+15 x all 128 cols.
// D = Ah*Wh + Ah*Wl + Al*Wh (bf16 hi/lo split), fp32 accum.
__device__ __forceinline__ void gemm_mma(uint32_t Ah, uint32_t Al, uint32_t Wh, uint32_t Wl,
                                         int w, int lane, float d[16][4]){
#pragma unroll
    for (int t = 0; t < 16; t++){ d[t][0]=0.f; d[t][1]=0.f; d[t][2]=0.f; d[t][3]=0.f; }
    const uint32_t alx  = (uint32_t)((lane & 7) << 4);
    const uint32_t aroff = (uint32_t)((w*16 + (lane & 15)) * 256);
    const uint32_t broff = (uint32_t)((lane & 7) * 256);
    const uint32_t akx  = (uint32_t)(lane & 16);
    const uint32_t bkx  = (uint32_t)((lane & 8) << 1);
    const uint32_t aox  = (uint32_t)(((w*16 + (lane & 15)) & 7) << 4);
#pragma unroll 1
    for (int kk = 0; kk < 8; kk++){
        uint32_t ao = aroff + (((uint32_t)(kk*32) + akx) ^ aox);
        uint32_t bo = broff + (((uint32_t)(kk*32) + bkx) ^ alx);
        uint32_t ah[4], al_[4];
        ldsm4(ah,  Ah + ao);
        ldsm4(al_, Al + ao);
#pragma unroll
        for (int t = 0; t < 16; t++){
            uint32_t bh[2], bl[2];
            ldsm2(bh, Wh + (uint32_t)(t*2048) + bo);
            ldsm2(bl, Wl + (uint32_t)(t*2048) + bo);
            mma16816(d[t], ah,  bh);
            mma16816(d[t], ah,  bl);
            mma16816(d[t], al_, bh);
        }
    }
}

// ---------------- K0: weight prep ----------------
__global__ void k0_prep(const float* __restrict__ wq, const float* __restrict__ wk,
                        const float* __restrict__ wv, const float* __restrict__ w1,
                        const float* __restrict__ w2, const float* __restrict__ pe2,
                        const float* __restrict__ e2, const float* __restrict__ x1){
    int idx = blockIdx.x * blockDim.x + threadIdx.x;
    int stride = gridDim.x * blockDim.x;
    for (int t = idx; t < 16384; t += stride){
        int c = t >> 7, m = t & 127;
        uint32_t a = swz(c, m*2) >> 1;
        float v1 = w1[t];
        __nv_bfloat16 h1 = __float2bfloat16(v1);
        ((unsigned short*)g_w1hi)[a] = __bfloat16_as_ushort(h1);
        ((unsigned short*)g_w1lo)[a] = __bfloat16_as_ushort(__float2bfloat16(v1 - __bfloat162float(h1)));
        float v2 = w2[t];
        __nv_bfloat16 h2 = __float2bfloat16(v2);
        ((unsigned short*)g_w2hi)[a] = __bfloat16_as_ushort(h2);
        ((unsigned short*)g_w2lo)[a] = __bfloat16_as_ushort(__float2bfloat16(v2 - __bfloat162float(h2)));
    }
    for (int t = idx; t < 4096; t += stride){
        int c = t >> 5, m = t & 31;
        g_pe2T[m*128 + c] = pe2[t];
        g_e2T [m*128 + c] = e2[t];
        int m2 = t >> 7, c2 = t & 127;
        g_x1T[c2*32 + m2] = x1[t];
    }
    for (int t = idx; t < 8192; t += stride){
        int c = t >> 6, d = t & 63;
        g_wqT[d*128 + c] = wq[t];
        g_wkT[d*128 + c] = wk[t];
        g_wvT[d*128 + c] = wv[t];
    }
}

// ---------------- K1: q,k,v projections ----------------
__global__ void __launch_bounds__(128) k1_qkv(const float* __restrict__ x,
                                              const float* __restrict__ bq,
                                              const float* __restrict__ bk,
                                              const float* __restrict__ bv){
    __shared__ float sx[64];
    int row = blockIdx.x;
    int c = threadIdx.x;
    if (c < 64) sx[c] = x[(size_t)row*64 + c];
    __syncthreads();
    float aq = bq[c], ak = bk[c], av = bv[c];
#pragma unroll 8
    for (int d = 0; d < 64; d++){
        float xv = sx[d];
        aq = fmaf(xv, g_wqT[d*128 + c], aq);
        ak = fmaf(xv, g_wkT[d*128 + c], ak);
        av = fmaf(xv, g_wvT[d*128 + c], av);
    }
    g_q[(size_t)row*128 + c] = aq;
    g_k[(size_t)row*128 + c] = ak;
    g_v[(size_t)row*128 + c] = av;
}

// ---------------- K2: fused attention per (n,i), mma.sync GEMMs ----------------
__global__ void __launch_bounds__(256) k2_attn(
    const float* __restrict__ U, const float* __restrict__ p,
    const float* __restrict__ ln1_g, const float* __restrict__ ln1_b,
    const float* __restrict__ b1,
    const float* __restrict__ ln2_g, const float* __restrict__ ln2_b,
    const float* __restrict__ b2,
    const float* __restrict__ pe1,
    float* __restrict__ xout)
{
    extern __shared__ char sm8[];
    float* sA   = (float*)(sm8 + SA_B);
    float* sLog = (float*)(sm8 + LOG_B);     // [128][130]
    float* spe2 = (float*)(sm8 + PE2T_B);
    float* sk   = (float*)(sm8 + SK_B);
    float* sg1  = (float*)(sm8 + SG1_B);
    float* sb1v = (float*)(sm8 + SB1_B);
    float* sg2  = (float*)(sm8 + SG2_B);
    float* sb2v = (float*)(sm8 + SB2_B);
    float* sbi1 = (float*)(sm8 + SBI1_B);
    float* sbi2 = (float*)(sm8 + SBI2_B);
    float* spe1 = (float*)(sm8 + SPE1_B);
    float* spij = (float*)(sm8 + SPIJ_B);
    float* sred = (float*)(sm8 + SRED_B);

    const uint32_t sbase = smem_u32(sm8);
    const uint32_t Ah = sbase + ABF_HI_B, Al = sbase + ABF_LO_B;
    const uint32_t Wh = sbase + W_HI_B,   Wl = sbase + W_LO_B;
    const int tid = threadIdx.x;
    const int lane = tid & 31, warp = tid >> 5;
    const int n = blockIdx.x >> 7, i = blockIdx.x & 127;

    // ----- stage 0: small loads -----
    if (tid < 128){
        size_t rowk = (size_t)(n*128 + i);
        sk[tid]   = g_k[rowk*128 + tid];
        sg1[tid]  = ln1_g[tid];  sb1v[tid] = ln1_b[tid];
        sg2[tid]  = ln2_g[tid];  sb2v[tid] = ln2_b[tid];
        sbi1[tid] = b1[tid];     sbi2[tid] = b2[tid];
        spe1[tid] = pe1[tid];
        int j = tid;
        float4 pi = *(const float4*)(p + (size_t)(n*128 + i)*4);
        float4 pj = *(const float4*)(p + (size_t)(n*128 + j)*4);
        spij[j*4+0] = pi.x - pj.x;
        spij[j*4+1] = pi.y - pj.y;
        spij[j*4+2] = pi.z - pj.z;
        spij[j*4+3] = pi.w - pj.w;
    }
    for (int t = tid; t < 4096; t += 256) spe2[t] = g_pe2T[t];
    const bool pad_i = (p[(size_t)(n*128 + i)*4] == 0.0f);
    __syncthreads();

    // ----- stage 1: eqpe -> sA = U + eqpe -----
    const float* Ub = U + (size_t)blockIdx.x * 128 * 128;
    float4 pe1r = ((const float4*)spe1)[lane];
    for (int jj = warp; jj < 128; jj += 8){
        float4 pd = *(const float4*)(spij + jj*4);
        float t = pd.x*pe1r.x + pd.y*pe1r.y + pd.z*pe1r.z + pd.w*pe1r.w;
        float mu = wsum(t) * (1.0f/32.0f);
        float dd = t - mu;
        float var = wsum(dd*dd) * (1.0f/32.0f);
        float tn = fmaxf(dd * rsqrtf(var + 1e-5f), 0.0f);
        float e0 = 0, e1v = 0, e2v = 0, e3v = 0;
#pragma unroll
        for (int m = 0; m < 32; m++){
            float tm = __shfl_sync(0xffffffffu, tn, m);
            const float* pr = spe2 + m*128 + lane;
            e0  = fmaf(tm, pr[0],  e0);
            e1v = fmaf(tm, pr[32], e1v);
            e2v = fmaf(tm, pr[64], e2v);
            e3v = fmaf(tm, pr[96], e3v);
        }
        float mu2 = wsum(e0 + e1v + e2v + e3v) * (1.0f/128.0f);
        float d0 = e0 - mu2, d1 = e1v - mu2, d2 = e2v - mu2, d3 = e3v - mu2;
        float v2 = wsum(d0*d0 + d1*d1 + d2*d2 + d3*d3) * (1.0f/128.0f);
        float rs = rsqrtf(v2 + 1e-5f);
        const float* Up = Ub + jj*128;
        sA[jj*128 + lane]      = Up[lane]      + fmaxf(d0*rs, 0.0f);
        sA[jj*128 + lane + 32] = Up[lane + 32] + fmaxf(d1*rs, 0.0f);
        sA[jj*128 + lane + 64] = Up[lane + 64] + fmaxf(d2*rs, 0.0f);
        sA[jj*128 + lane + 96] = Up[lane + 96] + fmaxf(d3*rs, 0.0f);
    }
    __syncthreads();

    // ----- stage 2: A1 = relu(ln(k_i - q_j + A, g1,b1)) -> bf16 hi/lo; W1 copy -----
    const float* qb = g_q + (size_t)n*128*128;
    for (int jj = warp; jj < 128; jj += 8){
        const float* qp = qb + jj*128;
        float2 a0 = *(float2*)(sA + jj*128 + 2*lane);
        float2 a1 = *(float2*)(sA + jj*128 + 2*lane + 64);
        float2 q0 = *(const float2*)(qp + 2*lane);
        float2 q1 = *(const float2*)(qp + 2*lane + 64);
        float2 k0 = *(float2*)(sk + 2*lane);
        float2 k1 = *(float2*)(sk + 2*lane + 64);
        float r00 = k0.x - q0.x + a0.x;
        float r01 = k0.y - q0.y + a0.y;
        float r10 = k1.x - q1.x + a1.x;
        float r11 = k1.y - q1.y + a1.y;
        float mu = wsum(r00 + r01 + r10 + r11) * (1.0f/128.0f);
        float d00 = r00 - mu, d01 = r01 - mu, d10 = r10 - mu, d11 = r11 - mu;
        float var = wsum(d00*d00 + d01*d01 + d10*d10 + d11*d11) * (1.0f/128.0f);
        float rs = rsqrtf(var + 1e-5f);
        float2 g0 = *(float2*)(sg1 + 2*lane),  g1v = *(float2*)(sg1 + 2*lane + 64);
        float2 b0 = *(float2*)(sb1v + 2*lane), b1v = *(float2*)(sb1v + 2*lane + 64);
        float y00 = fmaxf(fmaf(d00*rs, g0.x,  b0.x),  0.0f);
        float y01 = fmaxf(fmaf(d01*rs, g0.y,  b0.y),  0.0f);
        float y10 = fmaxf(fmaf(d10*rs, g1v.x, b1v.x), 0.0f);
        float y11 = fmaxf(fmaf(d11*rs, g1v.y, b1v.y), 0.0f);
        uint32_t h0, l0, h1, l1;
        split2(y00, y01, h0, l0);
        split2(y10, y11, h1, l1);
        *(uint32_t*)(sm8 + ABF_HI_B + swz(jj, 4*lane))       = h0;
        *(uint32_t*)(sm8 + ABF_LO_B + swz(jj, 4*lane))       = l0;
        *(uint32_t*)(sm8 + ABF_HI_B + swz(jj, 4*lane + 128)) = h1;
        *(uint32_t*)(sm8 + ABF_LO_B + swz(jj, 4*lane + 128)) = l1;
    }
    for (int t = tid; t < 8192; t += 256){
        ((uint32_t*)(sm8 + W_HI_B))[t] = g_w1hi[t];
        ((uint32_t*)(sm8 + W_LO_B))[t] = g_w1lo[t];
    }
    __syncthreads();

    // ----- GEMM1 -----
    float d[16][4];
    gemm_mma(Ah, Al, Wh, Wl, warp, lane, d);
    __syncthreads();

    // ----- epilogue 1: +b1, LN(g2,b2), relu -> A2 bf16; W2 copy -----
    for (int t = tid; t < 8192; t += 256){
        ((uint32_t*)(sm8 + W_HI_B))[t] = g_w2hi[t];
        ((uint32_t*)(sm8 + W_LO_B))[t] = g_w2lo[t];
    }
    {
        const int g4 = lane & 3;
        const int rowA = warp*16 + (lane >> 2), rowB = rowA + 8;
        float s1A = 0, s2A = 0, s1B = 0, s2B = 0;
#pragma unroll
        for (int t = 0; t < 16; t++){
            int c0 = t*8 + g4*2;
            float2 bb = *(float2*)(sbi1 + c0);
            d[t][0] += bb.x; d[t][1] += bb.y;
            d[t][2] += bb.x; d[t][3] += bb.y;
            s1A += d[t][0] + d[t][1]; s2A += d[t][0]*d[t][0] + d[t][1]*d[t][1];
            s1B += d[t][2] + d[t][3]; s2B += d[t][2]*d[t][2] + d[t][3]*d[t][3];
        }
        s1A += __shfl_xor_sync(~0u, s1A, 1); s1A += __shfl_xor_sync(~0u, s1A, 2);
        s2A += __shfl_xor_sync(~0u, s2A, 1); s2A += __shfl_xor_sync(~0u, s2A, 2);
        s1B += __shfl_xor_sync(~0u, s1B, 1); s1B += __shfl_xor_sync(~0u, s1B, 2);
        s2B += __shfl_xor_sync(~0u, s2B, 1); s2B += __shfl_xor_sync(~0u, s2B, 2);
        float muA = s1A*(1.0f/128.0f), rsA = rsqrtf(s2A*(1.0f/128.0f) - muA*muA + 1e-5f);
        float muB = s1B*(1.0f/128.0f), rsB = rsqrtf(s2B*(1.0f/128.0f) - muB*muB + 1e-5f);
#pragma unroll
        for (int t = 0; t < 16; t++){
            int c0 = t*8 + g4*2;
            float2 gg = *(float2*)(sg2 + c0);
            float2 bb = *(float2*)(sb2v + c0);
            float yA0 = fmaxf(fmaf((d[t][0]-muA)*rsA, gg.x, bb.x), 0.0f);
            float yA1 = fmaxf(fmaf((d[t][1]-muA)*rsA, gg.y, bb.y), 0.0f);
            float yB0 = fmaxf(fmaf((d[t][2]-muB)*rsB, gg.x, bb.x), 0.0f);
            float yB1 = fmaxf(fmaf((d[t][3]-muB)*rsB, gg.y, bb.y), 0.0f);
            uint32_t hA, lA, hB, lB;
            split2(yA0, yA1, hA, lA);
            split2(yB0, yB1, hB, lB);
            int kb = t*16 + g4*4;
            *(uint32_t*)(sm8 + ABF_HI_B + swz(rowA, kb)) = hA;
            *(uint32_t*)(sm8 + ABF_LO_B + swz(rowA, kb)) = lA;
            *(uint32_t*)(sm8 + ABF_HI_B + swz(rowB, kb)) = hB;
            *(uint32_t*)(sm8 + ABF_LO_B + swz(rowB, kb)) = lB;
        }
    }
    __syncthreads();

    // ----- GEMM2 -----
    gemm_mma(Ah, Al, Wh, Wl, warp, lane, d);
    __syncthreads();

    // ----- epilogue 2: +b2, mask -> logits (stride 130, aliases A region) -----
    {
        const int g4 = lane & 3;
        const int rowA = warp*16 + (lane >> 2), rowB = rowA + 8;
#pragma unroll
        for (int t = 0; t < 16; t++){
            int c0 = t*8 + g4*2;
            float2 bb = *(float2*)(sbi2 + c0);
            float vA0 = d[t][0] + bb.x, vA1 = d[t][1] + bb.y;
            float vB0 = d[t][2] + bb.x, vB1 = d[t][3] + bb.y;
            if (pad_i){ vA0 = NEGV; vA1 = NEGV; vB0 = NEGV; vB1 = NEGV; }
            *(float2*)(sLog + rowA*130 + c0) = make_float2(vA0, vA1);
            *(float2*)(sLog + rowB*130 + c0) = make_float2(vB0, vB1);
        }
    }
    __syncthreads();

    // ----- softmax over j (per c) + weighted sum of xv = v_j + A -----
    {
        const int c = tid & 127, half = tid >> 7;
        const int jb = half * 64;
        float M = -3.4e38f;
        for (int j = jb; j < jb + 64; j++) M = fmaxf(M, sLog[j*130 + c]);
        sred[half*128 + c] = M;
        __syncthreads();
        M = fmaxf(sred[c], sred[128 + c]);
        __syncthreads();
        float den = 0, num = 0;
        const float* vp = g_v + (size_t)n*128*128;
        for (int j = jb; j < jb + 64; j++){
            float w = __expf(sLog[j*130 + c] - M);
            den += w;
            num = fmaf(w, vp[j*128 + c] + sA[j*128 + c], num);
        }
        sred[half*128 + c]       = den;
        sred[256 + half*128 + c] = num;
        __syncthreads();
        if (half == 0){
            float dtot = sred[c] + sred[128 + c];
            float ntot = sred[256 + c] + sred[384 + c];
            xout[(size_t)blockIdx.x*128 + c] = ntot / dtot;
        }
    }
}

// ---------------- K2b: avec/bvec = e1 row projections of x_out ----------------
__global__ void __launch_bounds__(64) k2b_vec(const float* __restrict__ xout,
                                              const float* __restrict__ e1){
    __shared__ float sx[128];
    int row = blockIdx.x;
    int tid = threadIdx.x;
    sx[tid]      = xout[(size_t)row*128 + tid];
    sx[tid + 64] = xout[(size_t)row*128 + tid + 64];
    __syncthreads();
    int lane = tid & 31;
    const float* er = e1 + lane*257 + ((tid >= 32) ? 128 : 0);
    float a = 0;
#pragma unroll 8
    for (int c2 = 0; c2 < 128; c2++) a = fmaf(sx[c2], er[c2], a);
    if (tid < 32) g_avec[(size_t)row*32 + lane] = a;
    else          g_bvec[(size_t)row*32 + lane] = a;
}

// ---------------- K3: message MLP + position update per (n,i) ----------------
__global__ void __launch_bounds__(256) k3_msg(
    const float* __restrict__ p, const float* __restrict__ e1,
    const float* __restrict__ x1b, const float* __restrict__ x2,
    const float* __restrict__ x2b,
    float* __restrict__ outp)
{
    extern __shared__ float sm[];
    float* sb   = sm;            // 4096
    float* se2  = sm + 4096;     // 4096
    float* sx1  = sm + 8192;     // 4096
    float* sy   = sm + 12288;    // 1024
    float* spij = sm + 13312;    // 512
    float* ss   = sm + 13824;    // 128
    float* spad = sm + 13952;    // 128
    float* sa   = sm + 14080;    // 32
    float* se1c = sm + 14112;    // 32
    float* sx1b = sm + 14144;    // 32
    float* sx2v = sm + 14176;    // 32

    int tid = threadIdx.x, lane = tid & 31, warp = tid >> 5;
    int n = blockIdx.x >> 7, i = blockIdx.x & 127;
    bool pad_i = (p[(size_t)(n*128 + i)*4] == 0.0f);

    for (int t = tid; t < 4096; t += 256){
        sb[t]  = g_bvec[(size_t)n*4096 + t];
        se2[t] = g_e2T[t];
        sx1[t] = g_x1T[t];
    }
    if (tid < 32){
        sa[tid]   = g_avec[(size_t)(n*128 + i)*32 + tid];
        se1c[tid] = e1[tid*257 + 256];
        sx1b[tid] = x1b[tid];
        sx2v[tid] = x2[tid];
    }
    if (tid < 128){
        int j = tid;
        float4 pi = *(const float4*)(p + (size_t)(n*128 + i)*4);
        float4 pj = *(const float4*)(p + (size_t)(n*128 + j)*4);
        spij[j*4+0] = pi.x - pj.x;
        spij[j*4+1] = pi.y - pj.y;
        spij[j*4+2] = pi.z - pj.z;
        spij[j*4+3] = pi.w - pj.w;
        spad[j] = (pj.x != 0.0f) ? 1.0f : 0.0f;
    }
    __syncthreads();

    float x2bv = x2b[0];
    float* syw = sy + warp*128;
    for (int b = warp; b < 128; b += 8){
        float4 pd = *(const float4*)(spij + b*4);
        float normb = pad_i ? 0.0f : (pd.w*pd.w - pd.x*pd.x - pd.y*pd.y - pd.z*pd.z);
        float hm = fmaxf(sa[lane] + sb[b*32 + lane] + normb*se1c[lane], 0.0f);
        float mc0 = 0, mc1 = 0, mc2 = 0, mc3 = 0;
#pragma unroll
        for (int m = 0; m < 32; m++){
            float hv = __shfl_sync(0xffffffffu, hm, m);
            const float* er = se2 + m*128 + lane;
            mc0 = fmaf(hv, er[0],  mc0);
            mc1 = fmaf(hv, er[32], mc1);
            mc2 = fmaf(hv, er[64], mc2);
            mc3 = fmaf(hv, er[96], mc3);
        }
        mc0 = fmaxf(mc0, 0.f); mc1 = fmaxf(mc1, 0.f);
        mc2 = fmaxf(mc2, 0.f); mc3 = fmaxf(mc3, 0.f);
        if (pad_i){ mc0 = NEGV; mc1 = NEGV; mc2 = NEGV; mc3 = NEGV; }
        float mu = wsum(mc0 + mc1 + mc2 + mc3) * (1.0f/128.0f);
        float d0 = mc0 - mu, d1 = mc1 - mu, d2 = mc2 - mu, d3 = mc3 - mu;
        float var = wsum(d0*d0 + d1*d1 + d2*d2 + d3*d3) * (1.0f/128.0f);
        float rs = rsqrtf(var + 1e-5f);
        syw[lane]      = d0 * rs;
        syw[lane + 32] = d1 * rs;
        syw[lane + 64] = d2 * rs;
        syw[lane + 96] = d3 * rs;
        __syncwarp();
        float acc = sx1b[lane];
#pragma unroll 8
        for (int c = 0; c < 128; c++)
            acc = fmaf(syw[c], sx1[c*32 + lane], acc);
        __syncwarp();
        float prod = fmaxf(acc, 0.0f) * sx2v[lane];
        float sv = wsum(prod) + x2bv;
        if (lane == 0) ss[b] = fmaxf(sv, 0.0f);
    }
    __syncthreads();

    if (warp == 0){
        float m0 = fmaxf(fmaxf(ss[lane], ss[lane+32]), fmaxf(ss[lane+64], ss[lane+96]));
#pragma unroll
        for (int k = 16; k > 0; k >>= 1) m0 = fmaxf(m0, __shfl_xor_sync(0xffffffffu, m0, k));
        float den = 0, dx = 0, dy = 0, dz = 0, dw = 0, cnt = 0;
#pragma unroll
        for (int q2 = 0; q2 < 4; q2++){
            int b = lane + 32*q2;
            float w = __expf(ss[b] - m0);
            den += w;
            dx = fmaf(w, spij[b*4+0], dx);
            dy = fmaf(w, spij[b*4+1], dy);
            dz = fmaf(w, spij[b*4+2], dz);
            dw = fmaf(w, spij[b*4+3], dw);
            cnt += spad[b];
        }
        den = wsum(den); dx = wsum(dx); dy = wsum(dy);
        dz = wsum(dz);   dw = wsum(dw); cnt = wsum(cnt);
        if (lane == 0){
            float inv = 1.0f / (den * cnt);
            const float* pr = p + (size_t)(n*128 + i)*4;
            float* o = outp + (size_t)(n*128 + i)*4;
            float d4[4] = {dx, dy, dz, dw};
#pragma unroll
            for (int d = 0; d < 4; d++){
                float pv = pr[d];
                o[d] = (pv == 0.0f) ? 0.0f : pv + d4[d]*inv;
            }
        }
    }
}

extern "C" void kernel_launch(void* const* d_in, const int* in_sizes, int n_in,
                              void* d_out, int out_size){
    const float* x     = (const float*)d_in[0];
    const float* p     = (const float*)d_in[1];
    const float* U     = (const float*)d_in[2];
    const float* wq    = (const float*)d_in[3];
    const float* bq    = (const float*)d_in[4];
    const float* wk    = (const float*)d_in[5];
    const float* bk    = (const float*)d_in[6];
    const float* wv    = (const float*)d_in[7];
    const float* bv    = (const float*)d_in[8];
    const float* ln1_g = (const float*)d_in[9];
    const float* ln1_b = (const float*)d_in[10];
    const float* w1    = (const float*)d_in[11];
    const float* b1    = (const float*)d_in[12];
    const float* ln2_g = (const float*)d_in[13];
    const float* ln2_b = (const float*)d_in[14];
    const float* w2    = (const float*)d_in[15];
    const float* b2    = (const float*)d_in[16];
    const float* pe1   = (const float*)d_in[17];
    const float* pe2   = (const float*)d_in[18];
    const float* e1    = (const float*)d_in[19];
    const float* e2    = (const float*)d_in[20];
    const float* x1    = (const float*)d_in[21];
    const float* x1b   = (const float*)d_in[22];
    const float* x2    = (const float*)d_in[23];
    const float* x2b   = (const float*)d_in[24];
    float* out  = (float*)d_out;
    float* xout = out;                 // (16,128,128)
    float* newp = out + 16*128*128;    // (16,128,4)

    cudaFuncSetAttribute(k2_attn, cudaFuncAttributeMaxDynamicSharedMemorySize, K2_SMEM);
    cudaFuncSetAttribute(k3_msg,  cudaFuncAttributeMaxDynamicSharedMemorySize, 57344);

    k0_prep<<<64, 256>>>(wq, wk, wv, w1, w2, pe2, e2, x1);
    k1_qkv<<<2048, 128>>>(x, bq, bk, bv);
    k2_attn<<<2048, 256, K2_SMEM>>>(U, p, ln1_g, ln1_b, b1, ln2_g, ln2_b, b2, pe1, xout);
    k2b_vec<<<2048, 64>>>(xout, e1);
    k3_msg<<<2048, 256, 57344>>>(p, e1, x1b, x2, x2b, newp);
}

// round 5
// speedup vs baseline: 2.1384x; 1.8231x over previous
#include <cuda_runtime.h>
#include <cuda_bf16.h>
#include <math.h>
#include <stdint.h>

#define NEGV (-10000.0f)

// ---------------- K2 smem byte offsets ----------------
#define XV_B     0          // fp32 [128][128] xv = v + U + eqpe (64KB)
#define A_HI_B   65536      // bf16 A tile hi (32KB, XOR swizzle)
#define A_LO_B   98304      // bf16 A tile lo (32KB)
#define LOG_B    65536      // fp32 logits [128][130] (aliases A tiles; tail into W_HI, dead)
#define W_HI_B   131072     // bf16 B tile hi (32KB): pe2(80B fmt) -> w1 -> w2
#define W_LO_B   163840
#define TN_HI_B  196608     // bf16 tn tile hi (80B-stride, 10240B)
#define TN_LO_B  206848
#define SK_B     217088
#define SG1_B    217600
#define SB1_B    218112
#define SG2_B    218624
#define SB2_B    219136
#define SBI1_B   219648
#define SBI2_B   220160
#define SPE1_B   220672
#define SPIJ_B   221184     // 2048
#define SRED_B   223232     // 2048
#define K2_SMEM  225280

// ---------------- K3 smem byte offsets ----------------
#define K3_A1H   0          // h32 tile hi (80B-stride, 10240)
#define K3_A1L   10240
#define K3_A2H   20480      // y tile hi (XOR, 32KB)
#define K3_A2L   53248
#define K3_B1H   86016      // e2 tile hi (80B, 10240)
#define K3_B1L   96256
#define K3_B2H   106496     // x1 tile hi (XOR, 32 rows, 8KB)
#define K3_B2L   114688
#define K3_SPIJ  122880     // 2048
#define K3_SNORM 124928     // 512
#define K3_SS    125440     // 512
#define K3_SPAD  125952     // 512
#define K3_SA    126464     // 128
#define K3_SE1C  126592     // 128
#define K3_SX1B  126720     // 128
#define K3_SX2V  126848     // 128
#define K3_SMEM  126976

// ---------------- device scratch ----------------
__device__ float g_q[16*128*128];
__device__ float g_k[16*128*128];
__device__ float g_v[16*128*128];
__device__ float g_wqT[64*128];
__device__ float g_wkT[64*128];
__device__ float g_wvT[64*128];
__device__ float g_avec[16*128*32];
__device__ float g_bvec[16*128*32];
// XOR-swizzled [n][k] bf16 tiles (256B rows)
__device__ uint32_t g_w1hi[8192];
__device__ uint32_t g_w1lo[8192];
__device__ uint32_t g_w2hi[8192];
__device__ uint32_t g_w2lo[8192];
__device__ uint32_t g_x1hi[2048];
__device__ uint32_t g_x1lo[2048];
// 80B-stride [n][k<32] bf16 tiles
__device__ uint32_t g_pe2hi[2560];
__device__ uint32_t g_pe2lo[2560];
__device__ uint32_t g_e2hi[2560];
__device__ uint32_t g_e2lo[2560];

// ---------------- helpers ----------------
__device__ __forceinline__ float wsum(float v){
#pragma unroll
    for (int k = 16; k > 0; k >>= 1) v += __shfl_xor_sync(0xffffffffu, v, k);
    return v;
}
__device__ __forceinline__ uint32_t smem_u32(const void* p){
    uint32_t a;
    asm("{ .reg .u64 t; cvta.to.shared.u64 t, %1; cvt.u32.u64 %0, t; }" : "=r"(a) : "l"(p));
    return a;
}
// XOR swizzle inside [rows][128] bf16 tile, 256B per row; kb = byte within row
__device__ __forceinline__ uint32_t swz(int row, int kb){
    return (uint32_t)(row*256 + ((kb & 0xF0) ^ ((row & 7) << 4)) + (kb & 15));
}
__device__ __forceinline__ void split2(float x, float y, uint32_t &hi, uint32_t &lo){
    __nv_bfloat16 hx = __float2bfloat16(x), hy = __float2bfloat16(y);
    __nv_bfloat16 lx = __float2bfloat16(x - __bfloat162float(hx));
    __nv_bfloat16 ly = __float2bfloat16(y - __bfloat162float(hy));
    hi = (uint32_t)__bfloat16_as_ushort(hx) | ((uint32_t)__bfloat16_as_ushort(hy) << 16);
    lo = (uint32_t)__bfloat16_as_ushort(lx) | ((uint32_t)__bfloat16_as_ushort(ly) << 16);
}
__device__ __forceinline__ void ldsm4(uint32_t a[4], uint32_t addr){
    asm volatile("ldmatrix.sync.aligned.m8n8.x4.shared.b16 {%0,%1,%2,%3}, [%4];"
        : "=r"(a[0]), "=r"(a[1]), "=r"(a[2]), "=r"(a[3]) : "r"(addr));
}
__device__ __forceinline__ void mma16816(float d[4], const uint32_t a[4], const uint32_t b[2]){
    asm volatile("mma.sync.aligned.m16n8k16.row.col.f32.bf16.bf16.f32 "
        "{%0,%1,%2,%3}, {%4,%5,%6,%7}, {%8,%9}, {%0,%1,%2,%3};"
        : "+f"(d[0]), "+f"(d[1]), "+f"(d[2]), "+f"(d[3])
        : "r"(a[0]), "r"(a[1]), "r"(a[2]), "r"(a[3]), "r"(b[0]), "r"(b[1]));
}

// full 128x128x128, A/B XOR tiles, 3-term split, x4 B loads
__device__ __forceinline__ void gemm128(uint32_t Ah, uint32_t Al, uint32_t Wh, uint32_t Wl,
                                        int warp, int lane, float d[16][4]){
#pragma unroll
    for (int t = 0; t < 16; t++){ d[t][0]=0.f; d[t][1]=0.f; d[t][2]=0.f; d[t][3]=0.f; }
    const uint32_t aro = (uint32_t)((warp*16 + (lane&15))*256);
    const uint32_t aox = (uint32_t)((lane&7)<<4);
    const uint32_t akx = (uint32_t)(lane&16);
    const uint32_t bro = (uint32_t)(((lane&7) + ((lane>>4)<<3))*256);
    const uint32_t bkx = (uint32_t)((lane&8)<<1);
#pragma unroll 1
    for (int kk = 0; kk < 8; kk++){
        uint32_t ka = (uint32_t)(kk*32);
        uint32_t ah[4], al_[4];
        ldsm4(ah,  Ah + aro + ((ka + akx) ^ aox));
        ldsm4(al_, Al + aro + ((ka + akx) ^ aox));
        uint32_t bo = bro + ((ka + bkx) ^ aox);
#pragma unroll
        for (int t2 = 0; t2 < 8; t2++){
            uint32_t bh[4], bl[4];
            ldsm4(bh, Wh + bo + (uint32_t)(t2*4096));
            ldsm4(bl, Wl + bo + (uint32_t)(t2*4096));
            mma16816(d[2*t2],   ah,  bh);
            mma16816(d[2*t2],   ah,  bl);
            mma16816(d[2*t2],   al_, bh);
            mma16816(d[2*t2+1], ah,  bh+2);
            mma16816(d[2*t2+1], ah,  bl+2);
            mma16816(d[2*t2+1], al_, bh+2);
        }
    }
}

// 128xN x32, A/B 80B-stride tiles, 3-term split (ntiles2*16 = N cols)
__device__ __forceinline__ void gemm32(uint32_t Ah, uint32_t Al, uint32_t Bh, uint32_t Bl,
                                       int warp, int lane, float d[16][4]){
#pragma unroll
    for (int t = 0; t < 16; t++){ d[t][0]=0.f; d[t][1]=0.f; d[t][2]=0.f; d[t][3]=0.f; }
    const uint32_t aro = (uint32_t)((warp*16 + (lane&15))*80 + (lane&16));
    const uint32_t bro = (uint32_t)(((lane&7) + ((lane>>4)<<3))*80 + ((lane&8)<<1));
#pragma unroll
    for (int kk = 0; kk < 2; kk++){
        uint32_t ah[4], al_[4];
        ldsm4(ah,  Ah + aro + (uint32_t)(kk*32));
        ldsm4(al_, Al + aro + (uint32_t)(kk*32));
#pragma unroll
        for (int t2 = 0; t2 < 8; t2++){
            uint32_t bh[4], bl[4];
            ldsm4(bh, Bh + bro + (uint32_t)(kk*32 + t2*1280));
            ldsm4(bl, Bl + bro + (uint32_t)(kk*32 + t2*1280));
            mma16816(d[2*t2],   ah,  bh);
            mma16816(d[2*t2],   ah,  bl);
            mma16816(d[2*t2],   al_, bh);
            mma16816(d[2*t2+1], ah,  bh+2);
            mma16816(d[2*t2+1], ah,  bl+2);
            mma16816(d[2*t2+1], al_, bh+2);
        }
    }
}

// 128x32 x128: A XOR tile, B XOR tile with 32 rows
__device__ __forceinline__ void gemm128_n32(uint32_t Ah, uint32_t Al, uint32_t Bh, uint32_t Bl,
                                            int warp, int lane, float d[4][4]){
#pragma unroll
    for (int t = 0; t < 4; t++){ d[t][0]=0.f; d[t][1]=0.f; d[t][2]=0.f; d[t][3]=0.f; }
    const uint32_t aro = (uint32_t)((warp*16 + (lane&15))*256);
    const uint32_t aox = (uint32_t)((lane&7)<<4);
    const uint32_t akx = (uint32_t)(lane&16);
    const uint32_t bro = (uint32_t)(((lane&7) + ((lane>>4)<<3))*256);
    const uint32_t bkx = (uint32_t)((lane&8)<<1);
#pragma unroll 1
    for (int kk = 0; kk < 8; kk++){
        uint32_t ka = (uint32_t)(kk*32);
        uint32_t ah[4], al_[4];
        ldsm4(ah,  Ah + aro + ((ka + akx) ^ aox));
        ldsm4(al_, Al + aro + ((ka + akx) ^ aox));
        uint32_t bo = bro + ((ka + bkx) ^ aox);
#pragma unroll
        for (int t2 = 0; t2 < 2; t2++){
            uint32_t bh[4], bl[4];
            ldsm4(bh, Bh + bo + (uint32_t)(t2*4096));
            ldsm4(bl, Bl + bo + (uint32_t)(t2*4096));
            mma16816(d[2*t2],   ah,  bh);
            mma16816(d[2*t2],   ah,  bl);
            mma16816(d[2*t2],   al_, bh);
            mma16816(d[2*t2+1], ah,  bh+2);
            mma16816(d[2*t2+1], ah,  bl+2);
            mma16816(d[2*t2+1], al_, bh+2);
        }
    }
}

// ---------------- K0: weight prep ----------------
__global__ void k0_prep(const float* __restrict__ wq, const float* __restrict__ wk,
                        const float* __restrict__ wv, const float* __restrict__ w1,
                        const float* __restrict__ w2, const float* __restrict__ pe2,
                        const float* __restrict__ e2, const float* __restrict__ x1){
    int idx = blockIdx.x * blockDim.x + threadIdx.x;
    int stride = gridDim.x * blockDim.x;
    for (int t = idx; t < 16384; t += stride){
        int c = t >> 7, m = t & 127;
        uint32_t a = swz(c, m*2) >> 1;
        float v1 = w1[t];
        __nv_bfloat16 h1 = __float2bfloat16(v1);
        ((unsigned short*)g_w1hi)[a] = __bfloat16_as_ushort(h1);
        ((unsigned short*)g_w1lo)[a] = __bfloat16_as_ushort(__float2bfloat16(v1 - __bfloat162float(h1)));
        float v2 = w2[t];
        __nv_bfloat16 h2 = __float2bfloat16(v2);
        ((unsigned short*)g_w2hi)[a] = __bfloat16_as_ushort(h2);
        ((unsigned short*)g_w2lo)[a] = __bfloat16_as_ushort(__float2bfloat16(v2 - __bfloat162float(h2)));
    }
    for (int t = idx; t < 4096; t += stride){
        int c = t >> 5, m = t & 31;
        uint32_t a80 = (uint32_t)(c*40 + m);
        float vp = pe2[t];
        __nv_bfloat16 hp = __float2bfloat16(vp);
        ((unsigned short*)g_pe2hi)[a80] = __bfloat16_as_ushort(hp);
        ((unsigned short*)g_pe2lo)[a80] = __bfloat16_as_ushort(__float2bfloat16(vp - __bfloat162float(hp)));
        float ve = e2[t];
        __nv_bfloat16 he = __float2bfloat16(ve);
        ((unsigned short*)g_e2hi)[a80] = __bfloat16_as_ushort(he);
        ((unsigned short*)g_e2lo)[a80] = __bfloat16_as_ushort(__float2bfloat16(ve - __bfloat162float(he)));
        int m2 = t >> 7, c2 = t & 127;
        uint32_t ax = swz(m2, c2*2) >> 1;
        float vx = x1[t];
        __nv_bfloat16 hx = __float2bfloat16(vx);
        ((unsigned short*)g_x1hi)[ax] = __bfloat16_as_ushort(hx);
        ((unsigned short*)g_x1lo)[ax] = __bfloat16_as_ushort(__float2bfloat16(vx - __bfloat162float(hx)));
    }
    for (int t = idx; t < 8192; t += stride){
        int c = t >> 6, d = t & 63;
        g_wqT[d*128 + c] = wq[t];
        g_wkT[d*128 + c] = wk[t];
        g_wvT[d*128 + c] = wv[t];
    }
}

// ---------------- K1: q,k,v projections ----------------
__global__ void __launch_bounds__(128) k1_qkv(const float* __restrict__ x,
                                              const float* __restrict__ bq,
                                              const float* __restrict__ bk,
                                              const float* __restrict__ bv){
    __shared__ float sx[64];
    int row = blockIdx.x;
    int c = threadIdx.x;
    if (c < 64) sx[c] = x[(size_t)row*64 + c];
    __syncthreads();
    float aq = bq[c], ak = bk[c], av = bv[c];
#pragma unroll 8
    for (int d = 0; d < 64; d++){
        float xv = sx[d];
        aq = fmaf(xv, g_wqT[d*128 + c], aq);
        ak = fmaf(xv, g_wkT[d*128 + c], ak);
        av = fmaf(xv, g_wvT[d*128 + c], av);
    }
    g_q[(size_t)row*128 + c] = aq;
    g_k[(size_t)row*128 + c] = ak;
    g_v[(size_t)row*128 + c] = av;
}

// ---------------- K2: fused attention per (n,i) ----------------
__global__ void __launch_bounds__(256) k2_attn(
    const float* __restrict__ U, const float* __restrict__ p,
    const float* __restrict__ ln1_g, const float* __restrict__ ln1_b,
    const float* __restrict__ b1,
    const float* __restrict__ ln2_g, const float* __restrict__ ln2_b,
    const float* __restrict__ b2,
    const float* __restrict__ pe1,
    float* __restrict__ xout)
{
    extern __shared__ char sm8[];
    float* sxv  = (float*)(sm8 + XV_B);
    float* sLog = (float*)(sm8 + LOG_B);     // [128][130]
    float* sk   = (float*)(sm8 + SK_B);
    float* sg1  = (float*)(sm8 + SG1_B);
    float* sb1v = (float*)(sm8 + SB1_B);
    float* sg2  = (float*)(sm8 + SG2_B);
    float* sb2v = (float*)(sm8 + SB2_B);
    float* sbi1 = (float*)(sm8 + SBI1_B);
    float* sbi2 = (float*)(sm8 + SBI2_B);
    float* spe1 = (float*)(sm8 + SPE1_B);
    float* spij = (float*)(sm8 + SPIJ_B);
    float* sred = (float*)(sm8 + SRED_B);

    const uint32_t sbase = smem_u32(sm8);
    const uint32_t Ah = sbase + A_HI_B, Al = sbase + A_LO_B;
    const uint32_t Wh = sbase + W_HI_B, Wl = sbase + W_LO_B;
    const uint32_t Th = sbase + TN_HI_B, Tl = sbase + TN_LO_B;
    const int tid = threadIdx.x;
    const int lane = tid & 31, warp = tid >> 5;
    const int n = blockIdx.x >> 7, i = blockIdx.x & 127;

    // ----- stage 0 -----
    if (tid < 128){
        size_t rowk = (size_t)(n*128 + i);
        sk[tid]   = g_k[rowk*128 + tid];
        sg1[tid]  = ln1_g[tid];  sb1v[tid] = ln1_b[tid];
        sg2[tid]  = ln2_g[tid];  sb2v[tid] = ln2_b[tid];
        sbi1[tid] = b1[tid];     sbi2[tid] = b2[tid];
        spe1[tid] = pe1[tid];
        int j = tid;
        float4 pi = *(const float4*)(p + (size_t)(n*128 + i)*4);
        float4 pj = *(const float4*)(p + (size_t)(n*128 + j)*4);
        spij[j*4+0] = pi.x - pj.x;
        spij[j*4+1] = pi.y - pj.y;
        spij[j*4+2] = pi.z - pj.z;
        spij[j*4+3] = pi.w - pj.w;
    }
    // pe2 tiles into W region (80B-stride format)
    for (int t = tid; t < 2560; t += 256){
        ((uint32_t*)(sm8 + W_HI_B))[t] = g_pe2hi[t];
        ((uint32_t*)(sm8 + W_LO_B))[t] = g_pe2lo[t];
    }
    const bool pad_i = (p[(size_t)(n*128 + i)*4] == 0.0f);
    __syncthreads();

    // ----- tn = relu(LN32(pij @ pe1^T)) -> 80B-stride bf16 tiles -----
    float4 pe1r = ((const float4*)spe1)[lane];
    for (int jj = warp; jj < 128; jj += 8){
        float4 pd = *(const float4*)(spij + jj*4);
        float t = pd.x*pe1r.x + pd.y*pe1r.y + pd.z*pe1r.z + pd.w*pe1r.w;
        float mu = wsum(t) * (1.0f/32.0f);
        float dd = t - mu;
        float var = wsum(dd*dd) * (1.0f/32.0f);
        float tn = fmaxf(dd * rsqrtf(var + 1e-5f), 0.0f);
        float tn1 = __shfl_down_sync(0xffffffffu, tn, 1);
        if (!(lane & 1)){
            uint32_t hi, lo;
            split2(tn, tn1, hi, lo);
            *(uint32_t*)(sm8 + TN_HI_B + jj*80 + lane*2) = hi;
            *(uint32_t*)(sm8 + TN_LO_B + jj*80 + lane*2) = lo;
        }
    }
    __syncthreads();

    // ----- GEMM0: eqpe_pre = tn @ pe2^T -----
    float d[16][4];
    gemm32(Th, Tl, Wh, Wl, warp, lane, d);
    __syncthreads();

    // W1 copy (W region free now)
    for (int t = tid; t < 8192; t += 256){
        ((uint32_t*)(sm8 + W_HI_B))[t] = g_w1hi[t];
        ((uint32_t*)(sm8 + W_LO_B))[t] = g_w1lo[t];
    }

    // ----- epilogue0: LN(eqpe_pre), relu -> e; xv = v+U+e; r = k-q+U+e; LN1 -> A1 -----
    {
        const int g4 = lane & 3;
        const int rowA = warp*16 + (lane>>2), rowB = rowA + 8;
        float s1A = 0, s2A = 0, s1B = 0, s2B = 0;
#pragma unroll
        for (int t = 0; t < 16; t++){
            s1A += d[t][0] + d[t][1]; s2A += d[t][0]*d[t][0] + d[t][1]*d[t][1];
            s1B += d[t][2] + d[t][3]; s2B += d[t][2]*d[t][2] + d[t][3]*d[t][3];
        }
        s1A += __shfl_xor_sync(~0u, s1A, 1); s1A += __shfl_xor_sync(~0u, s1A, 2);
        s2A += __shfl_xor_sync(~0u, s2A, 1); s2A += __shfl_xor_sync(~0u, s2A, 2);
        s1B += __shfl_xor_sync(~0u, s1B, 1); s1B += __shfl_xor_sync(~0u, s1B, 2);
        s2B += __shfl_xor_sync(~0u, s2B, 1); s2B += __shfl_xor_sync(~0u, s2B, 2);
        float muA = s1A*(1.0f/128.0f), rsA = rsqrtf(s2A*(1.0f/128.0f) - muA*muA + 1e-5f);
        float muB = s1B*(1.0f/128.0f), rsB = rsqrtf(s2B*(1.0f/128.0f) - muB*muB + 1e-5f);

        const float* Ub  = U + (size_t)blockIdx.x * 16384;
        const float* qb  = g_q + (size_t)n*16384;
        const float* vb  = g_v + (size_t)n*16384;
        float t1A = 0, t2A = 0, t1B = 0, t2B = 0;
#pragma unroll
        for (int t = 0; t < 16; t++){
            int c0 = t*8 + g4*2;
            float2 uA = *(const float2*)(Ub + rowA*128 + c0);
            float2 uB = *(const float2*)(Ub + rowB*128 + c0);
            float2 qA = *(const float2*)(qb + rowA*128 + c0);
            float2 qB = *(const float2*)(qb + rowB*128 + c0);
            float2 vA = *(const float2*)(vb + rowA*128 + c0);
            float2 vB = *(const float2*)(vb + rowB*128 + c0);
            float2 kc = *(const float2*)(sk + c0);
            float eA0 = fmaxf((d[t][0]-muA)*rsA, 0.0f) + uA.x;
            float eA1 = fmaxf((d[t][1]-muA)*rsA, 0.0f) + uA.y;
            float eB0 = fmaxf((d[t][2]-muB)*rsB, 0.0f) + uB.x;
            float eB1 = fmaxf((d[t][3]-muB)*rsB, 0.0f) + uB.y;
            *(float2*)(sxv + rowA*128 + c0) = make_float2(vA.x + eA0, vA.y + eA1);
            *(float2*)(sxv + rowB*128 + c0) = make_float2(vB.x + eB0, vB.y + eB1);
            float rA0 = kc.x - qA.x + eA0;
            float rA1 = kc.y - qA.y + eA1;
            float rB0 = kc.x - qB.x + eB0;
            float rB1 = kc.y - qB.y + eB1;
            d[t][0] = rA0; d[t][1] = rA1; d[t][2] = rB0; d[t][3] = rB1;
            t1A += rA0 + rA1; t2A += rA0*rA0 + rA1*rA1;
            t1B += rB0 + rB1; t2B += rB0*rB0 + rB1*rB1;
        }
        t1A += __shfl_xor_sync(~0u, t1A, 1); t1A += __shfl_xor_sync(~0u, t1A, 2);
        t2A += __shfl_xor_sync(~0u, t2A, 1); t2A += __shfl_xor_sync(~0u, t2A, 2);
        t1B += __shfl_xor_sync(~0u, t1B, 1); t1B += __shfl_xor_sync(~0u, t1B, 2);
        t2B += __shfl_xor_sync(~0u, t2B, 1); t2B += __shfl_xor_sync(~0u, t2B, 2);
        float nuA = t1A*(1.0f/128.0f), nsA = rsqrtf(t2A*(1.0f/128.0f) - nuA*nuA + 1e-5f);
        float nuB = t1B*(1.0f/128.0f), nsB = rsqrtf(t2B*(1.0f/128.0f) - nuB*nuB + 1e-5f);
#pragma unroll
        for (int t = 0; t < 16; t++){
            int c0 = t*8 + g4*2;
            float2 gg = *(float2*)(sg1 + c0);
            float2 bb = *(float2*)(sb1v + c0);
            float yA0 = fmaxf(fmaf((d[t][0]-nuA)*nsA, gg.x, bb.x), 0.0f);
            float yA1 = fmaxf(fmaf((d[t][1]-nuA)*nsA, gg.y, bb.y), 0.0f);
            float yB0 = fmaxf(fmaf((d[t][2]-nuB)*nsB, gg.x, bb.x), 0.0f);
            float yB1 = fmaxf(fmaf((d[t][3]-nuB)*nsB, gg.y, bb.y), 0.0f);
            uint32_t hA, lA, hB, lB;
            split2(yA0, yA1, hA, lA);
            split2(yB0, yB1, hB, lB);
            int kb = t*16 + g4*4;
            *(uint32_t*)(sm8 + A_HI_B + swz(rowA, kb)) = hA;
            *(uint32_t*)(sm8 + A_LO_B + swz(rowA, kb)) = lA;
            *(uint32_t*)(sm8 + A_HI_B + swz(rowB, kb)) = hB;
            *(uint32_t*)(sm8 + A_LO_B + swz(rowB, kb)) = lB;
        }
    }
    __syncthreads();

    // ----- GEMM1 -----
    gemm128(Ah, Al, Wh, Wl, warp, lane, d);
    __syncthreads();

    // ----- epilogue1: +b1, LN(g2,b2), relu -> A2; W2 copy -----
    for (int t = tid; t < 8192; t += 256){
        ((uint32_t*)(sm8 + W_HI_B))[t] = g_w2hi[t];
        ((uint32_t*)(sm8 + W_LO_B))[t] = g_w2lo[t];
    }
    {
        const int g4 = lane & 3;
        const int rowA = warp*16 + (lane>>2), rowB = rowA + 8;
        float s1A = 0, s2A = 0, s1B = 0, s2B = 0;
#pragma unroll
        for (int t = 0; t < 16; t++){
            int c0 = t*8 + g4*2;
            float2 bb = *(float2*)(sbi1 + c0);
            d[t][0] += bb.x; d[t][1] += bb.y;
            d[t][2] += bb.x; d[t][3] += bb.y;
            s1A += d[t][0] + d[t][1]; s2A += d[t][0]*d[t][0] + d[t][1]*d[t][1];
            s1B += d[t][2] + d[t][3]; s2B += d[t][2]*d[t][2] + d[t][3]*d[t][3];
        }
        s1A += __shfl_xor_sync(~0u, s1A, 1); s1A += __shfl_xor_sync(~0u, s1A, 2);
        s2A += __shfl_xor_sync(~0u, s2A, 1); s2A += __shfl_xor_sync(~0u, s2A, 2);
        s1B += __shfl_xor_sync(~0u, s1B, 1); s1B += __shfl_xor_sync(~0u, s1B, 2);
        s2B += __shfl_xor_sync(~0u, s2B, 1); s2B += __shfl_xor_sync(~0u, s2B, 2);
        float muA = s1A*(1.0f/128.0f), rsA = rsqrtf(s2A*(1.0f/128.0f) - muA*muA + 1e-5f);
        float muB = s1B*(1.0f/128.0f), rsB = rsqrtf(s2B*(1.0f/128.0f) - muB*muB + 1e-5f);
#pragma unroll
        for (int t = 0; t < 16; t++){
            int c0 = t*8 + g4*2;
            float2 gg = *(float2*)(sg2 + c0);
            float2 bb = *(float2*)(sb2v + c0);
            float yA0 = fmaxf(fmaf((d[t][0]-muA)*rsA, gg.x, bb.x), 0.0f);
            float yA1 = fmaxf(fmaf((d[t][1]-muA)*rsA, gg.y, bb.y), 0.0f);
            float yB0 = fmaxf(fmaf((d[t][2]-muB)*rsB, gg.x, bb.x), 0.0f);
            float yB1 = fmaxf(fmaf((d[t][3]-muB)*rsB, gg.y, bb.y), 0.0f);
            uint32_t hA, lA, hB, lB;
            split2(yA0, yA1, hA, lA);
            split2(yB0, yB1, hB, lB);
            int kb = t*16 + g4*4;
            *(uint32_t*)(sm8 + A_HI_B + swz(rowA, kb)) = hA;
            *(uint32_t*)(sm8 + A_LO_B + swz(rowA, kb)) = lA;
            *(uint32_t*)(sm8 + A_HI_B + swz(rowB, kb)) = hB;
            *(uint32_t*)(sm8 + A_LO_B + swz(rowB, kb)) = lB;
        }
    }
    __syncthreads();

    // ----- GEMM2 -----
    gemm128(Ah, Al, Wh, Wl, warp, lane, d);
    __syncthreads();

    // ----- epilogue2: +b2, mask -> logits -----
    {
        const int g4 = lane & 3;
        const int rowA = warp*16 + (lane>>2), rowB = rowA + 8;
#pragma unroll
        for (int t = 0; t < 16; t++){
            int c0 = t*8 + g4*2;
            float2 bb = *(float2*)(sbi2 + c0);
            float vA0 = d[t][0] + bb.x, vA1 = d[t][1] + bb.y;
            float vB0 = d[t][2] + bb.x, vB1 = d[t][3] + bb.y;
            if (pad_i){ vA0 = NEGV; vA1 = NEGV; vB0 = NEGV; vB1 = NEGV; }
            *(float2*)(sLog + rowA*130 + c0) = make_float2(vA0, vA1);
            *(float2*)(sLog + rowB*130 + c0) = make_float2(vB0, vB1);
        }
    }
    __syncthreads();

    // ----- softmax over j + weighted sum of xv -----
    {
        const int c = tid & 127, half = tid >> 7;
        const int jb = half * 64;
        float M = -3.4e38f;
        for (int j = jb; j < jb + 64; j++) M = fmaxf(M, sLog[j*130 + c]);
        sred[half*128 + c] = M;
        __syncthreads();
        M = fmaxf(sred[c], sred[128 + c]);
        __syncthreads();
        float den = 0, num = 0;
        for (int j = jb; j < jb + 64; j++){
            float w = __expf(sLog[j*130 + c] - M);
            den += w;
            num = fmaf(w, sxv[j*128 + c], num);
        }
        sred[half*128 + c]       = den;
        sred[256 + half*128 + c] = num;
        __syncthreads();
        if (half == 0){
            float dtot = sred[c] + sred[128 + c];
            float ntot = sred[256 + c] + sred[384 + c];
            xout[(size_t)blockIdx.x*128 + c] = ntot / dtot;
        }
    }
}

// ---------------- K2b: avec/bvec = e1 row projections of x_out ----------------
__global__ void __launch_bounds__(64) k2b_vec(const float* __restrict__ xout,
                                              const float* __restrict__ e1){
    __shared__ float sx[128];
    int row = blockIdx.x;
    int tid = threadIdx.x;
    sx[tid]      = xout[(size_t)row*128 + tid];
    sx[tid + 64] = xout[(size_t)row*128 + tid + 64];
    __syncthreads();
    int lane = tid & 31;
    const float* er = e1 + lane*257 + ((tid >= 32) ? 128 : 0);
    float a = 0;
#pragma unroll 8
    for (int c2 = 0; c2 < 128; c2++) a = fmaf(sx[c2], er[c2], a);
    if (tid < 32) g_avec[(size_t)row*32 + lane] = a;
    else          g_bvec[(size_t)row*32 + lane] = a;
}

// ---------------- K3: message MLP + position update per (n,i), MMA ----------------
__global__ void __launch_bounds__(256) k3_msg(
    const float* __restrict__ p, const float* __restrict__ e1,
    const float* __restrict__ x1b, const float* __restrict__ x2,
    const float* __restrict__ x2b,
    float* __restrict__ outp)
{
    extern __shared__ char sm8[];
    float* spij  = (float*)(sm8 + K3_SPIJ);
    float* snorm = (float*)(sm8 + K3_SNORM);
    float* ss    = (float*)(sm8 + K3_SS);
    float* spad  = (float*)(sm8 + K3_SPAD);
    float* sa    = (float*)(sm8 + K3_SA);
    float* se1c  = (float*)(sm8 + K3_SE1C);
    float* sx1b_ = (float*)(sm8 + K3_SX1B);
    float* sx2v  = (float*)(sm8 + K3_SX2V);

    const uint32_t sbase = smem_u32(sm8);
    const int tid = threadIdx.x, lane = tid & 31, warp = tid >> 5;
    const int n = blockIdx.x >> 7, i = blockIdx.x & 127;
    const bool pad_i = (p[(size_t)(n*128 + i)*4] == 0.0f);

    if (tid < 128){
        int j = tid;
        float4 pi = *(const float4*)(p + (size_t)(n*128 + i)*4);
        float4 pj = *(const float4*)(p + (size_t)(n*128 + j)*4);
        float dx = pi.x - pj.x, dy = pi.y - pj.y, dz = pi.z - pj.z, dw = pi.w - pj.w;
        spij[j*4+0] = dx; spij[j*4+1] = dy; spij[j*4+2] = dz; spij[j*4+3] = dw;
        spad[j] = (pj.x != 0.0f) ? 1.0f : 0.0f;
        snorm[j] = pad_i ? 0.0f : (dw*dw - dx*dx - dy*dy - dz*dz);
    }
    if (tid < 32){
        sa[tid]    = g_avec[(size_t)(n*128 + i)*32 + tid];
        se1c[tid]  = e1[tid*257 + 256];
        sx1b_[tid] = x1b[tid];
        sx2v[tid]  = x2[tid];
    }
    for (int t = tid; t < 2560; t += 256){
        ((uint32_t*)(sm8 + K3_B1H))[t] = g_e2hi[t];
        ((uint32_t*)(sm8 + K3_B1L))[t] = g_e2lo[t];
    }
    for (int t = tid; t < 2048; t += 256){
        ((uint32_t*)(sm8 + K3_B2H))[t] = g_x1hi[t];
        ((uint32_t*)(sm8 + K3_B2L))[t] = g_x1lo[t];
    }
    __syncthreads();

    // h32 tile: relu(a_i + b_j + norm*e1c) -> 80B bf16 tiles
    const float* bv = g_bvec + (size_t)n*4096;
    for (int idx = tid; idx < 2048; idx += 256){
        int row = idx >> 4, mp = idx & 15, m = mp*2;
        float nb = snorm[row];
        float2 bb = *(const float2*)(bv + row*32 + m);
        float h0 = fmaxf(sa[m]   + bb.x + nb*se1c[m],   0.0f);
        float h1 = fmaxf(sa[m+1] + bb.y + nb*se1c[m+1], 0.0f);
        uint32_t hi, lo;
        split2(h0, h1, hi, lo);
        *(uint32_t*)(sm8 + K3_A1H + row*80 + mp*4) = hi;
        *(uint32_t*)(sm8 + K3_A1L + row*80 + mp*4) = lo;
    }
    __syncthreads();

    // MMA1: mij_pre = h32 @ e2^T
    float d[16][4];
    gemm32(sbase + K3_A1H, sbase + K3_A1L, sbase + K3_B1H, sbase + K3_B1L, warp, lane, d);

    // epilogue: relu -> mask -> LN(no affine) -> y -> A2 tile
    {
        const int g4 = lane & 3;
        const int rowA = warp*16 + (lane>>2), rowB = rowA + 8;
        float s1A = 0, s2A = 0, s1B = 0, s2B = 0;
#pragma unroll
        for (int t = 0; t < 16; t++){
            float a0 = fmaxf(d[t][0], 0.0f), a1 = fmaxf(d[t][1], 0.0f);
            float b0 = fmaxf(d[t][2], 0.0f), b1 = fmaxf(d[t][3], 0.0f);
            if (pad_i){ a0 = NEGV; a1 = NEGV; b0 = NEGV; b1 = NEGV; }
            d[t][0] = a0; d[t][1] = a1; d[t][2] = b0; d[t][3] = b1;
            s1A += a0 + a1; s2A += a0*a0 + a1*a1;
            s1B += b0 + b1; s2B += b0*b0 + b1*b1;
        }
        s1A += __shfl_xor_sync(~0u, s1A, 1); s1A += __shfl_xor_sync(~0u, s1A, 2);
        s2A += __shfl_xor_sync(~0u, s2A, 1); s2A += __shfl_xor_sync(~0u, s2A, 2);
        s1B += __shfl_xor_sync(~0u, s1B, 1); s1B += __shfl_xor_sync(~0u, s1B, 2);
        s2B += __shfl_xor_sync(~0u, s2B, 1); s2B += __shfl_xor_sync(~0u, s2B, 2);
        float muA = s1A*(1.0f/128.0f), vA = s2A*(1.0f/128.0f) - muA*muA;
        float muB = s1B*(1.0f/128.0f), vB = s2B*(1.0f/128.0f) - muB*muB;
        float rsA = rsqrtf(fmaxf(vA, 0.0f) + 1e-5f);
        float rsB = rsqrtf(fmaxf(vB, 0.0f) + 1e-5f);
#pragma unroll
        for (int t = 0; t < 16; t++){
            float yA0 = (d[t][0]-muA)*rsA, yA1 = (d[t][1]-muA)*rsA;
            float yB0 = (d[t][2]-muB)*rsB, yB1 = (d[t][3]-muB)*rsB;
            uint32_t hA, lA, hB, lB;
            split2(yA0, yA1, hA, lA);
            split2(yB0, yB1, hB, lB);
            int kb = t*16 + g4*4;
            *(uint32_t*)(sm8 + K3_A2H + swz(rowA, kb)) = hA;
            *(uint32_t*)(sm8 + K3_A2L + swz(rowA, kb)) = lA;
            *(uint32_t*)(sm8 + K3_A2H + swz(rowB, kb)) = hB;
            *(uint32_t*)(sm8 + K3_A2L + swz(rowB, kb)) = lB;
        }
    }
    __syncthreads();

    // MMA2: t_pre = y @ x1^T (N=32)
    float d2[4][4];
    gemm128_n32(sbase + K3_A2H, sbase + K3_A2L, sbase + K3_B2H, sbase + K3_B2L, warp, lane, d2);

    // scores
    {
        const int g4 = lane & 3;
        const int rowA = warp*16 + (lane>>2), rowB = rowA + 8;
        float x2bv = x2b[0];
        float sA = 0, sB = 0;
#pragma unroll
        for (int t = 0; t < 4; t++){
            int c0 = t*8 + g4*2;
            float2 xb = *(float2*)(sx1b_ + c0);
            float2 xv = *(float2*)(sx2v + c0);
            sA += fmaxf(d2[t][0] + xb.x, 0.0f)*xv.x + fmaxf(d2[t][1] + xb.y, 0.0f)*xv.y;
            sB += fmaxf(d2[t][2] + xb.x, 0.0f)*xv.x + fmaxf(d2[t][3] + xb.y, 0.0f)*xv.y;
        }
        sA += __shfl_xor_sync(~0u, sA, 1); sA += __shfl_xor_sync(~0u, sA, 2);
        sB += __shfl_xor_sync(~0u, sB, 1); sB += __shfl_xor_sync(~0u, sB, 2);
        if (g4 == 0){
            ss[rowA] = fmaxf(sA + x2bv, 0.0f);
            ss[rowB] = fmaxf(sB + x2bv, 0.0f);
        }
    }
    __syncthreads();

    if (warp == 0){
        float m0 = fmaxf(fmaxf(ss[lane], ss[lane+32]), fmaxf(ss[lane+64], ss[lane+96]));
#pragma unroll
        for (int k = 16; k > 0; k >>= 1) m0 = fmaxf(m0, __shfl_xor_sync(0xffffffffu, m0, k));
        float den = 0, dx = 0, dy = 0, dz = 0, dw = 0, cnt = 0;
#pragma unroll
        for (int q2 = 0; q2 < 4; q2++){
            int b = lane + 32*q2;
            float w = __expf(ss[b] - m0);
            den += w;
            dx = fmaf(w, spij[b*4+0], dx);
            dy = fmaf(w, spij[b*4+1], dy);
            dz = fmaf(w, spij[b*4+2], dz);
            dw = fmaf(w, spij[b*4+3], dw);
            cnt += spad[b];
        }
        den = wsum(den); dx = wsum(dx); dy = wsum(dy);
        dz = wsum(dz);   dw = wsum(dw); cnt = wsum(cnt);
        if (lane == 0){
            float inv = 1.0f / (den * cnt);
            const float* pr = p + (size_t)(n*128 + i)*4;
            float* o = outp + (size_t)(n*128 + i)*4;
            float d4[4] = {dx, dy, dz, dw};
#pragma unroll
            for (int dd = 0; dd < 4; dd++){
                float pv = pr[dd];
                o[dd] = (pv == 0.0f) ? 0.0f : pv + d4[dd]*inv;
            }
        }
    }
}

extern "C" void kernel_launch(void* const* d_in, const int* in_sizes, int n_in,
                              void* d_out, int out_size){
    const float* x     = (const float*)d_in[0];
    const float* p     = (const float*)d_in[1];
    const float* U     = (const float*)d_in[2];
    const float* wq    = (const float*)d_in[3];
    const float* bq    = (const float*)d_in[4];
    const float* wk    = (const float*)d_in[5];
    const float* bk    = (const float*)d_in[6];
    const float* wv    = (const float*)d_in[7];
    const float* bv    = (const float*)d_in[8];
    const float* ln1_g = (const float*)d_in[9];
    const float* ln1_b = (const float*)d_in[10];
    const float* w1    = (const float*)d_in[11];
    const float* b1    = (const float*)d_in[12];
    const float* ln2_g = (const float*)d_in[13];
    const float* ln2_b = (const float*)d_in[14];
    const float* w2    = (const float*)d_in[15];
    const float* b2    = (const float*)d_in[16];
    const float* pe1   = (const float*)d_in[17];
    const float* pe2   = (const float*)d_in[18];
    const float* e1    = (const float*)d_in[19];
    const float* e2    = (const float*)d_in[20];
    const float* x1    = (const float*)d_in[21];
    const float* x1b   = (const float*)d_in[22];
    const float* x2    = (const float*)d_in[23];
    const float* x2b   = (const float*)d_in[24];
    float* out  = (float*)d_out;
    float* xout = out;                 // (16,128,128)
    float* newp = out + 16*128*128;    // (16,128,4)

    cudaFuncSetAttribute(k2_attn, cudaFuncAttributeMaxDynamicSharedMemorySize, K2_SMEM);
    cudaFuncSetAttribute(k3_msg,  cudaFuncAttributeMaxDynamicSharedMemorySize, K3_SMEM);

    k0_prep<<<64, 256>>>(wq, wk, wv, w1, w2, pe2, e2, x1);
    k1_qkv<<<2048, 128>>>(x, bq, bk, bv);
    k2_attn<<<2048, 256, K2_SMEM>>>(U, p, ln1_g, ln1_b, b1, ln2_g, ln2_b, b2, pe1, xout);
    k2b_vec<<<2048, 64>>>(xout, e1);
    k3_msg<<<2048, 256, K3_SMEM>>>(p, e1, x1b, x2, x2b, newp);
}

// round 6
// speedup vs baseline: 2.3529x; 1.1003x over previous
#include <cuda_runtime.h>
#include <cuda_bf16.h>
#include <math.h>
#include <stdint.h>

#define NEGV (-10000.0f)

// ---------------- K2 smem byte offsets ----------------
#define XVT_B    0          // fp32 xvT [128][130] (66560B); pe2/tn tiles alias front pre-epilogue0
#define PE2H_B   0          // 10240
#define PE2L_B   10240
#define TNH_B    20480
#define TNL_B    30720
#define A_HI_B   67584      // bf16 A tile hi (32KB, XOR swizzle)
#define A_LO_B   100352
#define W_HI_B   133120     // bf16 W tile hi (32KB): w1 -> w2
#define W_LO_B   165888
#define SK_B     198656
#define SG1_B    199168
#define SB1_B    199680
#define SG2_B    200192
#define SB2_B    200704
#define SBI1_B   201216
#define SBI2_B   201728
#define SPE1_B   202240
#define SPIJ_B   202752     // 2048
#define SXO_B    204800     // 512
#define K2_SMEM  205312

// ---------------- K3 smem byte offsets ----------------
#define K3_A1H   0          // h32 tile hi (80B-stride, 10240); aliased by A2 later
#define K3_A1L   10240
#define K3_B1H   20480      // e2 tile (80B), aliased by A2 later
#define K3_B1L   30720
#define K3_A2H   0          // y tile (XOR, 32KB each) aliases A1+B1
#define K3_A2L   32768
#define K3_B2H   65536      // x1 tile (XOR, 32 rows, 8KB each)
#define K3_B2L   73728
#define K3_SPIJ  81920      // 2048
#define K3_SNORM 83968      // 512
#define K3_SS    84480      // 512
#define K3_SPAD  84992      // 512
#define K3_SA    85504      // 128
#define K3_SE1C  85632      // 128
#define K3_SX1B  85760      // 128
#define K3_SX2V  85888      // 128
#define K3_SMEM  86016

// ---------------- device scratch ----------------
__device__ float g_q[16*128*128];
__device__ float g_k[16*128*128];
__device__ float g_v[16*128*128];
__device__ float g_wqT[64*128];
__device__ float g_wkT[64*128];
__device__ float g_wvT[64*128];
__device__ float g_avec[16*128*32];
__device__ float g_bvec[16*128*32];
// XOR-swizzled [n][k] bf16 tiles (256B rows)
__device__ uint32_t g_w1hi[8192];
__device__ uint32_t g_w1lo[8192];
__device__ uint32_t g_w2hi[8192];
__device__ uint32_t g_w2lo[8192];
__device__ uint32_t g_x1hi[2048];
__device__ uint32_t g_x1lo[2048];
// 80B-stride [n][k<32] bf16 tiles
__device__ uint32_t g_pe2hi[2560];
__device__ uint32_t g_pe2lo[2560];
__device__ uint32_t g_e2hi[2560];
__device__ uint32_t g_e2lo[2560];

// ---------------- helpers ----------------
__device__ __forceinline__ float wsum(float v){
#pragma unroll
    for (int k = 16; k > 0; k >>= 1) v += __shfl_xor_sync(0xffffffffu, v, k);
    return v;
}
__device__ __forceinline__ float qsum(float v){
    v += __shfl_xor_sync(0xffffffffu, v, 1);
    v += __shfl_xor_sync(0xffffffffu, v, 2);
    return v;
}
__device__ __forceinline__ float qmax(float v){
    v = fmaxf(v, __shfl_xor_sync(0xffffffffu, v, 1));
    v = fmaxf(v, __shfl_xor_sync(0xffffffffu, v, 2));
    return v;
}
__device__ __forceinline__ uint32_t smem_u32(const void* p){
    uint32_t a;
    asm("{ .reg .u64 t; cvta.to.shared.u64 t, %1; cvt.u32.u64 %0, t; }" : "=r"(a) : "l"(p));
    return a;
}
__device__ __forceinline__ uint32_t swz(int row, int kb){
    return (uint32_t)(row*256 + ((kb & 0xF0) ^ ((row & 7) << 4)) + (kb & 15));
}
__device__ __forceinline__ void split2(float x, float y, uint32_t &hi, uint32_t &lo){
    __nv_bfloat16 hx = __float2bfloat16(x), hy = __float2bfloat16(y);
    __nv_bfloat16 lx = __float2bfloat16(x - __bfloat162float(hx));
    __nv_bfloat16 ly = __float2bfloat16(y - __bfloat162float(hy));
    hi = (uint32_t)__bfloat16_as_ushort(hx) | ((uint32_t)__bfloat16_as_ushort(hy) << 16);
    lo = (uint32_t)__bfloat16_as_ushort(lx) | ((uint32_t)__bfloat16_as_ushort(ly) << 16);
}
__device__ __forceinline__ void ldsm4(uint32_t a[4], uint32_t addr){
    asm volatile("ldmatrix.sync.aligned.m8n8.x4.shared.b16 {%0,%1,%2,%3}, [%4];"
        : "=r"(a[0]), "=r"(a[1]), "=r"(a[2]), "=r"(a[3]) : "r"(addr));
}
__device__ __forceinline__ void mma16816(float d[4], const uint32_t a[4], const uint32_t b[2]){
    asm volatile("mma.sync.aligned.m16n8k16.row.col.f32.bf16.bf16.f32 "
        "{%0,%1,%2,%3}, {%4,%5,%6,%7}, {%8,%9}, {%0,%1,%2,%3};"
        : "+f"(d[0]), "+f"(d[1]), "+f"(d[2]), "+f"(d[3])
        : "r"(a[0]), "r"(a[1]), "r"(a[2]), "r"(a[3]), "r"(b[0]), "r"(b[1]));
}

// 128x128x128: warp computes A-rows warp*16..+15 vs all 128 B-rows. XOR tiles.
__device__ __forceinline__ void gemm128(uint32_t Ah, uint32_t Al, uint32_t Wh, uint32_t Wl,
                                        int warp, int lane, float d[16][4]){
#pragma unroll
    for (int t = 0; t < 16; t++){ d[t][0]=0.f; d[t][1]=0.f; d[t][2]=0.f; d[t][3]=0.f; }
    const uint32_t aro = (uint32_t)((warp*16 + (lane&15))*256);
    const uint32_t aox = (uint32_t)((lane&7)<<4);
    const uint32_t akx = (uint32_t)(lane&16);
    const uint32_t bro = (uint32_t)(((lane&7) + ((lane>>4)<<3))*256);
    const uint32_t bkx = (uint32_t)((lane&8)<<1);
#pragma unroll 1
    for (int kk = 0; kk < 8; kk++){
        uint32_t ka = (uint32_t)(kk*32);
        uint32_t ah[4], al_[4];
        ldsm4(ah,  Ah + aro + ((ka + akx) ^ aox));
        ldsm4(al_, Al + aro + ((ka + akx) ^ aox));
        uint32_t bo = bro + ((ka + bkx) ^ aox);
#pragma unroll
        for (int t2 = 0; t2 < 8; t2++){
            uint32_t bh[4], bl[4];
            ldsm4(bh, Wh + bo + (uint32_t)(t2*4096));
            ldsm4(bl, Wl + bo + (uint32_t)(t2*4096));
            mma16816(d[2*t2],   ah,  bh);
            mma16816(d[2*t2],   ah,  bl);
            mma16816(d[2*t2],   al_, bh);
            mma16816(d[2*t2+1], ah,  bh+2);
            mma16816(d[2*t2+1], ah,  bl+2);
            mma16816(d[2*t2+1], al_, bh+2);
        }
    }
}

// 128x128 x K=32, 80B-stride tiles
__device__ __forceinline__ void gemm32(uint32_t Ah, uint32_t Al, uint32_t Bh, uint32_t Bl,
                                       int warp, int lane, float d[16][4]){
#pragma unroll
    for (int t = 0; t < 16; t++){ d[t][0]=0.f; d[t][1]=0.f; d[t][2]=0.f; d[t][3]=0.f; }
    const uint32_t aro = (uint32_t)((warp*16 + (lane&15))*80 + (lane&16));
    const uint32_t bro = (uint32_t)(((lane&7) + ((lane>>4)<<3))*80 + ((lane&8)<<1));
#pragma unroll
    for (int kk = 0; kk < 2; kk++){
        uint32_t ah[4], al_[4];
        ldsm4(ah,  Ah + aro + (uint32_t)(kk*32));
        ldsm4(al_, Al + aro + (uint32_t)(kk*32));
#pragma unroll
        for (int t2 = 0; t2 < 8; t2++){
            uint32_t bh[4], bl[4];
            ldsm4(bh, Bh + bro + (uint32_t)(kk*32 + t2*1280));
            ldsm4(bl, Bl + bro + (uint32_t)(kk*32 + t2*1280));
            mma16816(d[2*t2],   ah,  bh);
            mma16816(d[2*t2],   ah,  bl);
            mma16816(d[2*t2],   al_, bh);
            mma16816(d[2*t2+1], ah,  bh+2);
            mma16816(d[2*t2+1], ah,  bl+2);
            mma16816(d[2*t2+1], al_, bh+2);
        }
    }
}

// 128x32 x128: B has 32 rows
__device__ __forceinline__ void gemm128_n32(uint32_t Ah, uint32_t Al, uint32_t Bh, uint32_t Bl,
                                            int warp, int lane, float d[4][4]){
#pragma unroll
    for (int t = 0; t < 4; t++){ d[t][0]=0.f; d[t][1]=0.f; d[t][2]=0.f; d[t][3]=0.f; }
    const uint32_t aro = (uint32_t)((warp*16 + (lane&15))*256);
    const uint32_t aox = (uint32_t)((lane&7)<<4);
    const uint32_t akx = (uint32_t)(lane&16);
    const uint32_t bro = (uint32_t)(((lane&7) + ((lane>>4)<<3))*256);
    const uint32_t bkx = (uint32_t)((lane&8)<<1);
#pragma unroll 1
    for (int kk = 0; kk < 8; kk++){
        uint32_t ka = (uint32_t)(kk*32);
        uint32_t ah[4], al_[4];
        ldsm4(ah,  Ah + aro + ((ka + akx) ^ aox));
        ldsm4(al_, Al + aro + ((ka + akx) ^ aox));
        uint32_t bo = bro + ((ka + bkx) ^ aox);
#pragma unroll
        for (int t2 = 0; t2 < 2; t2++){
            uint32_t bh[4], bl[4];
            ldsm4(bh, Bh + bo + (uint32_t)(t2*4096));
            ldsm4(bl, Bl + bo + (uint32_t)(t2*4096));
            mma16816(d[2*t2],   ah,  bh);
            mma16816(d[2*t2],   ah,  bl);
            mma16816(d[2*t2],   al_, bh);
            mma16816(d[2*t2+1], ah,  bh+2);
            mma16816(d[2*t2+1], ah,  bl+2);
            mma16816(d[2*t2+1], al_, bh+2);
        }
    }
}

// ---------------- K0: weight prep ----------------
__global__ void k0_prep(const float* __restrict__ wq, const float* __restrict__ wk,
                        const float* __restrict__ wv, const float* __restrict__ w1,
                        const float* __restrict__ w2, const float* __restrict__ pe2,
                        const float* __restrict__ e2, const float* __restrict__ x1){
    int idx = blockIdx.x * blockDim.x + threadIdx.x;
    int stride = gridDim.x * blockDim.x;
    for (int t = idx; t < 16384; t += stride){
        int c = t >> 7, m = t & 127;
        uint32_t a = swz(c, m*2) >> 1;
        float v1 = w1[t];
        __nv_bfloat16 h1 = __float2bfloat16(v1);
        ((unsigned short*)g_w1hi)[a] = __bfloat16_as_ushort(h1);
        ((unsigned short*)g_w1lo)[a] = __bfloat16_as_ushort(__float2bfloat16(v1 - __bfloat162float(h1)));
        float v2 = w2[t];
        __nv_bfloat16 h2 = __float2bfloat16(v2);
        ((unsigned short*)g_w2hi)[a] = __bfloat16_as_ushort(h2);
        ((unsigned short*)g_w2lo)[a] = __bfloat16_as_ushort(__float2bfloat16(v2 - __bfloat162float(h2)));
    }
    for (int t = idx; t < 4096; t += stride){
        int c = t >> 5, m = t & 31;
        uint32_t a80 = (uint32_t)(c*40 + m);
        float vp = pe2[t];
        __nv_bfloat16 hp = __float2bfloat16(vp);
        ((unsigned short*)g_pe2hi)[a80] = __bfloat16_as_ushort(hp);
        ((unsigned short*)g_pe2lo)[a80] = __bfloat16_as_ushort(__float2bfloat16(vp - __bfloat162float(hp)));
        float ve = e2[t];
        __nv_bfloat16 he = __float2bfloat16(ve);
        ((unsigned short*)g_e2hi)[a80] = __bfloat16_as_ushort(he);
        ((unsigned short*)g_e2lo)[a80] = __bfloat16_as_ushort(__float2bfloat16(ve - __bfloat162float(he)));
        int m2 = t >> 7, c2 = t & 127;
        uint32_t ax = swz(m2, c2*2) >> 1;
        float vx = x1[t];
        __nv_bfloat16 hx = __float2bfloat16(vx);
        ((unsigned short*)g_x1hi)[ax] = __bfloat16_as_ushort(hx);
        ((unsigned short*)g_x1lo)[ax] = __bfloat16_as_ushort(__float2bfloat16(vx - __bfloat162float(hx)));
    }
    for (int t = idx; t < 8192; t += stride){
        int c = t >> 6, d = t & 63;
        g_wqT[d*128 + c] = wq[t];
        g_wkT[d*128 + c] = wk[t];
        g_wvT[d*128 + c] = wv[t];
    }
}

// ---------------- K1: q,k,v projections ----------------
__global__ void __launch_bounds__(128) k1_qkv(const float* __restrict__ x,
                                              const float* __restrict__ bq,
                                              const float* __restrict__ bk,
                                              const float* __restrict__ bv){
    __shared__ float sx[64];
    int row = blockIdx.x;
    int c = threadIdx.x;
    if (c < 64) sx[c] = x[(size_t)row*64 + c];
    __syncthreads();
    float aq = bq[c], ak = bk[c], av = bv[c];
#pragma unroll 8
    for (int d = 0; d < 64; d++){
        float xv = sx[d];
        aq = fmaf(xv, g_wqT[d*128 + c], aq);
        ak = fmaf(xv, g_wkT[d*128 + c], ak);
        av = fmaf(xv, g_wvT[d*128 + c], av);
    }
    g_q[(size_t)row*128 + c] = aq;
    g_k[(size_t)row*128 + c] = ak;
    g_v[(size_t)row*128 + c] = av;
}

// ---------------- K2: fused attention per (n,i) ----------------
__global__ void __launch_bounds__(256) k2_attn(
    const float* __restrict__ U, const float* __restrict__ p,
    const float* __restrict__ ln1_g, const float* __restrict__ ln1_b,
    const float* __restrict__ b1,
    const float* __restrict__ ln2_g, const float* __restrict__ ln2_b,
    const float* __restrict__ b2,
    const float* __restrict__ pe1, const float* __restrict__ e1,
    float* __restrict__ xout)
{
    extern __shared__ char sm8[];
    float* sxvT = (float*)(sm8 + XVT_B);     // [c][j] stride 130
    float* sk   = (float*)(sm8 + SK_B);
    float* sg1  = (float*)(sm8 + SG1_B);
    float* sb1v = (float*)(sm8 + SB1_B);
    float* sg2  = (float*)(sm8 + SG2_B);
    float* sb2v = (float*)(sm8 + SB2_B);
    float* sbi1 = (float*)(sm8 + SBI1_B);
    float* sbi2 = (float*)(sm8 + SBI2_B);
    float* spe1 = (float*)(sm8 + SPE1_B);
    float* spij = (float*)(sm8 + SPIJ_B);
    float* sxo  = (float*)(sm8 + SXO_B);

    const uint32_t sbase = smem_u32(sm8);
    const uint32_t Ah = sbase + A_HI_B, Al = sbase + A_LO_B;
    const uint32_t Wh = sbase + W_HI_B, Wl = sbase + W_LO_B;
    const int tid = threadIdx.x;
    const int lane = tid & 31, warp = tid >> 5;
    const int n = blockIdx.x >> 7, i = blockIdx.x & 127;
    const int g4 = lane & 3;
    const int rowA = warp*16 + (lane>>2), rowB = rowA + 8;

    // ----- stage 0: smalls + pe2 tiles + W1 copy -----
    if (tid < 128){
        size_t rowk = (size_t)(n*128 + i);
        sk[tid]   = g_k[rowk*128 + tid];
        sg1[tid]  = ln1_g[tid];  sb1v[tid] = ln1_b[tid];
        sg2[tid]  = ln2_g[tid];  sb2v[tid] = ln2_b[tid];
        sbi1[tid] = b1[tid];     sbi2[tid] = b2[tid];
        spe1[tid] = pe1[tid];
        int j = tid;
        float4 pi = *(const float4*)(p + (size_t)(n*128 + i)*4);
        float4 pj = *(const float4*)(p + (size_t)(n*128 + j)*4);
        spij[j*4+0] = pi.x - pj.x;
        spij[j*4+1] = pi.y - pj.y;
        spij[j*4+2] = pi.z - pj.z;
        spij[j*4+3] = pi.w - pj.w;
    }
    for (int t = tid; t < 2560; t += 256){
        ((uint32_t*)(sm8 + PE2H_B))[t] = g_pe2hi[t];
        ((uint32_t*)(sm8 + PE2L_B))[t] = g_pe2lo[t];
    }
    {
        const uint4* whi = (const uint4*)g_w1hi;
        const uint4* wlo = (const uint4*)g_w1lo;
        uint4* dhi = (uint4*)(sm8 + W_HI_B);
        uint4* dlo = (uint4*)(sm8 + W_LO_B);
#pragma unroll
        for (int t = 0; t < 8; t++){
            dhi[tid + 256*t] = whi[tid + 256*t];
            dlo[tid + 256*t] = wlo[tid + 256*t];
        }
    }
    const bool pad_i = (p[(size_t)(n*128 + i)*4] == 0.0f);
    __syncthreads();

    // ----- tn (per-warp rows warp*16..+15): relu(LN32(pij @ pe1^T)) -----
    {
        float4 pe1r = ((const float4*)spe1)[lane];
#pragma unroll 1
        for (int r = 0; r < 16; r++){
            int jj = warp*16 + r;
            float4 pd = *(const float4*)(spij + jj*4);
            float t = pd.x*pe1r.x + pd.y*pe1r.y + pd.z*pe1r.z + pd.w*pe1r.w;
            float mu = wsum(t) * (1.0f/32.0f);
            float dd = t - mu;
            float var = wsum(dd*dd) * (1.0f/32.0f);
            float tn = fmaxf(dd * rsqrtf(var + 1e-5f), 0.0f);
            float tn1 = __shfl_down_sync(0xffffffffu, tn, 1);
            if (!(lane & 1)){
                uint32_t hi, lo;
                split2(tn, tn1, hi, lo);
                *(uint32_t*)(sm8 + TNH_B + jj*80 + lane*2) = hi;
                *(uint32_t*)(sm8 + TNL_B + jj*80 + lane*2) = lo;
            }
        }
    }
    __syncwarp();

    // ----- GEMM0: eqpe_pre rows (own) -----
    float d[16][4];
    gemm32(sbase + TNH_B, sbase + TNL_B, sbase + PE2H_B, sbase + PE2L_B, warp, lane, d);
    __syncthreads();   // pe2/tn region becomes xvT

    // ----- epilogue0: LN(eqpe) relu -> e; xvT = v+U+e; r = k-q+U+e; LN1 -> A1 (own rows) -----
    {
        float s1A = 0, s2A = 0, s1B = 0, s2B = 0;
#pragma unroll
        for (int t = 0; t < 16; t++){
            s1A += d[t][0] + d[t][1]; s2A += d[t][0]*d[t][0] + d[t][1]*d[t][1];
            s1B += d[t][2] + d[t][3]; s2B += d[t][2]*d[t][2] + d[t][3]*d[t][3];
        }
        s1A = qsum(s1A); s2A = qsum(s2A); s1B = qsum(s1B); s2B = qsum(s2B);
        float muA = s1A*(1.0f/128.0f), rsA = rsqrtf(s2A*(1.0f/128.0f) - muA*muA + 1e-5f);
        float muB = s1B*(1.0f/128.0f), rsB = rsqrtf(s2B*(1.0f/128.0f) - muB*muB + 1e-5f);

        const float* Ub = U + (size_t)blockIdx.x * 16384;
        const float* qb = g_q + (size_t)n*16384;
        const float* vb = g_v + (size_t)n*16384;
        float t1A = 0, t2A = 0, t1B = 0, t2B = 0;
#pragma unroll
        for (int t = 0; t < 16; t++){
            int c0 = t*8 + g4*2;
            float2 uA = *(const float2*)(Ub + rowA*128 + c0);
            float2 uB = *(const float2*)(Ub + rowB*128 + c0);
            float2 qA = *(const float2*)(qb + rowA*128 + c0);
            float2 qB = *(const float2*)(qb + rowB*128 + c0);
            float2 vA = *(const float2*)(vb + rowA*128 + c0);
            float2 vB = *(const float2*)(vb + rowB*128 + c0);
            float2 kc = *(const float2*)(sk + c0);
            float eA0 = fmaxf((d[t][0]-muA)*rsA, 0.0f) + uA.x;
            float eA1 = fmaxf((d[t][1]-muA)*rsA, 0.0f) + uA.y;
            float eB0 = fmaxf((d[t][2]-muB)*rsB, 0.0f) + uB.x;
            float eB1 = fmaxf((d[t][3]-muB)*rsB, 0.0f) + uB.y;
            sxvT[(c0  )*130 + rowA] = vA.x + eA0;
            sxvT[(c0+1)*130 + rowA] = vA.y + eA1;
            sxvT[(c0  )*130 + rowB] = vB.x + eB0;
            sxvT[(c0+1)*130 + rowB] = vB.y + eB1;
            float rA0 = kc.x - qA.x + eA0;
            float rA1 = kc.y - qA.y + eA1;
            float rB0 = kc.x - qB.x + eB0;
            float rB1 = kc.y - qB.y + eB1;
            d[t][0] = rA0; d[t][1] = rA1; d[t][2] = rB0; d[t][3] = rB1;
            t1A += rA0 + rA1; t2A += rA0*rA0 + rA1*rA1;
            t1B += rB0 + rB1; t2B += rB0*rB0 + rB1*rB1;
        }
        t1A = qsum(t1A); t2A = qsum(t2A); t1B = qsum(t1B); t2B = qsum(t2B);
        float nuA = t1A*(1.0f/128.0f), nsA = rsqrtf(t2A*(1.0f/128.0f) - nuA*nuA + 1e-5f);
        float nuB = t1B*(1.0f/128.0f), nsB = rsqrtf(t2B*(1.0f/128.0f) - nuB*nuB + 1e-5f);
#pragma unroll
        for (int t = 0; t < 16; t++){
            int c0 = t*8 + g4*2;
            float2 gg = *(float2*)(sg1 + c0);
            float2 bb = *(float2*)(sb1v + c0);
            float yA0 = fmaxf(fmaf((d[t][0]-nuA)*nsA, gg.x, bb.x), 0.0f);
            float yA1 = fmaxf(fmaf((d[t][1]-nuA)*nsA, gg.y, bb.y), 0.0f);
            float yB0 = fmaxf(fmaf((d[t][2]-nuB)*nsB, gg.x, bb.x), 0.0f);
            float yB1 = fmaxf(fmaf((d[t][3]-nuB)*nsB, gg.y, bb.y), 0.0f);
            uint32_t hA, lA, hB, lB;
            split2(yA0, yA1, hA, lA);
            split2(yB0, yB1, hB, lB);
            int kb = t*16 + g4*4;
            *(uint32_t*)(sm8 + A_HI_B + swz(rowA, kb)) = hA;
            *(uint32_t*)(sm8 + A_LO_B + swz(rowA, kb)) = lA;
            *(uint32_t*)(sm8 + A_HI_B + swz(rowB, kb)) = hB;
            *(uint32_t*)(sm8 + A_LO_B + swz(rowB, kb)) = lB;
        }
    }
    __syncwarp();

    // ----- GEMM1 (W1 ready since stage0; A1 own rows) -----
    gemm128(Ah, Al, Wh, Wl, warp, lane, d);

    // ----- epilogue1: +b1, LN(g2,b2), relu -> A2 (own rows) -----
    {
        float s1A = 0, s2A = 0, s1B = 0, s2B = 0;
#pragma unroll
        for (int t = 0; t < 16; t++){
            int c0 = t*8 + g4*2;
            float2 bb = *(float2*)(sbi1 + c0);
            d[t][0] += bb.x; d[t][1] += bb.y;
            d[t][2] += bb.x; d[t][3] += bb.y;
            s1A += d[t][0] + d[t][1]; s2A += d[t][0]*d[t][0] + d[t][1]*d[t][1];
            s1B += d[t][2] + d[t][3]; s2B += d[t][2]*d[t][2] + d[t][3]*d[t][3];
        }
        s1A = qsum(s1A); s2A = qsum(s2A); s1B = qsum(s1B); s2B = qsum(s2B);
        float muA = s1A*(1.0f/128.0f), rsA = rsqrtf(s2A*(1.0f/128.0f) - muA*muA + 1e-5f);
        float muB = s1B*(1.0f/128.0f), rsB = rsqrtf(s2B*(1.0f/128.0f) - muB*muB + 1e-5f);
#pragma unroll
        for (int t = 0; t < 16; t++){
            int c0 = t*8 + g4*2;
            float2 gg = *(float2*)(sg2 + c0);
            float2 bb = *(float2*)(sb2v + c0);
            float yA0 = fmaxf(fmaf((d[t][0]-muA)*rsA, gg.x, bb.x), 0.0f);
            float yA1 = fmaxf(fmaf((d[t][1]-muA)*rsA, gg.y, bb.y), 0.0f);
            float yB0 = fmaxf(fmaf((d[t][2]-muB)*rsB, gg.x, bb.x), 0.0f);
            float yB1 = fmaxf(fmaf((d[t][3]-muB)*rsB, gg.y, bb.y), 0.0f);
            uint32_t hA, lA, hB, lB;
            split2(yA0, yA1, hA, lA);
            split2(yB0, yB1, hB, lB);
            int kb = t*16 + g4*4;
            *(uint32_t*)(sm8 + A_HI_B + swz(rowA, kb)) = hA;
            *(uint32_t*)(sm8 + A_LO_B + swz(rowA, kb)) = lA;
            *(uint32_t*)(sm8 + A_HI_B + swz(rowB, kb)) = hB;
            *(uint32_t*)(sm8 + A_LO_B + swz(rowB, kb)) = lB;
        }
    }
    __syncthreads();   // all warps done reading W1 + A2 stores visible

    // ----- W2 copy -----
    {
        const uint4* whi = (const uint4*)g_w2hi;
        const uint4* wlo = (const uint4*)g_w2lo;
        uint4* dhi = (uint4*)(sm8 + W_HI_B);
        uint4* dlo = (uint4*)(sm8 + W_LO_B);
#pragma unroll
        for (int t = 0; t < 8; t++){
            dhi[tid + 256*t] = whi[tid + 256*t];
            dlo[tid + 256*t] = wlo[tid + 256*t];
        }
    }
    __syncthreads();

    // ----- GEMM2 transposed: D[c][j] = W2 @ A2^T -----
    gemm128(Wh, Wl, Ah, Al, warp, lane, d);

    // ----- softmax over j in registers + weighted sum of xvT -----
    {
        float bA = sbi2[rowA], bB = sbi2[rowB];
        float mA = -3.4e38f, mB = -3.4e38f;
#pragma unroll
        for (int t = 0; t < 16; t++){
            d[t][0] += bA; d[t][1] += bA;
            d[t][2] += bB; d[t][3] += bB;
            if (pad_i){ d[t][0] = NEGV; d[t][1] = NEGV; d[t][2] = NEGV; d[t][3] = NEGV; }
            mA = fmaxf(mA, fmaxf(d[t][0], d[t][1]));
            mB = fmaxf(mB, fmaxf(d[t][2], d[t][3]));
        }
        mA = qmax(mA); mB = qmax(mB);
        float denA = 0, numA = 0, denB = 0, numB = 0;
#pragma unroll
        for (int t = 0; t < 16; t++){
            int jj = t*8 + g4*2;
            float w0 = __expf(d[t][0] - mA), w1 = __expf(d[t][1] - mA);
            float w2 = __expf(d[t][2] - mB), w3 = __expf(d[t][3] - mB);
            float2 xA = *(float2*)(sxvT + rowA*130 + jj);
            float2 xB = *(float2*)(sxvT + rowB*130 + jj);
            denA += w0 + w1; numA += w0*xA.x + w1*xA.y;
            denB += w2 + w3; numB += w2*xB.x + w3*xB.y;
        }
        denA = qsum(denA); numA = qsum(numA);
        denB = qsum(denB); numB = qsum(numB);
        if (g4 == 0){
            float oA = numA/denA, oB = numB/denB;
            sxo[rowA] = oA; sxo[rowB] = oB;
            xout[(size_t)blockIdx.x*128 + rowA] = oA;
            xout[(size_t)blockIdx.x*128 + rowB] = oB;
        }
    }
    __syncthreads();

    // ----- tail: avec/bvec = e1 projections of x_out -----
    if (tid < 64){
        int m = tid & 31, half = tid >> 5;
        const float* er = e1 + m*257 + half*128;
        float a = 0;
#pragma unroll 8
        for (int c2 = 0; c2 < 128; c2++) a = fmaf(sxo[c2], er[c2], a);
        if (half == 0) g_avec[(size_t)blockIdx.x*32 + m] = a;
        else           g_bvec[(size_t)blockIdx.x*32 + m] = a;
    }
}

// ---------------- K3: message MLP + position update, 2 CTAs/SM ----------------
__global__ void __launch_bounds__(256, 2) k3_msg(
    const float* __restrict__ p, const float* __restrict__ e1,
    const float* __restrict__ x1b, const float* __restrict__ x2,
    const float* __restrict__ x2b,
    float* __restrict__ outp)
{
    extern __shared__ char sm8[];
    float* spij  = (float*)(sm8 + K3_SPIJ);
    float* snorm = (float*)(sm8 + K3_SNORM);
    float* ss    = (float*)(sm8 + K3_SS);
    float* spad  = (float*)(sm8 + K3_SPAD);
    float* sa    = (float*)(sm8 + K3_SA);
    float* se1c  = (float*)(sm8 + K3_SE1C);
    float* sx1b_ = (float*)(sm8 + K3_SX1B);
    float* sx2v  = (float*)(sm8 + K3_SX2V);

    const uint32_t sbase = smem_u32(sm8);
    const int tid = threadIdx.x, lane = tid & 31, warp = tid >> 5;
    const int n = blockIdx.x >> 7, i = blockIdx.x & 127;
    const bool pad_i = (p[(size_t)(n*128 + i)*4] == 0.0f);
    const int g4 = lane & 3;
    const int rowA = warp*16 + (lane>>2), rowB = rowA + 8;

    if (tid < 128){
        int j = tid;
        float4 pi = *(const float4*)(p + (size_t)(n*128 + i)*4);
        float4 pj = *(const float4*)(p + (size_t)(n*128 + j)*4);
        float dx = pi.x - pj.x, dy = pi.y - pj.y, dz = pi.z - pj.z, dw = pi.w - pj.w;
        spij[j*4+0] = dx; spij[j*4+1] = dy; spij[j*4+2] = dz; spij[j*4+3] = dw;
        spad[j] = (pj.x != 0.0f) ? 1.0f : 0.0f;
        snorm[j] = pad_i ? 0.0f : (dw*dw - dx*dx - dy*dy - dz*dz);
    }
    if (tid < 32){
        sa[tid]    = g_avec[(size_t)(n*128 + i)*32 + tid];
        se1c[tid]  = e1[tid*257 + 256];
        sx1b_[tid] = x1b[tid];
        sx2v[tid]  = x2[tid];
    }
    for (int t = tid; t < 2560; t += 256){
        ((uint32_t*)(sm8 + K3_B1H))[t] = g_e2hi[t];
        ((uint32_t*)(sm8 + K3_B1L))[t] = g_e2lo[t];
    }
    for (int t = tid; t < 2048; t += 256){
        ((uint32_t*)(sm8 + K3_B2H))[t] = g_x1hi[t];
        ((uint32_t*)(sm8 + K3_B2L))[t] = g_x1lo[t];
    }
    __syncthreads();

    // h32 tile
    const float* bv = g_bvec + (size_t)n*4096;
    for (int idx = tid; idx < 2048; idx += 256){
        int row = idx >> 4, mp = idx & 15, m = mp*2;
        float nb = snorm[row];
        float2 bb = *(const float2*)(bv + row*32 + m);
        float h0 = fmaxf(sa[m]   + bb.x + nb*se1c[m],   0.0f);
        float h1 = fmaxf(sa[m+1] + bb.y + nb*se1c[m+1], 0.0f);
        uint32_t hi, lo;
        split2(h0, h1, hi, lo);
        *(uint32_t*)(sm8 + K3_A1H + row*80 + mp*4) = hi;
        *(uint32_t*)(sm8 + K3_A1L + row*80 + mp*4) = lo;
    }
    __syncthreads();

    // MMA1: mij_pre = h32 @ e2^T
    float d[16][4];
    gemm32(sbase + K3_A1H, sbase + K3_A1L, sbase + K3_B1H, sbase + K3_B1L, warp, lane, d);

    // relu -> mask -> LN (register phase)
    {
        float s1A = 0, s2A = 0, s1B = 0, s2B = 0;
#pragma unroll
        for (int t = 0; t < 16; t++){
            float a0 = fmaxf(d[t][0], 0.0f), a1 = fmaxf(d[t][1], 0.0f);
            float b0 = fmaxf(d[t][2], 0.0f), b1 = fmaxf(d[t][3], 0.0f);
            if (pad_i){ a0 = NEGV; a1 = NEGV; b0 = NEGV; b1 = NEGV; }
            d[t][0] = a0; d[t][1] = a1; d[t][2] = b0; d[t][3] = b1;
            s1A += a0 + a1; s2A += a0*a0 + a1*a1;
            s1B += b0 + b1; s2B += b0*b0 + b1*b1;
        }
        s1A = qsum(s1A); s2A = qsum(s2A); s1B = qsum(s1B); s2B = qsum(s2B);
        float muA = s1A*(1.0f/128.0f), vA = s2A*(1.0f/128.0f) - muA*muA;
        float muB = s1B*(1.0f/128.0f), vB = s2B*(1.0f/128.0f) - muB*muB;
        float rsA = rsqrtf(fmaxf(vA, 0.0f) + 1e-5f);
        float rsB = rsqrtf(fmaxf(vB, 0.0f) + 1e-5f);
#pragma unroll
        for (int t = 0; t < 16; t++){
            d[t][0] = (d[t][0]-muA)*rsA; d[t][1] = (d[t][1]-muA)*rsA;
            d[t][2] = (d[t][2]-muB)*rsB; d[t][3] = (d[t][3]-muB)*rsB;
        }
    }
    __syncthreads();   // all warps done reading A1/B1 before A2 overwrite

    {
#pragma unroll
        for (int t = 0; t < 16; t++){
            uint32_t hA, lA, hB, lB;
            split2(d[t][0], d[t][1], hA, lA);
            split2(d[t][2], d[t][3], hB, lB);
            int kb = t*16 + g4*4;
            *(uint32_t*)(sm8 + K3_A2H + swz(rowA, kb)) = hA;
            *(uint32_t*)(sm8 + K3_A2L + swz(rowA, kb)) = lA;
            *(uint32_t*)(sm8 + K3_A2H + swz(rowB, kb)) = hB;
            *(uint32_t*)(sm8 + K3_A2L + swz(rowB, kb)) = lB;
        }
    }
    __syncthreads();

    // MMA2: t_pre = y @ x1^T (N=32)
    float d2[4][4];
    gemm128_n32(sbase + K3_A2H, sbase + K3_A2L, sbase + K3_B2H, sbase + K3_B2L, warp, lane, d2);

    // scores
    {
        float x2bv = x2b[0];
        float sA = 0, sB = 0;
#pragma unroll
        for (int t = 0; t < 4; t++){
            int c0 = t*8 + g4*2;
            float2 xb = *(float2*)(sx1b_ + c0);
            float2 xv = *(float2*)(sx2v + c0);
            sA += fmaxf(d2[t][0] + xb.x, 0.0f)*xv.x + fmaxf(d2[t][1] + xb.y, 0.0f)*xv.y;
            sB += fmaxf(d2[t][2] + xb.x, 0.0f)*xv.x + fmaxf(d2[t][3] + xb.y, 0.0f)*xv.y;
        }
        sA = qsum(sA); sB = qsum(sB);
        if (g4 == 0){
            ss[rowA] = fmaxf(sA + x2bv, 0.0f);
            ss[rowB] = fmaxf(sB + x2bv, 0.0f);
        }
    }
    __syncthreads();

    if (warp == 0){
        float m0 = fmaxf(fmaxf(ss[lane], ss[lane+32]), fmaxf(ss[lane+64], ss[lane+96]));
#pragma unroll
        for (int k = 16; k > 0; k >>= 1) m0 = fmaxf(m0, __shfl_xor_sync(0xffffffffu, m0, k));
        float den = 0, dx = 0, dy = 0, dz = 0, dw = 0, cnt = 0;
#pragma unroll
        for (int q2 = 0; q2 < 4; q2++){
            int b = lane + 32*q2;
            float w = __expf(ss[b] - m0);
            den += w;
            dx = fmaf(w, spij[b*4+0], dx);
            dy = fmaf(w, spij[b*4+1], dy);
            dz = fmaf(w, spij[b*4+2], dz);
            dw = fmaf(w, spij[b*4+3], dw);
            cnt += spad[b];
        }
        den = wsum(den); dx = wsum(dx); dy = wsum(dy);
        dz = wsum(dz);   dw = wsum(dw); cnt = wsum(cnt);
        if (lane == 0){
            float inv = 1.0f / (den * cnt);
            const float* pr = p + (size_t)(n*128 + i)*4;
            float* o = outp + (size_t)(n*128 + i)*4;
            float d4[4] = {dx, dy, dz, dw};
#pragma unroll
            for (int dd = 0; dd < 4; dd++){
                float pv = pr[dd];
                o[dd] = (pv == 0.0f) ? 0.0f : pv + d4[dd]*inv;
            }
        }
    }
}

extern "C" void kernel_launch(void* const* d_in, const int* in_sizes, int n_in,
                              void* d_out, int out_size){
    const float* x     = (const float*)d_in[0];
    const float* p     = (const float*)d_in[1];
    const float* U     = (const float*)d_in[2];
    const float* wq    = (const float*)d_in[3];
    const float* bq    = (const float*)d_in[4];
    const float* wk    = (const float*)d_in[5];
    const float* bk    = (const float*)d_in[6];
    const float* wv    = (const float*)d_in[7];
    const float* bv    = (const float*)d_in[8];
    const float* ln1_g = (const float*)d_in[9];
    const float* ln1_b = (const float*)d_in[10];
    const float* w1    = (const float*)d_in[11];
    const float* b1    = (const float*)d_in[12];
    const float* ln2_g = (const float*)d_in[13];
    const float* ln2_b = (const float*)d_in[14];
    const float* w2    = (const float*)d_in[15];
    const float* b2    = (const float*)d_in[16];
    const float* pe1   = (const float*)d_in[17];
    const float* pe2   = (const float*)d_in[18];
    const float* e1    = (const float*)d_in[19];
    const float* e2    = (const float*)d_in[20];
    const float* x1    = (const float*)d_in[21];
    const float* x1b   = (const float*)d_in[22];
    const float* x2    = (const float*)d_in[23];
    const float* x2b   = (const float*)d_in[24];
    float* out  = (float*)d_out;
    float* xout = out;                 // (16,128,128)
    float* newp = out + 16*128*128;    // (16,128,4)

    cudaFuncSetAttribute(k2_attn, cudaFuncAttributeMaxDynamicSharedMemorySize, K2_SMEM);
    cudaFuncSetAttribute(k3_msg,  cudaFuncAttributeMaxDynamicSharedMemorySize, K3_SMEM);

    k0_prep<<<64, 256>>>(wq, wk, wv, w1, w2, pe2, e2, x1);
    k1_qkv<<<2048, 128>>>(x, bq, bk, bv);
    k2_attn<<<2048, 256, K2_SMEM>>>(U, p, ln1_g, ln1_b, b1, ln2_g, ln2_b, b2, pe1, e1, xout);
    k3_msg<<<2048, 256, K3_SMEM>>>(p, e1, x1b, x2, x2b, newp);
}

// round 7
// speedup vs baseline: 2.4734x; 1.0512x over previous
#include <cuda_runtime.h>
#include <cuda_bf16.h>
#include <math.h>
#include <stdint.h>

#define NEGV (-10000.0f)

// ---------------- K2 smem byte offsets (512-thread version) ----------------
#define XVT_B    0          // fp32 xvT [128][130] (66560B); pe2/tn tiles alias front
#define PE2H_B   0
#define PE2L_B   10240
#define TNH_B    20480
#define TNL_B    30720
#define A_HI_B   67584      // bf16 A tile (XOR swizzle, 32KB each)
#define A_LO_B   100352
#define W_HI_B   133120     // bf16 W tile: w1 -> w2
#define W_LO_B   165888
#define SK_B     198656
#define SG1_B    199168
#define SB1_B    199680
#define SG2_B    200192
#define SB2_B    200704
#define SBI1_B   201216
#define SBI2_B   201728
#define SPE1_B   202240
#define SPIJ_B   202752     // 2048
#define SXO_B    204800     // 512
#define SP_B     205312     // 2048: [ch][row] float2 partials
#define SP2_B    207360     // 2048
#define SMAX_B   209408     // 1024: [ch][c] float
#define SDN_B    210432     // 2048: [ch][c] float2
#define K2_SMEM  212480

// ---------------- K3 smem byte offsets ----------------
#define K3_A1H   0          // h32 tile (80B-stride, 10240 each)
#define K3_A1L   10240
#define K3_B1H   20480      // e2 tile (80B)
#define K3_B1L   30720
#define K3_B2H   40960      // x1 tile (XOR, 32 rows, 8KB each)
#define K3_B2L   49152
#define K3_SPIJ  57344      // 2048
#define K3_SNORM 59392      // 512
#define K3_SS    59904      // 512
#define K3_SPAD  60416      // 512
#define K3_SA    60928      // 128
#define K3_SE1C  61056      // 128
#define K3_SX1B  61184      // 128
#define K3_SX2V  61312      // 128
#define K3_SMEM  61440

// ---------------- device scratch ----------------
__device__ float g_q[16*128*128];
__device__ float g_k[16*128*128];
__device__ float g_v[16*128*128];
__device__ float g_wqT[64*128];
__device__ float g_wkT[64*128];
__device__ float g_wvT[64*128];
__device__ float g_avec[16*128*32];
__device__ float g_bvec[16*128*32];
__device__ uint32_t g_w1hi[8192];
__device__ uint32_t g_w1lo[8192];
__device__ uint32_t g_w2hi[8192];
__device__ uint32_t g_w2lo[8192];
__device__ uint32_t g_x1hi[2048];
__device__ uint32_t g_x1lo[2048];
__device__ uint32_t g_pe2hi[2560];
__device__ uint32_t g_pe2lo[2560];
__device__ uint32_t g_e2hi[2560];
__device__ uint32_t g_e2lo[2560];

// ---------------- helpers ----------------
__device__ __forceinline__ float wsum(float v){
#pragma unroll
    for (int k = 16; k > 0; k >>= 1) v += __shfl_xor_sync(0xffffffffu, v, k);
    return v;
}
__device__ __forceinline__ float qsum(float v){
    v += __shfl_xor_sync(0xffffffffu, v, 1);
    v += __shfl_xor_sync(0xffffffffu, v, 2);
    return v;
}
__device__ __forceinline__ float qmax(float v){
    v = fmaxf(v, __shfl_xor_sync(0xffffffffu, v, 1));
    v = fmaxf(v, __shfl_xor_sync(0xffffffffu, v, 2));
    return v;
}
__device__ __forceinline__ uint32_t smem_u32(const void* p){
    uint32_t a;
    asm("{ .reg .u64 t; cvta.to.shared.u64 t, %1; cvt.u32.u64 %0, t; }" : "=r"(a) : "l"(p));
    return a;
}
__device__ __forceinline__ uint32_t swz(int row, int kb){
    return (uint32_t)(row*256 + ((kb & 0xF0) ^ ((row & 7) << 4)) + (kb & 15));
}
__device__ __forceinline__ void split2(float x, float y, uint32_t &hi, uint32_t &lo){
    __nv_bfloat16 hx = __float2bfloat16(x), hy = __float2bfloat16(y);
    __nv_bfloat16 lx = __float2bfloat16(x - __bfloat162float(hx));
    __nv_bfloat16 ly = __float2bfloat16(y - __bfloat162float(hy));
    hi = (uint32_t)__bfloat16_as_ushort(hx) | ((uint32_t)__bfloat16_as_ushort(hy) << 16);
    lo = (uint32_t)__bfloat16_as_ushort(lx) | ((uint32_t)__bfloat16_as_ushort(ly) << 16);
}
__device__ __forceinline__ void ldsm4(uint32_t a[4], uint32_t addr){
    asm volatile("ldmatrix.sync.aligned.m8n8.x4.shared.b16 {%0,%1,%2,%3}, [%4];"
        : "=r"(a[0]), "=r"(a[1]), "=r"(a[2]), "=r"(a[3]) : "r"(addr));
}
__device__ __forceinline__ void mma16816(float d[4], const uint32_t a[4], const uint32_t b[2]){
    asm volatile("mma.sync.aligned.m16n8k16.row.col.f32.bf16.bf16.f32 "
        "{%0,%1,%2,%3}, {%4,%5,%6,%7}, {%8,%9}, {%0,%1,%2,%3};"
        : "+f"(d[0]), "+f"(d[1]), "+f"(d[2]), "+f"(d[3])
        : "r"(a[0]), "r"(a[1]), "r"(a[2]), "r"(a[3]), "r"(b[0]), "r"(b[1]));
}

// K2 quadrant GEMM: A rows r*16..+15, B rows cb..cb+63, K=128, XOR tiles.
__device__ __forceinline__ void gemm128q(uint32_t Ah, uint32_t Al, uint32_t Bh, uint32_t Bl,
                                         int r, int cb, int lane, float d[8][4]){
#pragma unroll
    for (int t = 0; t < 8; t++){ d[t][0]=0.f; d[t][1]=0.f; d[t][2]=0.f; d[t][3]=0.f; }
    const uint32_t aro = (uint32_t)((r*16 + (lane&15))*256);
    const uint32_t aox = (uint32_t)((lane&7)<<4);
    const uint32_t akx = (uint32_t)(lane&16);
    const uint32_t bro = (uint32_t)((cb + (lane&7) + ((lane>>4)<<3))*256);
    const uint32_t bkx = (uint32_t)((lane&8)<<1);
#pragma unroll 1
    for (int kk = 0; kk < 8; kk++){
        uint32_t ka = (uint32_t)(kk*32);
        uint32_t ah[4], al_[4];
        ldsm4(ah,  Ah + aro + ((ka + akx) ^ aox));
        ldsm4(al_, Al + aro + ((ka + akx) ^ aox));
        uint32_t bo = bro + ((ka + bkx) ^ aox);
#pragma unroll
        for (int t2 = 0; t2 < 4; t2++){
            uint32_t bh[4], bl[4];
            ldsm4(bh, Bh + bo + (uint32_t)(t2*4096));
            ldsm4(bl, Bl + bo + (uint32_t)(t2*4096));
            mma16816(d[2*t2],   ah,  bh);
            mma16816(d[2*t2],   ah,  bl);
            mma16816(d[2*t2],   al_, bh);
            mma16816(d[2*t2+1], ah,  bh+2);
            mma16816(d[2*t2+1], ah,  bl+2);
            mma16816(d[2*t2+1], al_, bh+2);
        }
    }
}

// K2 quadrant small-K GEMM: K=32, 80B-stride tiles.
__device__ __forceinline__ void gemm32q(uint32_t Ah, uint32_t Al, uint32_t Bh, uint32_t Bl,
                                        int r, int cb, int lane, float d[8][4]){
#pragma unroll
    for (int t = 0; t < 8; t++){ d[t][0]=0.f; d[t][1]=0.f; d[t][2]=0.f; d[t][3]=0.f; }
    const uint32_t aro = (uint32_t)((r*16 + (lane&15))*80 + (lane&16));
    const uint32_t bro = (uint32_t)((cb + (lane&7) + ((lane>>4)<<3))*80 + ((lane&8)<<1));
#pragma unroll
    for (int kk = 0; kk < 2; kk++){
        uint32_t ah[4], al_[4];
        ldsm4(ah,  Ah + aro + (uint32_t)(kk*32));
        ldsm4(al_, Al + aro + (uint32_t)(kk*32));
#pragma unroll
        for (int t2 = 0; t2 < 4; t2++){
            uint32_t bh[4], bl[4];
            ldsm4(bh, Bh + bro + (uint32_t)(kk*32 + t2*1280));
            ldsm4(bl, Bl + bro + (uint32_t)(kk*32 + t2*1280));
            mma16816(d[2*t2],   ah,  bh);
            mma16816(d[2*t2],   ah,  bl);
            mma16816(d[2*t2],   al_, bh);
            mma16816(d[2*t2+1], ah,  bh+2);
            mma16816(d[2*t2+1], ah,  bl+2);
            mma16816(d[2*t2+1], al_, bh+2);
        }
    }
}

// K3 full-width K=32 GEMM (8 warps, 16 rows each, all 128 cols)
__device__ __forceinline__ void gemm32(uint32_t Ah, uint32_t Al, uint32_t Bh, uint32_t Bl,
                                       int warp, int lane, float d[16][4]){
#pragma unroll
    for (int t = 0; t < 16; t++){ d[t][0]=0.f; d[t][1]=0.f; d[t][2]=0.f; d[t][3]=0.f; }
    const uint32_t aro = (uint32_t)((warp*16 + (lane&15))*80 + (lane&16));
    const uint32_t bro = (uint32_t)(((lane&7) + ((lane>>4)<<3))*80 + ((lane&8)<<1));
#pragma unroll
    for (int kk = 0; kk < 2; kk++){
        uint32_t ah[4], al_[4];
        ldsm4(ah,  Ah + aro + (uint32_t)(kk*32));
        ldsm4(al_, Al + aro + (uint32_t)(kk*32));
#pragma unroll
        for (int t2 = 0; t2 < 8; t2++){
            uint32_t bh[4], bl[4];
            ldsm4(bh, Bh + bro + (uint32_t)(kk*32 + t2*1280));
            ldsm4(bl, Bl + bro + (uint32_t)(kk*32 + t2*1280));
            mma16816(d[2*t2],   ah,  bh);
            mma16816(d[2*t2],   ah,  bl);
            mma16816(d[2*t2],   al_, bh);
            mma16816(d[2*t2+1], ah,  bh+2);
            mma16816(d[2*t2+1], ah,  bl+2);
            mma16816(d[2*t2+1], al_, bh+2);
        }
    }
}

// K3 MMA2 with A from registers (y in C-fragment layout), B = x1 tile (32 rows, XOR)
__device__ __forceinline__ void mma2_regA(const float y[16][4], uint32_t Bh, uint32_t Bl,
                                          int lane, float d2[4][4]){
#pragma unroll
    for (int t = 0; t < 4; t++){ d2[t][0]=0.f; d2[t][1]=0.f; d2[t][2]=0.f; d2[t][3]=0.f; }
    const uint32_t aox = (uint32_t)((lane&7)<<4);
    const uint32_t bro = (uint32_t)(((lane&7) + ((lane>>4)<<3))*256);
    const uint32_t bkx = (uint32_t)((lane&8)<<1);
#pragma unroll
    for (int kt = 0; kt < 8; kt++){
        uint32_t ah[4], al_[4];
        split2(y[2*kt][0],   y[2*kt][1],   ah[0], al_[0]);
        split2(y[2*kt][2],   y[2*kt][3],   ah[1], al_[1]);
        split2(y[2*kt+1][0], y[2*kt+1][1], ah[2], al_[2]);
        split2(y[2*kt+1][2], y[2*kt+1][3], ah[3], al_[3]);
        uint32_t bo = bro + (((uint32_t)(kt*32) + bkx) ^ aox);
#pragma unroll
        for (int t2 = 0; t2 < 2; t2++){
            uint32_t bh[4], bl[4];
            ldsm4(bh, Bh + bo + (uint32_t)(t2*4096));
            ldsm4(bl, Bl + bo + (uint32_t)(t2*4096));
            mma16816(d2[2*t2],   ah,  bh);
            mma16816(d2[2*t2],   ah,  bl);
            mma16816(d2[2*t2],   al_, bh);
            mma16816(d2[2*t2+1], ah,  bh+2);
            mma16816(d2[2*t2+1], ah,  bl+2);
            mma16816(d2[2*t2+1], al_, bh+2);
        }
    }
}

// ---------------- K0: weight prep ----------------
__global__ void k0_prep(const float* __restrict__ wq, const float* __restrict__ wk,
                        const float* __restrict__ wv, const float* __restrict__ w1,
                        const float* __restrict__ w2, const float* __restrict__ pe2,
                        const float* __restrict__ e2, const float* __restrict__ x1){
    int idx = blockIdx.x * blockDim.x + threadIdx.x;
    int stride = gridDim.x * blockDim.x;
    for (int t = idx; t < 16384; t += stride){
        int c = t >> 7, m = t & 127;
        uint32_t a = swz(c, m*2) >> 1;
        float v1 = w1[t];
        __nv_bfloat16 h1 = __float2bfloat16(v1);
        ((unsigned short*)g_w1hi)[a] = __bfloat16_as_ushort(h1);
        ((unsigned short*)g_w1lo)[a] = __bfloat16_as_ushort(__float2bfloat16(v1 - __bfloat162float(h1)));
        float v2 = w2[t];
        __nv_bfloat16 h2 = __float2bfloat16(v2);
        ((unsigned short*)g_w2hi)[a] = __bfloat16_as_ushort(h2);
        ((unsigned short*)g_w2lo)[a] = __bfloat16_as_ushort(__float2bfloat16(v2 - __bfloat162float(h2)));
    }
    for (int t = idx; t < 4096; t += stride){
        int c = t >> 5, m = t & 31;
        uint32_t a80 = (uint32_t)(c*40 + m);
        float vp = pe2[t];
        __nv_bfloat16 hp = __float2bfloat16(vp);
        ((unsigned short*)g_pe2hi)[a80] = __bfloat16_as_ushort(hp);
        ((unsigned short*)g_pe2lo)[a80] = __bfloat16_as_ushort(__float2bfloat16(vp - __bfloat162float(hp)));
        float ve = e2[t];
        __nv_bfloat16 he = __float2bfloat16(ve);
        ((unsigned short*)g_e2hi)[a80] = __bfloat16_as_ushort(he);
        ((unsigned short*)g_e2lo)[a80] = __bfloat16_as_ushort(__float2bfloat16(ve - __bfloat162float(he)));
        int m2 = t >> 7, c2 = t & 127;
        uint32_t ax = swz(m2, c2*2) >> 1;
        float vx = x1[t];
        __nv_bfloat16 hx = __float2bfloat16(vx);
        ((unsigned short*)g_x1hi)[ax] = __bfloat16_as_ushort(hx);
        ((unsigned short*)g_x1lo)[ax] = __bfloat16_as_ushort(__float2bfloat16(vx - __bfloat162float(hx)));
    }
    for (int t = idx; t < 8192; t += stride){
        int c = t >> 6, d = t & 63;
        g_wqT[d*128 + c] = wq[t];
        g_wkT[d*128 + c] = wk[t];
        g_wvT[d*128 + c] = wv[t];
    }
}

// ---------------- K1: q,k,v projections ----------------
__global__ void __launch_bounds__(128) k1_qkv(const float* __restrict__ x,
                                              const float* __restrict__ bq,
                                              const float* __restrict__ bk,
                                              const float* __restrict__ bv){
    __shared__ float sx[64];
    int row = blockIdx.x;
    int c = threadIdx.x;
    if (c < 64) sx[c] = x[(size_t)row*64 + c];
    __syncthreads();
    float aq = bq[c], ak = bk[c], av = bv[c];
#pragma unroll 8
    for (int d = 0; d < 64; d++){
        float xv = sx[d];
        aq = fmaf(xv, g_wqT[d*128 + c], aq);
        ak = fmaf(xv, g_wkT[d*128 + c], ak);
        av = fmaf(xv, g_wvT[d*128 + c], av);
    }
    g_q[(size_t)row*128 + c] = aq;
    g_k[(size_t)row*128 + c] = ak;
    g_v[(size_t)row*128 + c] = av;
}

// ---------------- K2: fused attention per (n,i), 512 threads ----------------
__global__ void __launch_bounds__(512) k2_attn(
    const float* __restrict__ U, const float* __restrict__ p,
    const float* __restrict__ ln1_g, const float* __restrict__ ln1_b,
    const float* __restrict__ b1,
    const float* __restrict__ ln2_g, const float* __restrict__ ln2_b,
    const float* __restrict__ b2,
    const float* __restrict__ pe1, const float* __restrict__ e1,
    float* __restrict__ xout)
{
    extern __shared__ char sm8[];
    float*  sxvT = (float*)(sm8 + XVT_B);     // [c][j] stride 130
    float*  sk   = (float*)(sm8 + SK_B);
    float*  sg1  = (float*)(sm8 + SG1_B);
    float*  sb1v = (float*)(sm8 + SB1_B);
    float*  sg2  = (float*)(sm8 + SG2_B);
    float*  sb2v = (float*)(sm8 + SB2_B);
    float*  sbi1 = (float*)(sm8 + SBI1_B);
    float*  sbi2 = (float*)(sm8 + SBI2_B);
    float*  spe1 = (float*)(sm8 + SPE1_B);
    float*  spij = (float*)(sm8 + SPIJ_B);
    float*  sxo  = (float*)(sm8 + SXO_B);
    float2* sp   = (float2*)(sm8 + SP_B);     // [ch][row]
    float2* sp2  = (float2*)(sm8 + SP2_B);
    float*  smax = (float*)(sm8 + SMAX_B);    // [ch][c]
    float2* sdn  = (float2*)(sm8 + SDN_B);    // [ch][c]

    const uint32_t sbase = smem_u32(sm8);
    const uint32_t Ah = sbase + A_HI_B, Al = sbase + A_LO_B;
    const uint32_t Wh = sbase + W_HI_B, Wl = sbase + W_LO_B;
    const int tid = threadIdx.x;
    const int lane = tid & 31, warp = tid >> 5;
    const int r = warp & 7, ch = warp >> 3;
    const int cb = ch*64;
    const int n = blockIdx.x >> 7, i = blockIdx.x & 127;
    const int g4 = lane & 3;
    const int rowA = r*16 + (lane>>2), rowB = rowA + 8;

    // ----- stage 0 -----
    if (tid < 128){
        size_t rowk = (size_t)(n*128 + i);
        sk[tid]   = g_k[rowk*128 + tid];
        sg1[tid]  = ln1_g[tid];  sb1v[tid] = ln1_b[tid];
        sg2[tid]  = ln2_g[tid];  sb2v[tid] = ln2_b[tid];
        sbi1[tid] = b1[tid];     sbi2[tid] = b2[tid];
        spe1[tid] = pe1[tid];
        int j = tid;
        float4 pi = *(const float4*)(p + (size_t)(n*128 + i)*4);
        float4 pj = *(const float4*)(p + (size_t)(n*128 + j)*4);
        spij[j*4+0] = pi.x - pj.x;
        spij[j*4+1] = pi.y - pj.y;
        spij[j*4+2] = pi.z - pj.z;
        spij[j*4+3] = pi.w - pj.w;
    }
    for (int t = tid; t < 2560; t += 512){
        ((uint32_t*)(sm8 + PE2H_B))[t] = g_pe2hi[t];
        ((uint32_t*)(sm8 + PE2L_B))[t] = g_pe2lo[t];
    }
    {
        const uint4* whi = (const uint4*)g_w1hi;
        const uint4* wlo = (const uint4*)g_w1lo;
        uint4* dhi = (uint4*)(sm8 + W_HI_B);
        uint4* dlo = (uint4*)(sm8 + W_LO_B);
#pragma unroll
        for (int t = 0; t < 4; t++){
            dhi[tid + 512*t] = whi[tid + 512*t];
            dlo[tid + 512*t] = wlo[tid + 512*t];
        }
    }
    const bool pad_i = (p[(size_t)(n*128 + i)*4] == 0.0f);
    __syncthreads();                                            // B1

    // ----- tn rows r*16..+15 (ch duplicates compute; ch==0 writes) -----
    {
        float4 pe1r = ((const float4*)spe1)[lane];
#pragma unroll 1
        for (int rr = 0; rr < 16; rr++){
            int jj = r*16 + rr;
            float4 pd = *(const float4*)(spij + jj*4);
            float t = pd.x*pe1r.x + pd.y*pe1r.y + pd.z*pe1r.z + pd.w*pe1r.w;
            float mu = wsum(t) * (1.0f/32.0f);
            float dd = t - mu;
            float var = wsum(dd*dd) * (1.0f/32.0f);
            float tn = fmaxf(dd * rsqrtf(var + 1e-5f), 0.0f);
            float tn1 = __shfl_down_sync(0xffffffffu, tn, 1);
            if (ch == 0 && !(lane & 1)){
                uint32_t hi, lo;
                split2(tn, tn1, hi, lo);
                *(uint32_t*)(sm8 + TNH_B + jj*80 + lane*2) = hi;
                *(uint32_t*)(sm8 + TNL_B + jj*80 + lane*2) = lo;
            }
        }
    }
    __syncthreads();                                            // B2

    // ----- GEMM0 -----
    float d[8][4];
    gemm32q(sbase + TNH_B, sbase + TNL_B, sbase + PE2H_B, sbase + PE2L_B, r, cb, lane, d);

    // ----- epi0: LN(eqpe) cross-warp -----
    {
        float s1A = 0, s2A = 0, s1B = 0, s2B = 0;
#pragma unroll
        for (int t = 0; t < 8; t++){
            s1A += d[t][0] + d[t][1]; s2A += d[t][0]*d[t][0] + d[t][1]*d[t][1];
            s1B += d[t][2] + d[t][3]; s2B += d[t][2]*d[t][2] + d[t][3]*d[t][3];
        }
        s1A = qsum(s1A); s2A = qsum(s2A); s1B = qsum(s1B); s2B = qsum(s2B);
        if (g4 == 0){
            sp[ch*128 + rowA] = make_float2(s1A, s2A);
            sp[ch*128 + rowB] = make_float2(s1B, s2B);
        }
    }
    __syncthreads();                                            // B3
    {
        float2 pA0 = sp[rowA], pA1 = sp[128 + rowA];
        float2 pB0 = sp[rowB], pB1 = sp[128 + rowB];
        float muA = (pA0.x + pA1.x)*(1.0f/128.0f);
        float rsA = rsqrtf((pA0.y + pA1.y)*(1.0f/128.0f) - muA*muA + 1e-5f);
        float muB = (pB0.x + pB1.x)*(1.0f/128.0f);
        float rsB = rsqrtf((pB0.y + pB1.y)*(1.0f/128.0f) - muB*muB + 1e-5f);

        const float* Ub = U + (size_t)blockIdx.x * 16384;
        const float* qb = g_q + (size_t)n*16384;
        const float* vb = g_v + (size_t)n*16384;
        float t1A = 0, t2A = 0, t1B = 0, t2B = 0;
#pragma unroll
        for (int t = 0; t < 8; t++){
            int c0 = cb + t*8 + g4*2;
            float2 uA = *(const float2*)(Ub + rowA*128 + c0);
            float2 uB = *(const float2*)(Ub + rowB*128 + c0);
            float2 qA = *(const float2*)(qb + rowA*128 + c0);
            float2 qB = *(const float2*)(qb + rowB*128 + c0);
            float2 vA = *(const float2*)(vb + rowA*128 + c0);
            float2 vB = *(const float2*)(vb + rowB*128 + c0);
            float2 kc = *(const float2*)(sk + c0);
            float eA0 = fmaxf((d[t][0]-muA)*rsA, 0.0f) + uA.x;
            float eA1 = fmaxf((d[t][1]-muA)*rsA, 0.0f) + uA.y;
            float eB0 = fmaxf((d[t][2]-muB)*rsB, 0.0f) + uB.x;
            float eB1 = fmaxf((d[t][3]-muB)*rsB, 0.0f) + uB.y;
            sxvT[(c0  )*130 + rowA] = vA.x + eA0;
            sxvT[(c0+1)*130 + rowA] = vA.y + eA1;
            sxvT[(c0  )*130 + rowB] = vB.x + eB0;
            sxvT[(c0+1)*130 + rowB] = vB.y + eB1;
            float rA0 = kc.x - qA.x + eA0;
            float rA1 = kc.y - qA.y + eA1;
            float rB0 = kc.x - qB.x + eB0;
            float rB1 = kc.y - qB.y + eB1;
            d[t][0] = rA0; d[t][1] = rA1; d[t][2] = rB0; d[t][3] = rB1;
            t1A += rA0 + rA1; t2A += rA0*rA0 + rA1*rA1;
            t1B += rB0 + rB1; t2B += rB0*rB0 + rB1*rB1;
        }
        t1A = qsum(t1A); t2A = qsum(t2A); t1B = qsum(t1B); t2B = qsum(t2B);
        if (g4 == 0){
            sp2[ch*128 + rowA] = make_float2(t1A, t2A);
            sp2[ch*128 + rowB] = make_float2(t1B, t2B);
        }
    }
    __syncthreads();                                            // B4
    {
        float2 pA0 = sp2[rowA], pA1 = sp2[128 + rowA];
        float2 pB0 = sp2[rowB], pB1 = sp2[128 + rowB];
        float nuA = (pA0.x + pA1.x)*(1.0f/128.0f);
        float nsA = rsqrtf((pA0.y + pA1.y)*(1.0f/128.0f) - nuA*nuA + 1e-5f);
        float nuB = (pB0.x + pB1.x)*(1.0f/128.0f);
        float nsB = rsqrtf((pB0.y + pB1.y)*(1.0f/128.0f) - nuB*nuB + 1e-5f);
#pragma unroll
        for (int t = 0; t < 8; t++){
            int c0 = cb + t*8 + g4*2;
            float2 gg = *(float2*)(sg1 + c0);
            float2 bb = *(float2*)(sb1v + c0);
            float yA0 = fmaxf(fmaf((d[t][0]-nuA)*nsA, gg.x, bb.x), 0.0f);
            float yA1 = fmaxf(fmaf((d[t][1]-nuA)*nsA, gg.y, bb.y), 0.0f);
            float yB0 = fmaxf(fmaf((d[t][2]-nuB)*nsB, gg.x, bb.x), 0.0f);
            float yB1 = fmaxf(fmaf((d[t][3]-nuB)*nsB, gg.y, bb.y), 0.0f);
            uint32_t hA, lA, hB, lB;
            split2(yA0, yA1, hA, lA);
            split2(yB0, yB1, hB, lB);
            int kb = cb*2 + t*16 + g4*4;
            *(uint32_t*)(sm8 + A_HI_B + swz(rowA, kb)) = hA;
            *(uint32_t*)(sm8 + A_LO_B + swz(rowA, kb)) = lA;
            *(uint32_t*)(sm8 + A_HI_B + swz(rowB, kb)) = hB;
            *(uint32_t*)(sm8 + A_LO_B + swz(rowB, kb)) = lB;
        }
    }
    __syncthreads();                                            // B5

    // ----- GEMM1 -----
    gemm128q(Ah, Al, Wh, Wl, r, cb, lane, d);

    // ----- epi1 -----
    {
        float s1A = 0, s2A = 0, s1B = 0, s2B = 0;
#pragma unroll
        for (int t = 0; t < 8; t++){
            int c0 = cb + t*8 + g4*2;
            float2 bb = *(float2*)(sbi1 + c0);
            d[t][0] += bb.x; d[t][1] += bb.y;
            d[t][2] += bb.x; d[t][3] += bb.y;
            s1A += d[t][0] + d[t][1]; s2A += d[t][0]*d[t][0] + d[t][1]*d[t][1];
            s1B += d[t][2] + d[t][3]; s2B += d[t][2]*d[t][2] + d[t][3]*d[t][3];
        }
        s1A = qsum(s1A); s2A = qsum(s2A); s1B = qsum(s1B); s2B = qsum(s2B);
        if (g4 == 0){
            sp[ch*128 + rowA] = make_float2(s1A, s2A);
            sp[ch*128 + rowB] = make_float2(s1B, s2B);
        }
    }
    __syncthreads();                                            // B6
    {
        float2 pA0 = sp[rowA], pA1 = sp[128 + rowA];
        float2 pB0 = sp[rowB], pB1 = sp[128 + rowB];
        float muA = (pA0.x + pA1.x)*(1.0f/128.0f);
        float rsA = rsqrtf((pA0.y + pA1.y)*(1.0f/128.0f) - muA*muA + 1e-5f);
        float muB = (pB0.x + pB1.x)*(1.0f/128.0f);
        float rsB = rsqrtf((pB0.y + pB1.y)*(1.0f/128.0f) - muB*muB + 1e-5f);
#pragma unroll
        for (int t = 0; t < 8; t++){
            int c0 = cb + t*8 + g4*2;
            float2 gg = *(float2*)(sg2 + c0);
            float2 bb = *(float2*)(sb2v + c0);
            float yA0 = fmaxf(fmaf((d[t][0]-muA)*rsA, gg.x, bb.x), 0.0f);
            float yA1 = fmaxf(fmaf((d[t][1]-muA)*rsA, gg.y, bb.y), 0.0f);
            float yB0 = fmaxf(fmaf((d[t][2]-muB)*rsB, gg.x, bb.x), 0.0f);
            float yB1 = fmaxf(fmaf((d[t][3]-muB)*rsB, gg.y, bb.y), 0.0f);
            uint32_t hA, lA, hB, lB;
            split2(yA0, yA1, hA, lA);
            split2(yB0, yB1, hB, lB);
            int kb = cb*2 + t*16 + g4*4;
            *(uint32_t*)(sm8 + A_HI_B + swz(rowA, kb)) = hA;
            *(uint32_t*)(sm8 + A_LO_B + swz(rowA, kb)) = lA;
            *(uint32_t*)(sm8 + A_HI_B + swz(rowB, kb)) = hB;
            *(uint32_t*)(sm8 + A_LO_B + swz(rowB, kb)) = lB;
        }
    }
    __syncthreads();                                            // B7 (A2 done, W1 reads done)

    // ----- W2 copy -----
    {
        const uint4* whi = (const uint4*)g_w2hi;
        const uint4* wlo = (const uint4*)g_w2lo;
        uint4* dhi = (uint4*)(sm8 + W_HI_B);
        uint4* dlo = (uint4*)(sm8 + W_LO_B);
#pragma unroll
        for (int t = 0; t < 4; t++){
            dhi[tid + 512*t] = whi[tid + 512*t];
            dlo[tid + 512*t] = wlo[tid + 512*t];
        }
    }
    __syncthreads();                                            // B8

    // ----- GEMM2 transposed: D[c][j] = W2 @ A2^T -----
    gemm128q(Wh, Wl, Ah, Al, r, cb, lane, d);

    // ----- softmax over j (cross-warp) + weighted xv sum -----
    {
        float bA = sbi2[rowA], bB = sbi2[rowB];
        float mA = -3.4e38f, mB = -3.4e38f;
#pragma unroll
        for (int t = 0; t < 8; t++){
            d[t][0] += bA; d[t][1] += bA;
            d[t][2] += bB; d[t][3] += bB;
            if (pad_i){ d[t][0] = NEGV; d[t][1] = NEGV; d[t][2] = NEGV; d[t][3] = NEGV; }
            mA = fmaxf(mA, fmaxf(d[t][0], d[t][1]));
            mB = fmaxf(mB, fmaxf(d[t][2], d[t][3]));
        }
        mA = qmax(mA); mB = qmax(mB);
        if (g4 == 0){
            smax[ch*128 + rowA] = mA;
            smax[ch*128 + rowB] = mB;
        }
        __syncthreads();                                        // B9
        mA = fmaxf(smax[rowA], smax[128 + rowA]);
        mB = fmaxf(smax[rowB], smax[128 + rowB]);
        float denA = 0, numA = 0, denB = 0, numB = 0;
#pragma unroll
        for (int t = 0; t < 8; t++){
            int jj = cb + t*8 + g4*2;
            float w0 = __expf(d[t][0] - mA), w1 = __expf(d[t][1] - mA);
            float w2 = __expf(d[t][2] - mB), w3 = __expf(d[t][3] - mB);
            float2 xA = *(float2*)(sxvT + rowA*130 + jj);
            float2 xB = *(float2*)(sxvT + rowB*130 + jj);
            denA += w0 + w1; numA += w0*xA.x + w1*xA.y;
            denB += w2 + w3; numB += w2*xB.x + w3*xB.y;
        }
        denA = qsum(denA); numA = qsum(numA);
        denB = qsum(denB); numB = qsum(numB);
        if (g4 == 0){
            sdn[ch*128 + rowA] = make_float2(denA, numA);
            sdn[ch*128 + rowB] = make_float2(denB, numB);
        }
        __syncthreads();                                        // B10
        if (ch == 0 && g4 == 0){
            float2 a0 = sdn[rowA], a1 = sdn[128 + rowA];
            float2 b0 = sdn[rowB], b1 = sdn[128 + rowB];
            float oA = (a0.y + a1.y) / (a0.x + a1.x);
            float oB = (b0.y + b1.y) / (b0.x + b1.x);
            sxo[rowA] = oA; sxo[rowB] = oB;
            xout[(size_t)blockIdx.x*128 + rowA] = oA;
            xout[(size_t)blockIdx.x*128 + rowB] = oB;
        }
    }
    __syncthreads();                                            // B11

    // ----- tail: avec/bvec -----
    if (tid < 64){
        int m = tid & 31, half = tid >> 5;
        const float* er = e1 + m*257 + half*128;
        float a = 0;
#pragma unroll 8
        for (int c2 = 0; c2 < 128; c2++) a = fmaf(sxo[c2], er[c2], a);
        if (half == 0) g_avec[(size_t)blockIdx.x*32 + m] = a;
        else           g_bvec[(size_t)blockIdx.x*32 + m] = a;
    }
}

// ---------------- K3: message MLP + position update ----------------
__global__ void __launch_bounds__(256, 2) k3_msg(
    const float* __restrict__ p, const float* __restrict__ e1,
    const float* __restrict__ x1b, const float* __restrict__ x2,
    const float* __restrict__ x2b,
    float* __restrict__ outp)
{
    extern __shared__ char sm8[];
    float* spij  = (float*)(sm8 + K3_SPIJ);
    float* snorm = (float*)(sm8 + K3_SNORM);
    float* ss    = (float*)(sm8 + K3_SS);
    float* spad  = (float*)(sm8 + K3_SPAD);
    float* sa    = (float*)(sm8 + K3_SA);
    float* se1c  = (float*)(sm8 + K3_SE1C);
    float* sx1b_ = (float*)(sm8 + K3_SX1B);
    float* sx2v  = (float*)(sm8 + K3_SX2V);

    const uint32_t sbase = smem_u32(sm8);
    const int tid = threadIdx.x, lane = tid & 31, warp = tid >> 5;
    const int n = blockIdx.x >> 7, i = blockIdx.x & 127;
    const bool pad_i = (p[(size_t)(n*128 + i)*4] == 0.0f);
    const int g4 = lane & 3;
    const int rowA = warp*16 + (lane>>2), rowB = rowA + 8;

    if (tid < 128){
        int j = tid;
        float4 pi = *(const float4*)(p + (size_t)(n*128 + i)*4);
        float4 pj = *(const float4*)(p + (size_t)(n*128 + j)*4);
        float dx = pi.x - pj.x, dy = pi.y - pj.y, dz = pi.z - pj.z, dw = pi.w - pj.w;
        spij[j*4+0] = dx; spij[j*4+1] = dy; spij[j*4+2] = dz; spij[j*4+3] = dw;
        spad[j] = (pj.x != 0.0f) ? 1.0f : 0.0f;
        snorm[j] = pad_i ? 0.0f : (dw*dw - dx*dx - dy*dy - dz*dz);
    }
    if (tid < 32){
        sa[tid]    = g_avec[(size_t)(n*128 + i)*32 + tid];
        se1c[tid]  = e1[tid*257 + 256];
        sx1b_[tid] = x1b[tid];
        sx2v[tid]  = x2[tid];
    }
    for (int t = tid; t < 2560; t += 256){
        ((uint32_t*)(sm8 + K3_B1H))[t] = g_e2hi[t];
        ((uint32_t*)(sm8 + K3_B1L))[t] = g_e2lo[t];
    }
    for (int t = tid; t < 2048; t += 256){
        ((uint32_t*)(sm8 + K3_B2H))[t] = g_x1hi[t];
        ((uint32_t*)(sm8 + K3_B2L))[t] = g_x1lo[t];
    }
    __syncthreads();

    // h32 tile
    const float* bv = g_bvec + (size_t)n*4096;
    for (int idx = tid; idx < 2048; idx += 256){
        int row = idx >> 4, mp = idx & 15, m = mp*2;
        float nb = snorm[row];
        float2 bb = *(const float2*)(bv + row*32 + m);
        float h0 = fmaxf(sa[m]   + bb.x + nb*se1c[m],   0.0f);
        float h1 = fmaxf(sa[m+1] + bb.y + nb*se1c[m+1], 0.0f);
        uint32_t hi, lo;
        split2(h0, h1, hi, lo);
        *(uint32_t*)(sm8 + K3_A1H + row*80 + mp*4) = hi;
        *(uint32_t*)(sm8 + K3_A1L + row*80 + mp*4) = lo;
    }
    __syncthreads();

    // MMA1: mij_pre = h32 @ e2^T
    float d[16][4];
    gemm32(sbase + K3_A1H, sbase + K3_A1L, sbase + K3_B1H, sbase + K3_B1L, warp, lane, d);

    // relu -> mask -> LN (registers)
    {
        float s1A = 0, s2A = 0, s1B = 0, s2B = 0;
#pragma unroll
        for (int t = 0; t < 16; t++){
            float a0 = fmaxf(d[t][0], 0.0f), a1 = fmaxf(d[t][1], 0.0f);
            float b0 = fmaxf(d[t][2], 0.0f), b1 = fmaxf(d[t][3], 0.0f);
            if (pad_i){ a0 = NEGV; a1 = NEGV; b0 = NEGV; b1 = NEGV; }
            d[t][0] = a0; d[t][1] = a1; d[t][2] = b0; d[t][3] = b1;
            s1A += a0 + a1; s2A += a0*a0 + a1*a1;
            s1B += b0 + b1; s2B += b0*b0 + b1*b1;
        }
        s1A = qsum(s1A); s2A = qsum(s2A); s1B = qsum(s1B); s2B = qsum(s2B);
        float muA = s1A*(1.0f/128.0f), vA = s2A*(1.0f/128.0f) - muA*muA;
        float muB = s1B*(1.0f/128.0f), vB = s2B*(1.0f/128.0f) - muB*muB;
        float rsA = rsqrtf(fmaxf(vA, 0.0f) + 1e-5f);
        float rsB = rsqrtf(fmaxf(vB, 0.0f) + 1e-5f);
#pragma unroll
        for (int t = 0; t < 16; t++){
            d[t][0] = (d[t][0]-muA)*rsA; d[t][1] = (d[t][1]-muA)*rsA;
            d[t][2] = (d[t][2]-muB)*rsB; d[t][3] = (d[t][3]-muB)*rsB;
        }
    }

    // MMA2: t_pre = y @ x1^T, A straight from registers
    float d2[4][4];
    mma2_regA(d, sbase + K3_B2H, sbase + K3_B2L, lane, d2);

    // scores
    {
        float x2bv = x2b[0];
        float sA = 0, sB = 0;
#pragma unroll
        for (int t = 0; t < 4; t++){
            int c0 = t*8 + g4*2;
            float2 xb = *(float2*)(sx1b_ + c0);
            float2 xv = *(float2*)(sx2v + c0);
            sA += fmaxf(d2[t][0] + xb.x, 0.0f)*xv.x + fmaxf(d2[t][1] + xb.y, 0.0f)*xv.y;
            sB += fmaxf(d2[t][2] + xb.x, 0.0f)*xv.x + fmaxf(d2[t][3] + xb.y, 0.0f)*xv.y;
        }
        sA = qsum(sA); sB = qsum(sB);
        if (g4 == 0){
            ss[rowA] = fmaxf(sA + x2bv, 0.0f);
            ss[rowB] = fmaxf(sB + x2bv, 0.0f);
        }
    }
    __syncthreads();

    if (warp == 0){
        float m0 = fmaxf(fmaxf(ss[lane], ss[lane+32]), fmaxf(ss[lane+64], ss[lane+96]));
#pragma unroll
        for (int k = 16; k > 0; k >>= 1) m0 = fmaxf(m0, __shfl_xor_sync(0xffffffffu, m0, k));
        float den = 0, dx = 0, dy = 0, dz = 0, dw = 0, cnt = 0;
#pragma unroll
        for (int q2 = 0; q2 < 4; q2++){
            int b = lane + 32*q2;
            float w = __expf(ss[b] - m0);
            den += w;
            dx = fmaf(w, spij[b*4+0], dx);
            dy = fmaf(w, spij[b*4+1], dy);
            dz = fmaf(w, spij[b*4+2], dz);
            dw = fmaf(w, spij[b*4+3], dw);
            cnt += spad[b];
        }
        den = wsum(den); dx = wsum(dx); dy = wsum(dy);
        dz = wsum(dz);   dw = wsum(dw); cnt = wsum(cnt);
        if (lane == 0){
            float inv = 1.0f / (den * cnt);
            const float* pr = p + (size_t)(n*128 + i)*4;
            float* o = outp + (size_t)(n*128 + i)*4;
            float d4[4] = {dx, dy, dz, dw};
#pragma unroll
            for (int dd = 0; dd < 4; dd++){
                float pv = pr[dd];
                o[dd] = (pv == 0.0f) ? 0.0f : pv + d4[dd]*inv;
            }
        }
    }
}

extern "C" void kernel_launch(void* const* d_in, const int* in_sizes, int n_in,
                              void* d_out, int out_size){
    const float* x     = (const float*)d_in[0];
    const float* p     = (const float*)d_in[1];
    const float* U     = (const float*)d_in[2];
    const float* wq    = (const float*)d_in[3];
    const float* bq    = (const float*)d_in[4];
    const float* wk    = (const float*)d_in[5];
    const float* bk    = (const float*)d_in[6];
    const float* wv    = (const float*)d_in[7];
    const float* bv    = (const float*)d_in[8];
    const float* ln1_g = (const float*)d_in[9];
    const float* ln1_b = (const float*)d_in[10];
    const float* w1    = (const float*)d_in[11];
    const float* b1    = (const float*)d_in[12];
    const float* ln2_g = (const float*)d_in[13];
    const float* ln2_b = (const float*)d_in[14];
    const float* w2    = (const float*)d_in[15];
    const float* b2    = (const float*)d_in[16];
    const float* pe1   = (const float*)d_in[17];
    const float* pe2   = (const float*)d_in[18];
    const float* e1    = (const float*)d_in[19];
    const float* e2    = (const float*)d_in[20];
    const float* x1    = (const float*)d_in[21];
    const float* x1b   = (const float*)d_in[22];
    const float* x2    = (const float*)d_in[23];
    const float* x2b   = (const float*)d_in[24];
    float* out  = (float*)d_out;
    float* xout = out;                 // (16,128,128)
    float* newp = out + 16*128*128;    // (16,128,4)

    cudaFuncSetAttribute(k2_attn, cudaFuncAttributeMaxDynamicSharedMemorySize, K2_SMEM);
    cudaFuncSetAttribute(k3_msg,  cudaFuncAttributeMaxDynamicSharedMemorySize, K3_SMEM);

    k0_prep<<<64, 256>>>(wq, wk, wv, w1, w2, pe2, e2, x1);
    k1_qkv<<<2048, 128>>>(x, bq, bk, bv);
    k2_attn<<<2048, 512, K2_SMEM>>>(U, p, ln1_g, ln1_b, b1, ln2_g, ln2_b, b2, pe1, e1, xout);
    k3_msg<<<2048, 256, K3_SMEM>>>(p, e1, x1b, x2, x2b, newp);
}

// round 8
// speedup vs baseline: 3.1661x; 1.2801x over previous
#include <cuda_runtime.h>
#include <cuda_bf16.h>
#include <math.h>
#include <stdint.h>

#define NEGV (-10000.0f)
#define LOG2E 1.44269504088896340736f

// ---------------- K2 smem byte offsets (512-thread version) ----------------
#define XVT_B    0          // fp32 xvT [128][130] (66560B); pe2/tn tiles alias front
#define PE2H_B   0
#define PE2L_B   10240
#define TNH_B    20480
#define TNL_B    30720
#define A_HI_B   67584      // bf16 A tile (XOR swizzle, 32KB each)
#define A_LO_B   100352
#define W_HI_B   133120     // bf16 W tile: w1 -> w2
#define W_LO_B   165888
#define SK_B     198656
#define SG1_B    199168
#define SB1_B    199680
#define SG2_B    200192
#define SB2_B    200704
#define SBI1_B   201216
#define SBI2_B   201728
#define SPE1_B   202240
#define SPIJ_B   202752     // 2048
#define SXO_B    204800     // 512
#define SP_B     205312     // 2048: [ch][row] float2 partials
#define SP2_B    207360     // 2048
#define SDN_B    209408     // 2048: [ch][c] float2
#define K2_SMEM  211456

// ---------------- K3 smem byte offsets ----------------
#define K3_A1H   0
#define K3_A1L   10240
#define K3_B1H   20480
#define K3_B1L   30720
#define K3_B2H   40960
#define K3_B2L   49152
#define K3_SPIJ  57344      // 2048
#define K3_SNORM 59392      // 512
#define K3_SS    59904      // 512
#define K3_SPAD  60416      // 512
#define K3_SA    60928      // 128
#define K3_SE1C  61056      // 128
#define K3_SX1B  61184      // 128
#define K3_SX2V  61312      // 128
#define K3_SMEM  61440

// ---------------- device scratch ----------------
__device__ float g_q[16*128*128];
__device__ float g_k[16*128*128];
__device__ float g_v[16*128*128];
__device__ float g_wqT[64*128];
__device__ float g_wkT[64*128];
__device__ float g_wvT[64*128];
__device__ float g_avec[16*128*32];
__device__ float g_bvec[16*128*32];
__device__ uint32_t g_w1hi[8192];
__device__ uint32_t g_w1lo[8192];
__device__ uint32_t g_w2hi[8192];
__device__ uint32_t g_w2lo[8192];
__device__ uint32_t g_x1hi[2048];
__device__ uint32_t g_x1lo[2048];
__device__ uint32_t g_pe2hi[2560];
__device__ uint32_t g_pe2lo[2560];
__device__ uint32_t g_e2hi[2560];
__device__ uint32_t g_e2lo[2560];

// ---------------- helpers ----------------
__device__ __forceinline__ float wsum(float v){
#pragma unroll
    for (int k = 16; k > 0; k >>= 1) v += __shfl_xor_sync(0xffffffffu, v, k);
    return v;
}
__device__ __forceinline__ float qsum(float v){
    v += __shfl_xor_sync(0xffffffffu, v, 1);
    v += __shfl_xor_sync(0xffffffffu, v, 2);
    return v;
}
__device__ __forceinline__ uint32_t smem_u32(const void* p){
    uint32_t a;
    asm("{ .reg .u64 t; cvta.to.shared.u64 t, %1; cvt.u32.u64 %0, t; }" : "=r"(a) : "l"(p));
    return a;
}
__device__ __forceinline__ uint32_t swz(int row, int kb){
    return (uint32_t)(row*256 + ((kb & 0xF0) ^ ((row & 7) << 4)) + (kb & 15));
}
__device__ __forceinline__ float ex2(float x){
    float r; asm("ex2.approx.ftz.f32 %0, %1;" : "=f"(r) : "f"(x)); return r;
}
// fast hi/lo bf16 split: low halfword = x, high halfword = y
__device__ __forceinline__ void split2(float x, float y, uint32_t &hi, uint32_t &lo){
    uint32_t h;
    asm("cvt.rn.bf16x2.f32 %0, %1, %2;" : "=r"(h) : "f"(y), "f"(x));
    float xh = __uint_as_float(h << 16);
    float yh = __uint_as_float(h & 0xFFFF0000u);
    asm("cvt.rn.bf16x2.f32 %0, %1, %2;" : "=r"(lo) : "f"(y - yh), "f"(x - xh));
    hi = h;
}
__device__ __forceinline__ void ldsm4(uint32_t a[4], uint32_t addr){
    asm volatile("ldmatrix.sync.aligned.m8n8.x4.shared.b16 {%0,%1,%2,%3}, [%4];"
        : "=r"(a[0]), "=r"(a[1]), "=r"(a[2]), "=r"(a[3]) : "r"(addr));
}
__device__ __forceinline__ void mma16816(float d[4], const uint32_t a[4], const uint32_t b[2]){
    asm volatile("mma.sync.aligned.m16n8k16.row.col.f32.bf16.bf16.f32 "
        "{%0,%1,%2,%3}, {%4,%5,%6,%7}, {%8,%9}, {%0,%1,%2,%3};"
        : "+f"(d[0]), "+f"(d[1]), "+f"(d[2]), "+f"(d[3])
        : "r"(a[0]), "r"(a[1]), "r"(a[2]), "r"(a[3]), "r"(b[0]), "r"(b[1]));
}

// K2 quadrant GEMM: A rows r*16..+15, B rows cb..cb+63, K=128, XOR tiles.
__device__ __forceinline__ void gemm128q(uint32_t Ah, uint32_t Al, uint32_t Bh, uint32_t Bl,
                                         int r, int cb, int lane, float d[8][4]){
#pragma unroll
    for (int t = 0; t < 8; t++){ d[t][0]=0.f; d[t][1]=0.f; d[t][2]=0.f; d[t][3]=0.f; }
    const uint32_t aro = (uint32_t)((r*16 + (lane&15))*256);
    const uint32_t aox = (uint32_t)((lane&7)<<4);
    const uint32_t akx = (uint32_t)(lane&16);
    const uint32_t bro = (uint32_t)((cb + (lane&7) + ((lane>>4)<<3))*256);
    const uint32_t bkx = (uint32_t)((lane&8)<<1);
#pragma unroll 1
    for (int kk = 0; kk < 8; kk++){
        uint32_t ka = (uint32_t)(kk*32);
        uint32_t ah[4], al_[4];
        ldsm4(ah,  Ah + aro + ((ka + akx) ^ aox));
        ldsm4(al_, Al + aro + ((ka + akx) ^ aox));
        uint32_t bo = bro + ((ka + bkx) ^ aox);
#pragma unroll
        for (int t2 = 0; t2 < 4; t2++){
            uint32_t bh[4], bl[4];
            ldsm4(bh, Bh + bo + (uint32_t)(t2*4096));
            ldsm4(bl, Bl + bo + (uint32_t)(t2*4096));
            mma16816(d[2*t2],   ah,  bh);
            mma16816(d[2*t2],   ah,  bl);
            mma16816(d[2*t2],   al_, bh);
            mma16816(d[2*t2+1], ah,  bh+2);
            mma16816(d[2*t2+1], ah,  bl+2);
            mma16816(d[2*t2+1], al_, bh+2);
        }
    }
}

// K2 quadrant small-K GEMM: K=32, 80B-stride tiles.
__device__ __forceinline__ void gemm32q(uint32_t Ah, uint32_t Al, uint32_t Bh, uint32_t Bl,
                                        int r, int cb, int lane, float d[8][4]){
#pragma unroll
    for (int t = 0; t < 8; t++){ d[t][0]=0.f; d[t][1]=0.f; d[t][2]=0.f; d[t][3]=0.f; }
    const uint32_t aro = (uint32_t)((r*16 + (lane&15))*80 + (lane&16));
    const uint32_t bro = (uint32_t)((cb + (lane&7) + ((lane>>4)<<3))*80 + ((lane&8)<<1));
#pragma unroll
    for (int kk = 0; kk < 2; kk++){
        uint32_t ah[4], al_[4];
        ldsm4(ah,  Ah + aro + (uint32_t)(kk*32));
        ldsm4(al_, Al + aro + (uint32_t)(kk*32));
#pragma unroll
        for (int t2 = 0; t2 < 4; t2++){
            uint32_t bh[4], bl[4];
            ldsm4(bh, Bh + bro + (uint32_t)(kk*32 + t2*1280));
            ldsm4(bl, Bl + bro + (uint32_t)(kk*32 + t2*1280));
            mma16816(d[2*t2],   ah,  bh);
            mma16816(d[2*t2],   ah,  bl);
            mma16816(d[2*t2],   al_, bh);
            mma16816(d[2*t2+1], ah,  bh+2);
            mma16816(d[2*t2+1], ah,  bl+2);
            mma16816(d[2*t2+1], al_, bh+2);
        }
    }
}

// K3 full-width K=32 GEMM (8 warps, 16 rows each, all 128 cols)
__device__ __forceinline__ void gemm32(uint32_t Ah, uint32_t Al, uint32_t Bh, uint32_t Bl,
                                       int warp, int lane, float d[16][4]){
#pragma unroll
    for (int t = 0; t < 16; t++){ d[t][0]=0.f; d[t][1]=0.f; d[t][2]=0.f; d[t][3]=0.f; }
    const uint32_t aro = (uint32_t)((warp*16 + (lane&15))*80 + (lane&16));
    const uint32_t bro = (uint32_t)(((lane&7) + ((lane>>4)<<3))*80 + ((lane&8)<<1));
#pragma unroll
    for (int kk = 0; kk < 2; kk++){
        uint32_t ah[4], al_[4];
        ldsm4(ah,  Ah + aro + (uint32_t)(kk*32));
        ldsm4(al_, Al + aro + (uint32_t)(kk*32));
#pragma unroll
        for (int t2 = 0; t2 < 8; t2++){
            uint32_t bh[4], bl[4];
            ldsm4(bh, Bh + bro + (uint32_t)(kk*32 + t2*1280));
            ldsm4(bl, Bl + bro + (uint32_t)(kk*32 + t2*1280));
            mma16816(d[2*t2],   ah,  bh);
            mma16816(d[2*t2],   ah,  bl);
            mma16816(d[2*t2],   al_, bh);
            mma16816(d[2*t2+1], ah,  bh+2);
            mma16816(d[2*t2+1], ah,  bl+2);
            mma16816(d[2*t2+1], al_, bh+2);
        }
    }
}

// K3 MMA2 with A from registers (y in C-fragment layout), B = x1 tile (32 rows, XOR)
__device__ __forceinline__ void mma2_regA(const float y[16][4], uint32_t Bh, uint32_t Bl,
                                          int lane, float d2[4][4]){
#pragma unroll
    for (int t = 0; t < 4; t++){ d2[t][0]=0.f; d2[t][1]=0.f; d2[t][2]=0.f; d2[t][3]=0.f; }
    const uint32_t aox = (uint32_t)((lane&7)<<4);
    const uint32_t bro = (uint32_t)(((lane&7) + ((lane>>4)<<3))*256);
    const uint32_t bkx = (uint32_t)((lane&8)<<1);
#pragma unroll
    for (int kt = 0; kt < 8; kt++){
        uint32_t ah[4], al_[4];
        split2(y[2*kt][0],   y[2*kt][1],   ah[0], al_[0]);
        split2(y[2*kt][2],   y[2*kt][3],   ah[1], al_[1]);
        split2(y[2*kt+1][0], y[2*kt+1][1], ah[2], al_[2]);
        split2(y[2*kt+1][2], y[2*kt+1][3], ah[3], al_[3]);
        uint32_t bo = bro + (((uint32_t)(kt*32) + bkx) ^ aox);
#pragma unroll
        for (int t2 = 0; t2 < 2; t2++){
            uint32_t bh[4], bl[4];
            ldsm4(bh, Bh + bo + (uint32_t)(t2*4096));
            ldsm4(bl, Bl + bo + (uint32_t)(t2*4096));
            mma16816(d2[2*t2],   ah,  bh);
            mma16816(d2[2*t2],   ah,  bl);
            mma16816(d2[2*t2],   al_, bh);
            mma16816(d2[2*t2+1], ah,  bh+2);
            mma16816(d2[2*t2+1], ah,  bl+2);
            mma16816(d2[2*t2+1], al_, bh+2);
        }
    }
}

// ---------------- K0: weight prep ----------------
__global__ void k0_prep(const float* __restrict__ wq, const float* __restrict__ wk,
                        const float* __restrict__ wv, const float* __restrict__ w1,
                        const float* __restrict__ w2, const float* __restrict__ pe2,
                        const float* __restrict__ e2, const float* __restrict__ x1){
    int idx = blockIdx.x * blockDim.x + threadIdx.x;
    int stride = gridDim.x * blockDim.x;
    for (int t = idx; t < 16384; t += stride){
        int c = t >> 7, m = t & 127;
        uint32_t a = swz(c, m*2) >> 1;
        float v1 = w1[t];
        __nv_bfloat16 h1 = __float2bfloat16(v1);
        ((unsigned short*)g_w1hi)[a] = __bfloat16_as_ushort(h1);
        ((unsigned short*)g_w1lo)[a] = __bfloat16_as_ushort(__float2bfloat16(v1 - __bfloat162float(h1)));
        float v2 = w2[t] * LOG2E;   // pre-scale for ex2 softmax
        __nv_bfloat16 h2 = __float2bfloat16(v2);
        ((unsigned short*)g_w2hi)[a] = __bfloat16_as_ushort(h2);
        ((unsigned short*)g_w2lo)[a] = __bfloat16_as_ushort(__float2bfloat16(v2 - __bfloat162float(h2)));
    }
    for (int t = idx; t < 4096; t += stride){
        int c = t >> 5, m = t & 31;
        uint32_t a80 = (uint32_t)(c*40 + m);
        float vp = pe2[t];
        __nv_bfloat16 hp = __float2bfloat16(vp);
        ((unsigned short*)g_pe2hi)[a80] = __bfloat16_as_ushort(hp);
        ((unsigned short*)g_pe2lo)[a80] = __bfloat16_as_ushort(__float2bfloat16(vp - __bfloat162float(hp)));
        float ve = e2[t];
        __nv_bfloat16 he = __float2bfloat16(ve);
        ((unsigned short*)g_e2hi)[a80] = __bfloat16_as_ushort(he);
        ((unsigned short*)g_e2lo)[a80] = __bfloat16_as_ushort(__float2bfloat16(ve - __bfloat162float(he)));
        int m2 = t >> 7, c2 = t & 127;
        uint32_t ax = swz(m2, c2*2) >> 1;
        float vx = x1[t];
        __nv_bfloat16 hx = __float2bfloat16(vx);
        ((unsigned short*)g_x1hi)[ax] = __bfloat16_as_ushort(hx);
        ((unsigned short*)g_x1lo)[ax] = __bfloat16_as_ushort(__float2bfloat16(vx - __bfloat162float(hx)));
    }
    for (int t = idx; t < 8192; t += stride){
        int c = t >> 6, d = t & 63;
        g_wqT[d*128 + c] = wq[t];
        g_wkT[d*128 + c] = wk[t];
        g_wvT[d*128 + c] = wv[t];
    }
}

// ---------------- K1: q,k,v projections ----------------
__global__ void __launch_bounds__(128) k1_qkv(const float* __restrict__ x,
                                              const float* __restrict__ bq,
                                              const float* __restrict__ bk,
                                              const float* __restrict__ bv){
    __shared__ float sx[64];
    int row = blockIdx.x;
    int c = threadIdx.x;
    if (c < 64) sx[c] = x[(size_t)row*64 + c];
    __syncthreads();
    float aq = bq[c], ak = bk[c], av = bv[c];
#pragma unroll 8
    for (int d = 0; d < 64; d++){
        float xv = sx[d];
        aq = fmaf(xv, g_wqT[d*128 + c], aq);
        ak = fmaf(xv, g_wkT[d*128 + c], ak);
        av = fmaf(xv, g_wvT[d*128 + c], av);
    }
    g_q[(size_t)row*128 + c] = aq;
    g_k[(size_t)row*128 + c] = ak;
    g_v[(size_t)row*128 + c] = av;
}

// ---------------- K2: fused attention per (n,i), 512 threads ----------------
__global__ void __launch_bounds__(512) k2_attn(
    const float* __restrict__ U, const float* __restrict__ p,
    const float* __restrict__ ln1_g, const float* __restrict__ ln1_b,
    const float* __restrict__ b1,
    const float* __restrict__ ln2_g, const float* __restrict__ ln2_b,
    const float* __restrict__ b2,
    const float* __restrict__ pe1, const float* __restrict__ e1,
    float* __restrict__ xout)
{
    extern __shared__ char sm8[];
    float*  sxvT = (float*)(sm8 + XVT_B);     // [c][j] stride 130
    float*  sk   = (float*)(sm8 + SK_B);
    float*  sg1  = (float*)(sm8 + SG1_B);
    float*  sb1v = (float*)(sm8 + SB1_B);
    float*  sg2  = (float*)(sm8 + SG2_B);
    float*  sb2v = (float*)(sm8 + SB2_B);
    float*  sbi1 = (float*)(sm8 + SBI1_B);
    float*  sbi2 = (float*)(sm8 + SBI2_B);
    float*  spe1 = (float*)(sm8 + SPE1_B);
    float*  spij = (float*)(sm8 + SPIJ_B);
    float*  sxo  = (float*)(sm8 + SXO_B);
    float2* sp   = (float2*)(sm8 + SP_B);
    float2* sp2  = (float2*)(sm8 + SP2_B);
    float2* sdn  = (float2*)(sm8 + SDN_B);

    const uint32_t sbase = smem_u32(sm8);
    const uint32_t Ah = sbase + A_HI_B, Al = sbase + A_LO_B;
    const uint32_t Wh = sbase + W_HI_B, Wl = sbase + W_LO_B;
    const int tid = threadIdx.x;
    const int lane = tid & 31, warp = tid >> 5;
    const int r = warp & 7, ch = warp >> 3;
    const int cb = ch*64;
    const int n = blockIdx.x >> 7, i = blockIdx.x & 127;
    const int g4 = lane & 3;
    const int rowA = r*16 + (lane>>2), rowB = rowA + 8;

    // ----- stage 0 -----
    if (tid < 128){
        size_t rowk = (size_t)(n*128 + i);
        sk[tid]   = g_k[rowk*128 + tid];
        sg1[tid]  = ln1_g[tid];  sb1v[tid] = ln1_b[tid];
        sg2[tid]  = ln2_g[tid];  sb2v[tid] = ln2_b[tid];
        sbi1[tid] = b1[tid];     sbi2[tid] = b2[tid] * LOG2E;
        spe1[tid] = pe1[tid];
        int j = tid;
        float4 pi = *(const float4*)(p + (size_t)(n*128 + i)*4);
        float4 pj = *(const float4*)(p + (size_t)(n*128 + j)*4);
        spij[j*4+0] = pi.x - pj.x;
        spij[j*4+1] = pi.y - pj.y;
        spij[j*4+2] = pi.z - pj.z;
        spij[j*4+3] = pi.w - pj.w;
    }
    for (int t = tid; t < 2560; t += 512){
        ((uint32_t*)(sm8 + PE2H_B))[t] = g_pe2hi[t];
        ((uint32_t*)(sm8 + PE2L_B))[t] = g_pe2lo[t];
    }
    {
        const uint4* whi = (const uint4*)g_w1hi;
        const uint4* wlo = (const uint4*)g_w1lo;
        uint4* dhi = (uint4*)(sm8 + W_HI_B);
        uint4* dlo = (uint4*)(sm8 + W_LO_B);
#pragma unroll
        for (int t = 0; t < 4; t++){
            dhi[tid + 512*t] = whi[tid + 512*t];
            dlo[tid + 512*t] = wlo[tid + 512*t];
        }
    }
    const bool pad_i = (p[(size_t)(n*128 + i)*4] == 0.0f);
    __syncthreads();                                            // B1

    // ----- tn: 8 rows per warp (all 16 warps) -----
    {
        float4 pe1r = ((const float4*)spe1)[lane];
#pragma unroll 1
        for (int rr = 0; rr < 8; rr++){
            int jj = warp*8 + rr;
            float4 pd = *(const float4*)(spij + jj*4);
            float t = pd.x*pe1r.x + pd.y*pe1r.y + pd.z*pe1r.z + pd.w*pe1r.w;
            float mu = wsum(t) * (1.0f/32.0f);
            float dd = t - mu;
            float var = wsum(dd*dd) * (1.0f/32.0f);
            float tn = fmaxf(dd * rsqrtf(var + 1e-5f), 0.0f);
            float tn1 = __shfl_down_sync(0xffffffffu, tn, 1);
            if (!(lane & 1)){
                uint32_t hi, lo;
                split2(tn, tn1, hi, lo);
                *(uint32_t*)(sm8 + TNH_B + jj*80 + lane*2) = hi;
                *(uint32_t*)(sm8 + TNL_B + jj*80 + lane*2) = lo;
            }
        }
    }
    __syncthreads();                                            // B2

    // ----- GEMM0: eqpe_pre -----
    float d[8][4];
    gemm32q(sbase + TNH_B, sbase + TNL_B, sbase + PE2H_B, sbase + PE2L_B, r, cb, lane, d);

    // ----- epi0 stats -----
    {
        float s1A = 0, s2A = 0, s1B = 0, s2B = 0;
#pragma unroll
        for (int t = 0; t < 8; t++){
            s1A += d[t][0] + d[t][1]; s2A += d[t][0]*d[t][0] + d[t][1]*d[t][1];
            s1B += d[t][2] + d[t][3]; s2B += d[t][2]*d[t][2] + d[t][3]*d[t][3];
        }
        s1A = qsum(s1A); s2A = qsum(s2A); s1B = qsum(s1B); s2B = qsum(s2B);
        if (g4 == 0){
            sp[ch*128 + rowA] = make_float2(s1A, s2A);
            sp[ch*128 + rowB] = make_float2(s1B, s2B);
        }
    }
    __syncthreads();                                            // B3

    const float* Ub = U + (size_t)blockIdx.x * 16384;
    const float* vb = g_v + (size_t)n*16384;

    if (pad_i){
        // ---- pad short-circuit: x_out = mean_j(xv) ----
        float2 pA0 = sp[rowA], pA1 = sp[128 + rowA];
        float2 pB0 = sp[rowB], pB1 = sp[128 + rowB];
        float muA = (pA0.x + pA1.x)*(1.0f/128.0f);
        float rsA = rsqrtf((pA0.y + pA1.y)*(1.0f/128.0f) - muA*muA + 1e-5f);
        float muB = (pB0.x + pB1.x)*(1.0f/128.0f);
        float rsB = rsqrtf((pB0.y + pB1.y)*(1.0f/128.0f) - muB*muB + 1e-5f);
#pragma unroll
        for (int t = 0; t < 8; t++){
            int c0 = cb + t*8 + g4*2;
            float2 uA = *(const float2*)(Ub + rowA*128 + c0);
            float2 uB = *(const float2*)(Ub + rowB*128 + c0);
            float2 vA = *(const float2*)(vb + rowA*128 + c0);
            float2 vB = *(const float2*)(vb + rowB*128 + c0);
            sxvT[(c0  )*130 + rowA] = vA.x + fmaxf((d[t][0]-muA)*rsA, 0.0f) + uA.x;
            sxvT[(c0+1)*130 + rowA] = vA.y + fmaxf((d[t][1]-muA)*rsA, 0.0f) + uA.y;
            sxvT[(c0  )*130 + rowB] = vB.x + fmaxf((d[t][2]-muB)*rsB, 0.0f) + uB.x;
            sxvT[(c0+1)*130 + rowB] = vB.y + fmaxf((d[t][3]-muB)*rsB, 0.0f) + uB.y;
        }
        __syncthreads();
        if (tid < 128){
            float s = 0.0f;
            const float* row = sxvT + tid*130;
#pragma unroll 8
            for (int j = 0; j < 128; j++) s += row[j];
            float o = s * (1.0f/128.0f);
            sxo[tid] = o;
            xout[(size_t)blockIdx.x*128 + tid] = o;
        }
        __syncthreads();
        if (tid < 64){
            int m = tid & 31, half = tid >> 5;
            const float* er = e1 + m*257 + half*128;
            float a = 0;
#pragma unroll 8
            for (int c2 = 0; c2 < 128; c2++) a = fmaf(sxo[c2], er[c2], a);
            if (half == 0) g_avec[(size_t)blockIdx.x*32 + m] = a;
            else           g_bvec[(size_t)blockIdx.x*32 + m] = a;
        }
        return;
    }

    // ----- non-pad: full epi0 -----
    {
        float2 pA0 = sp[rowA], pA1 = sp[128 + rowA];
        float2 pB0 = sp[rowB], pB1 = sp[128 + rowB];
        float muA = (pA0.x + pA1.x)*(1.0f/128.0f);
        float rsA = rsqrtf((pA0.y + pA1.y)*(1.0f/128.0f) - muA*muA + 1e-5f);
        float muB = (pB0.x + pB1.x)*(1.0f/128.0f);
        float rsB = rsqrtf((pB0.y + pB1.y)*(1.0f/128.0f) - muB*muB + 1e-5f);

        const float* qb = g_q + (size_t)n*16384;
        float t1A = 0, t2A = 0, t1B = 0, t2B = 0;
#pragma unroll
        for (int t = 0; t < 8; t++){
            int c0 = cb + t*8 + g4*2;
            float2 uA = *(const float2*)(Ub + rowA*128 + c0);
            float2 uB = *(const float2*)(Ub + rowB*128 + c0);
            float2 qA = *(const float2*)(qb + rowA*128 + c0);
            float2 qB = *(const float2*)(qb + rowB*128 + c0);
            float2 vA = *(const float2*)(vb + rowA*128 + c0);
            float2 vB = *(const float2*)(vb + rowB*128 + c0);
            float2 kc = *(const float2*)(sk + c0);
            float eA0 = fmaxf((d[t][0]-muA)*rsA, 0.0f) + uA.x;
            float eA1 = fmaxf((d[t][1]-muA)*rsA, 0.0f) + uA.y;
            float eB0 = fmaxf((d[t][2]-muB)*rsB, 0.0f) + uB.x;
            float eB1 = fmaxf((d[t][3]-muB)*rsB, 0.0f) + uB.y;
            sxvT[(c0  )*130 + rowA] = vA.x + eA0;
            sxvT[(c0+1)*130 + rowA] = vA.y + eA1;
            sxvT[(c0  )*130 + rowB] = vB.x + eB0;
            sxvT[(c0+1)*130 + rowB] = vB.y + eB1;
            float rA0 = kc.x - qA.x + eA0;
            float rA1 = kc.y - qA.y + eA1;
            float rB0 = kc.x - qB.x + eB0;
            float rB1 = kc.y - qB.y + eB1;
            d[t][0] = rA0; d[t][1] = rA1; d[t][2] = rB0; d[t][3] = rB1;
            t1A += rA0 + rA1; t2A += rA0*rA0 + rA1*rA1;
            t1B += rB0 + rB1; t2B += rB0*rB0 + rB1*rB1;
        }
        t1A = qsum(t1A); t2A = qsum(t2A); t1B = qsum(t1B); t2B = qsum(t2B);
        if (g4 == 0){
            sp2[ch*128 + rowA] = make_float2(t1A, t2A);
            sp2[ch*128 + rowB] = make_float2(t1B, t2B);
        }
    }
    __syncthreads();                                            // B4
    {
        float2 pA0 = sp2[rowA], pA1 = sp2[128 + rowA];
        float2 pB0 = sp2[rowB], pB1 = sp2[128 + rowB];
        float nuA = (pA0.x + pA1.x)*(1.0f/128.0f);
        float nsA = rsqrtf((pA0.y + pA1.y)*(1.0f/128.0f) - nuA*nuA + 1e-5f);
        float nuB = (pB0.x + pB1.x)*(1.0f/128.0f);
        float nsB = rsqrtf((pB0.y + pB1.y)*(1.0f/128.0f) - nuB*nuB + 1e-5f);
#pragma unroll
        for (int t = 0; t < 8; t++){
            int c0 = cb + t*8 + g4*2;
            float2 gg = *(float2*)(sg1 + c0);
            float2 bb = *(float2*)(sb1v + c0);
            float yA0 = fmaxf(fmaf((d[t][0]-nuA)*nsA, gg.x, bb.x), 0.0f);
            float yA1 = fmaxf(fmaf((d[t][1]-nuA)*nsA, gg.y, bb.y), 0.0f);
            float yB0 = fmaxf(fmaf((d[t][2]-nuB)*nsB, gg.x, bb.x), 0.0f);
            float yB1 = fmaxf(fmaf((d[t][3]-nuB)*nsB, gg.y, bb.y), 0.0f);
            uint32_t hA, lA, hB, lB;
            split2(yA0, yA1, hA, lA);
            split2(yB0, yB1, hB, lB);
            int kb = cb*2 + t*16 + g4*4;
            *(uint32_t*)(sm8 + A_HI_B + swz(rowA, kb)) = hA;
            *(uint32_t*)(sm8 + A_LO_B + swz(rowA, kb)) = lA;
            *(uint32_t*)(sm8 + A_HI_B + swz(rowB, kb)) = hB;
            *(uint32_t*)(sm8 + A_LO_B + swz(rowB, kb)) = lB;
        }
    }
    __syncthreads();                                            // B5

    // ----- GEMM1 -----
    gemm128q(Ah, Al, Wh, Wl, r, cb, lane, d);

    // ----- epi1 -----
    {
        float s1A = 0, s2A = 0, s1B = 0, s2B = 0;
#pragma unroll
        for (int t = 0; t < 8; t++){
            int c0 = cb + t*8 + g4*2;
            float2 bb = *(float2*)(sbi1 + c0);
            d[t][0] += bb.x; d[t][1] += bb.y;
            d[t][2] += bb.x; d[t][3] += bb.y;
            s1A += d[t][0] + d[t][1]; s2A += d[t][0]*d[t][0] + d[t][1]*d[t][1];
            s1B += d[t][2] + d[t][3]; s2B += d[t][2]*d[t][2] + d[t][3]*d[t][3];
        }
        s1A = qsum(s1A); s2A = qsum(s2A); s1B = qsum(s1B); s2B = qsum(s2B);
        if (g4 == 0){
            sp[ch*128 + rowA] = make_float2(s1A, s2A);
            sp[ch*128 + rowB] = make_float2(s1B, s2B);
        }
    }
    __syncthreads();                                            // B6
    {
        float2 pA0 = sp[rowA], pA1 = sp[128 + rowA];
        float2 pB0 = sp[rowB], pB1 = sp[128 + rowB];
        float muA = (pA0.x + pA1.x)*(1.0f/128.0f);
        float rsA = rsqrtf((pA0.y + pA1.y)*(1.0f/128.0f) - muA*muA + 1e-5f);
        float muB = (pB0.x + pB1.x)*(1.0f/128.0f);
        float rsB = rsqrtf((pB0.y + pB1.y)*(1.0f/128.0f) - muB*muB + 1e-5f);
#pragma unroll
        for (int t = 0; t < 8; t++){
            int c0 = cb + t*8 + g4*2;
            float2 gg = *(float2*)(sg2 + c0);
            float2 bb = *(float2*)(sb2v + c0);
            float yA0 = fmaxf(fmaf((d[t][0]-muA)*rsA, gg.x, bb.x), 0.0f);
            float yA1 = fmaxf(fmaf((d[t][1]-muA)*rsA, gg.y, bb.y), 0.0f);
            float yB0 = fmaxf(fmaf((d[t][2]-muB)*rsB, gg.x, bb.x), 0.0f);
            float yB1 = fmaxf(fmaf((d[t][3]-muB)*rsB, gg.y, bb.y), 0.0f);
            uint32_t hA, lA, hB, lB;
            split2(yA0, yA1, hA, lA);
            split2(yB0, yB1, hB, lB);
            int kb = cb*2 + t*16 + g4*4;
            *(uint32_t*)(sm8 + A_HI_B + swz(rowA, kb)) = hA;
            *(uint32_t*)(sm8 + A_LO_B + swz(rowA, kb)) = lA;
            *(uint32_t*)(sm8 + A_HI_B + swz(rowB, kb)) = hB;
            *(uint32_t*)(sm8 + A_LO_B + swz(rowB, kb)) = lB;
        }
    }
    __syncthreads();                                            // B7

    // ----- W2 copy -----
    {
        const uint4* whi = (const uint4*)g_w2hi;
        const uint4* wlo = (const uint4*)g_w2lo;
        uint4* dhi = (uint4*)(sm8 + W_HI_B);
        uint4* dlo = (uint4*)(sm8 + W_LO_B);
#pragma unroll
        for (int t = 0; t < 4; t++){
            dhi[tid + 512*t] = whi[tid + 512*t];
            dlo[tid + 512*t] = wlo[tid + 512*t];
        }
    }
    __syncthreads();                                            // B8

    // ----- GEMM2 transposed: D[c][j] = W2 @ A2^T (pre-scaled by log2e) -----
    gemm128q(Wh, Wl, Ah, Al, r, cb, lane, d);

    // ----- softmax (no max-sub; logits O(1)) + weighted xv sum -----
    {
        float bA = sbi2[rowA], bB = sbi2[rowB];
        float denA = 0, numA = 0, denB = 0, numB = 0;
#pragma unroll
        for (int t = 0; t < 8; t++){
            int jj = cb + t*8 + g4*2;
            float w0 = ex2(d[t][0] + bA), w1 = ex2(d[t][1] + bA);
            float w2 = ex2(d[t][2] + bB), w3 = ex2(d[t][3] + bB);
            float2 xA = *(float2*)(sxvT + rowA*130 + jj);
            float2 xB = *(float2*)(sxvT + rowB*130 + jj);
            denA += w0 + w1; numA += w0*xA.x + w1*xA.y;
            denB += w2 + w3; numB += w2*xB.x + w3*xB.y;
        }
        denA = qsum(denA); numA = qsum(numA);
        denB = qsum(denB); numB = qsum(numB);
        if (g4 == 0){
            sdn[ch*128 + rowA] = make_float2(denA, numA);
            sdn[ch*128 + rowB] = make_float2(denB, numB);
        }
        __syncthreads();                                        // B9
        if (ch == 0 && g4 == 0){
            float2 a0 = sdn[rowA], a1 = sdn[128 + rowA];
            float2 b0 = sdn[rowB], b1 = sdn[128 + rowB];
            float oA = (a0.y + a1.y) / (a0.x + a1.x);
            float oB = (b0.y + b1.y) / (b0.x + b1.x);
            sxo[rowA] = oA; sxo[rowB] = oB;
            xout[(size_t)blockIdx.x*128 + rowA] = oA;
            xout[(size_t)blockIdx.x*128 + rowB] = oB;
        }
    }
    __syncthreads();                                            // B10

    // ----- tail: avec/bvec -----
    if (tid < 64){
        int m = tid & 31, half = tid >> 5;
        const float* er = e1 + m*257 + half*128;
        float a = 0;
#pragma unroll 8
        for (int c2 = 0; c2 < 128; c2++) a = fmaf(sxo[c2], er[c2], a);
        if (half == 0) g_avec[(size_t)blockIdx.x*32 + m] = a;
        else           g_bvec[(size_t)blockIdx.x*32 + m] = a;
    }
}

// ---------------- K3: message MLP + position update ----------------
__global__ void __launch_bounds__(256, 2) k3_msg(
    const float* __restrict__ p, const float* __restrict__ e1,
    const float* __restrict__ x1b, const float* __restrict__ x2,
    const float* __restrict__ x2b,
    float* __restrict__ outp)
{
    extern __shared__ char sm8[];
    float* spij  = (float*)(sm8 + K3_SPIJ);
    float* snorm = (float*)(sm8 + K3_SNORM);
    float* ss    = (float*)(sm8 + K3_SS);
    float* spad  = (float*)(sm8 + K3_SPAD);
    float* sa    = (float*)(sm8 + K3_SA);
    float* se1c  = (float*)(sm8 + K3_SE1C);
    float* sx1b_ = (float*)(sm8 + K3_SX1B);
    float* sx2v  = (float*)(sm8 + K3_SX2V);

    const uint32_t sbase = smem_u32(sm8);
    const int tid = threadIdx.x, lane = tid & 31, warp = tid >> 5;
    const int n = blockIdx.x >> 7, i = blockIdx.x & 127;
    const bool pad_i = (p[(size_t)(n*128 + i)*4] == 0.0f);

    // pad rows: output is exactly 0 (p_i == 0 elementwise)
    if (pad_i){
        if (tid == 0)
            *(float4*)(outp + (size_t)(n*128 + i)*4) = make_float4(0.f, 0.f, 0.f, 0.f);
        return;
    }

    const int g4 = lane & 3;
    const int rowA = warp*16 + (lane>>2), rowB = rowA + 8;

    if (tid < 128){
        int j = tid;
        float4 pi = *(const float4*)(p + (size_t)(n*128 + i)*4);
        float4 pj = *(const float4*)(p + (size_t)(n*128 + j)*4);
        float dx = pi.x - pj.x, dy = pi.y - pj.y, dz = pi.z - pj.z, dw = pi.w - pj.w;
        spij[j*4+0] = dx; spij[j*4+1] = dy; spij[j*4+2] = dz; spij[j*4+3] = dw;
        spad[j] = (pj.x != 0.0f) ? 1.0f : 0.0f;
        snorm[j] = dw*dw - dx*dx - dy*dy - dz*dz;
    }
    if (tid < 32){
        sa[tid]    = g_avec[(size_t)(n*128 + i)*32 + tid];
        se1c[tid]  = e1[tid*257 + 256];
        sx1b_[tid] = x1b[tid];
        sx2v[tid]  = x2[tid];
    }
    for (int t = tid; t < 2560; t += 256){
        ((uint32_t*)(sm8 + K3_B1H))[t] = g_e2hi[t];
        ((uint32_t*)(sm8 + K3_B1L))[t] = g_e2lo[t];
    }
    for (int t = tid; t < 2048; t += 256){
        ((uint32_t*)(sm8 + K3_B2H))[t] = g_x1hi[t];
        ((uint32_t*)(sm8 + K3_B2L))[t] = g_x1lo[t];
    }
    __syncthreads();

    // h32 tile
    const float* bv = g_bvec + (size_t)n*4096;
    for (int idx = tid; idx < 2048; idx += 256){
        int row = idx >> 4, mp = idx & 15, m = mp*2;
        float nb = snorm[row];
        float2 bb = *(const float2*)(bv + row*32 + m);
        float h0 = fmaxf(sa[m]   + bb.x + nb*se1c[m],   0.0f);
        float h1 = fmaxf(sa[m+1] + bb.y + nb*se1c[m+1], 0.0f);
        uint32_t hi, lo;
        split2(h0, h1, hi, lo);
        *(uint32_t*)(sm8 + K3_A1H + row*80 + mp*4) = hi;
        *(uint32_t*)(sm8 + K3_A1L + row*80 + mp*4) = lo;
    }
    __syncthreads();

    // MMA1: mij_pre = h32 @ e2^T
    float d[16][4];
    gemm32(sbase + K3_A1H, sbase + K3_A1L, sbase + K3_B1H, sbase + K3_B1L, warp, lane, d);

    // relu -> LN (registers; no masking needed, i non-pad)
    {
        float s1A = 0, s2A = 0, s1B = 0, s2B = 0;
#pragma unroll
        for (int t = 0; t < 16; t++){
            float a0 = fmaxf(d[t][0], 0.0f), a1 = fmaxf(d[t][1], 0.0f);
            float b0 = fmaxf(d[t][2], 0.0f), b1 = fmaxf(d[t][3], 0.0f);
            d[t][0] = a0; d[t][1] = a1; d[t][2] = b0; d[t][3] = b1;
            s1A += a0 + a1; s2A += a0*a0 + a1*a1;
            s1B += b0 + b1; s2B += b0*b0 + b1*b1;
        }
        s1A = qsum(s1A); s2A = qsum(s2A); s1B = qsum(s1B); s2B = qsum(s2B);
        float muA = s1A*(1.0f/128.0f), vA = s2A*(1.0f/128.0f) - muA*muA;
        float muB = s1B*(1.0f/128.0f), vB = s2B*(1.0f/128.0f) - muB*muB;
        float rsA = rsqrtf(fmaxf(vA, 0.0f) + 1e-5f);
        float rsB = rsqrtf(fmaxf(vB, 0.0f) + 1e-5f);
#pragma unroll
        for (int t = 0; t < 16; t++){
            d[t][0] = (d[t][0]-muA)*rsA; d[t][1] = (d[t][1]-muA)*rsA;
            d[t][2] = (d[t][2]-muB)*rsB; d[t][3] = (d[t][3]-muB)*rsB;
        }
    }

    // MMA2: t_pre = y @ x1^T, A from registers
    float d2[4][4];
    mma2_regA(d, sbase + K3_B2H, sbase + K3_B2L, lane, d2);

    // scores
    {
        float x2bv = x2b[0];
        float sA = 0, sB = 0;
#pragma unroll
        for (int t = 0; t < 4; t++){
            int c0 = t*8 + g4*2;
            float2 xb = *(float2*)(sx1b_ + c0);
            float2 xv = *(float2*)(sx2v + c0);
            sA += fmaxf(d2[t][0] + xb.x, 0.0f)*xv.x + fmaxf(d2[t][1] + xb.y, 0.0f)*xv.y;
            sB += fmaxf(d2[t][2] + xb.x, 0.0f)*xv.x + fmaxf(d2[t][3] + xb.y, 0.0f)*xv.y;
        }
        sA = qsum(sA); sB = qsum(sB);
        if (g4 == 0){
            ss[rowA] = fmaxf(sA + x2bv, 0.0f);
            ss[rowB] = fmaxf(sB + x2bv, 0.0f);
        }
    }
    __syncthreads();

    if (warp == 0){
        float m0 = fmaxf(fmaxf(ss[lane], ss[lane+32]), fmaxf(ss[lane+64], ss[lane+96]));
#pragma unroll
        for (int k = 16; k > 0; k >>= 1) m0 = fmaxf(m0, __shfl_xor_sync(0xffffffffu, m0, k));
        float den = 0, dx = 0, dy = 0, dz = 0, dw = 0, cnt = 0;
#pragma unroll
        for (int q2 = 0; q2 < 4; q2++){
            int b = lane + 32*q2;
            float w = __expf(ss[b] - m0);
            den += w;
            dx = fmaf(w, spij[b*4+0], dx);
            dy = fmaf(w, spij[b*4+1], dy);
            dz = fmaf(w, spij[b*4+2], dz);
            dw = fmaf(w, spij[b*4+3], dw);
            cnt += spad[b];
        }
        den = wsum(den); dx = wsum(dx); dy = wsum(dy);
        dz = wsum(dz);   dw = wsum(dw); cnt = wsum(cnt);
        if (lane == 0){
            float inv = 1.0f / (den * cnt);
            const float* pr = p + (size_t)(n*128 + i)*4;
            float* o = outp + (size_t)(n*128 + i)*4;
            float d4[4] = {dx, dy, dz, dw};
#pragma unroll
            for (int dd = 0; dd < 4; dd++){
                float pv = pr[dd];
                o[dd] = (pv == 0.0f) ? 0.0f : pv + d4[dd]*inv;
            }
        }
    }
}

extern "C" void kernel_launch(void* const* d_in, const int* in_sizes, int n_in,
                              void* d_out, int out_size){
    const float* x     = (const float*)d_in[0];
    const float* p     = (const float*)d_in[1];
    const float* U     = (const float*)d_in[2];
    const float* wq    = (const float*)d_in[3];
    const float* bq    = (const float*)d_in[4];
    const float* wk    = (const float*)d_in[5];
    const float* bk    = (const float*)d_in[6];
    const float* wv    = (const float*)d_in[7];
    const float* bv    = (const float*)d_in[8];
    const float* ln1_g = (const float*)d_in[9];
    const float* ln1_b = (const float*)d_in[10];
    const float* w1    = (const float*)d_in[11];
    const float* b1    = (const float*)d_in[12];
    const float* ln2_g = (const float*)d_in[13];
    const float* ln2_b = (const float*)d_in[14];
    const float* w2    = (const float*)d_in[15];
    const float* b2    = (const float*)d_in[16];
    const float* pe1   = (const float*)d_in[17];
    const float* pe2   = (const float*)d_in[18];
    const float* e1    = (const float*)d_in[19];
    const float* e2    = (const float*)d_in[20];
    const float* x1    = (const float*)d_in[21];
    const float* x1b   = (const float*)d_in[22];
    const float* x2    = (const float*)d_in[23];
    const float* x2b   = (const float*)d_in[24];
    float* out  = (float*)d_out;
    float* xout = out;                 // (16,128,128)
    float* newp = out + 16*128*128;    // (16,128,4)

    cudaFuncSetAttribute(k2_attn, cudaFuncAttributeMaxDynamicSharedMemorySize, K2_SMEM);
    cudaFuncSetAttribute(k3_msg,  cudaFuncAttributeMaxDynamicSharedMemorySize, K3_SMEM);

    k0_prep<<<64, 256>>>(wq, wk, wv, w1, w2, pe2, e2, x1);
    k1_qkv<<<2048, 128>>>(x, bq, bk, bv);
    k2_attn<<<2048, 512, K2_SMEM>>>(U, p, ln1_g, ln1_b, b1, ln2_g, ln2_b, b2, pe1, e1, xout);
    k3_msg<<<2048, 256, K3_SMEM>>>(p, e1, x1b, x2, x2b, newp);
}

// round 9
// speedup vs baseline: 3.6010x; 1.1374x over previous
#include <cuda_runtime.h>
#include <cuda_bf16.h>
#include <math.h>
#include <stdint.h>

#define NEGV (-10000.0f)
#define LOG2E 1.44269504088896340736f

// ---------------- K2 smem byte offsets (512-thread version) ----------------
#define XVT_B    0          // fp32 xvT [128][130] (66560B); pe2/tn tiles alias front
#define PE2H_B   0
#define PE2L_B   10240
#define TNH_B    20480
#define TNL_B    30720
#define A_HI_B   67584      // bf16 A tile (XOR swizzle, 32KB each)
#define A_LO_B   100352
#define W_HI_B   133120     // bf16 W tile: w1 -> w2
#define W_LO_B   165888
#define SK_B     198656
#define SG1_B    199168
#define SB1_B    199680
#define SG2_B    200192
#define SB2_B    200704
#define SBI1_B   201216
#define SBI2_B   201728
#define SPE1_B   202240
#define SPIJ_B   202752     // 2048
#define SXO_B    204800     // 512
#define SP_B     205312     // 2048: [ch][row] float2 partials / tail partials
#define SP2_B    207360     // 2048
#define SDN_B    209408     // 2048: [ch][c] float2
#define K2_SMEM  211456

// ---------------- K3 smem byte offsets ----------------
#define K3_A1H   0
#define K3_A1L   10240
#define K3_B1H   20480
#define K3_B1L   30720
#define K3_B2H   40960
#define K3_B2L   49152
#define K3_SPIJ  57344      // 2048
#define K3_SNORM 59392      // 512
#define K3_SS    59904      // 512
#define K3_SPAD  60416      // 512
#define K3_SA    60928      // 128
#define K3_SE1C  61056      // 128
#define K3_SX1B  61184      // 128
#define K3_SX2V  61312      // 128
#define K3_SMEM  61440

// ---------------- device scratch ----------------
__device__ float g_q[16*128*128];
__device__ float g_k[16*128*128];
__device__ float g_v[16*128*128];
__device__ float g_wqT[64*128];
__device__ float g_wkT[64*128];
__device__ float g_wvT[64*128];
__device__ float g_avec[16*128*32];
__device__ float g_bvec[16*128*32];
__device__ uint32_t g_w1hi[8192];
__device__ uint32_t g_w1lo[8192];
__device__ uint32_t g_w2hi[8192];
__device__ uint32_t g_w2lo[8192];
__device__ uint32_t g_x1hi[2048];
__device__ uint32_t g_x1lo[2048];
__device__ uint32_t g_pe2hi[2560];
__device__ uint32_t g_pe2lo[2560];
__device__ uint32_t g_e2hi[2560];
__device__ uint32_t g_e2lo[2560];

// ---------------- helpers ----------------
__device__ __forceinline__ float wsum(float v){
#pragma unroll
    for (int k = 16; k > 0; k >>= 1) v += __shfl_xor_sync(0xffffffffu, v, k);
    return v;
}
__device__ __forceinline__ float qsum(float v){
    v += __shfl_xor_sync(0xffffffffu, v, 1);
    v += __shfl_xor_sync(0xffffffffu, v, 2);
    return v;
}
__device__ __forceinline__ uint32_t smem_u32(const void* p){
    uint32_t a;
    asm("{ .reg .u64 t; cvta.to.shared.u64 t, %1; cvt.u32.u64 %0, t; }" : "=r"(a) : "l"(p));
    return a;
}
__device__ __forceinline__ uint32_t swz(int row, int kb){
    return (uint32_t)(row*256 + ((kb & 0xF0) ^ ((row & 7) << 4)) + (kb & 15));
}
__device__ __forceinline__ float ex2(float x){
    float r; asm("ex2.approx.ftz.f32 %0, %1;" : "=f"(r) : "f"(x)); return r;
}
// pairwise named barrier: 2 warps (64 threads), id in 1..8
__device__ __forceinline__ void barp(int id){
    asm volatile("bar.sync %0, 64;" :: "r"(id) : "memory");
}
// fast hi/lo bf16 split: low halfword = x, high halfword = y
__device__ __forceinline__ void split2(float x, float y, uint32_t &hi, uint32_t &lo){
    uint32_t h;
    asm("cvt.rn.bf16x2.f32 %0, %1, %2;" : "=r"(h) : "f"(y), "f"(x));
    float xh = __uint_as_float(h << 16);
    float yh = __uint_as_float(h & 0xFFFF0000u);
    asm("cvt.rn.bf16x2.f32 %0, %1, %2;" : "=r"(lo) : "f"(y - yh), "f"(x - xh));
    hi = h;
}
__device__ __forceinline__ void ldsm4(uint32_t a[4], uint32_t addr){
    asm volatile("ldmatrix.sync.aligned.m8n8.x4.shared.b16 {%0,%1,%2,%3}, [%4];"
        : "=r"(a[0]), "=r"(a[1]), "=r"(a[2]), "=r"(a[3]) : "r"(addr));
}
__device__ __forceinline__ void mma16816(float d[4], const uint32_t a[4], const uint32_t b[2]){
    asm volatile("mma.sync.aligned.m16n8k16.row.col.f32.bf16.bf16.f32 "
        "{%0,%1,%2,%3}, {%4,%5,%6,%7}, {%8,%9}, {%0,%1,%2,%3};"
        : "+f"(d[0]), "+f"(d[1]), "+f"(d[2]), "+f"(d[3])
        : "r"(a[0]), "r"(a[1]), "r"(a[2]), "r"(a[3]), "r"(b[0]), "r"(b[1]));
}

// K2 quadrant GEMM: A rows r*16..+15, B rows cb..cb+63, K=128, XOR tiles.
__device__ __forceinline__ void gemm128q(uint32_t Ah, uint32_t Al, uint32_t Bh, uint32_t Bl,
                                         int r, int cb, int lane, float d[8][4]){
#pragma unroll
    for (int t = 0; t < 8; t++){ d[t][0]=0.f; d[t][1]=0.f; d[t][2]=0.f; d[t][3]=0.f; }
    const uint32_t aro = (uint32_t)((r*16 + (lane&15))*256);
    const uint32_t aox = (uint32_t)((lane&7)<<4);
    const uint32_t akx = (uint32_t)(lane&16);
    const uint32_t bro = (uint32_t)((cb + (lane&7) + ((lane>>4)<<3))*256);
    const uint32_t bkx = (uint32_t)((lane&8)<<1);
#pragma unroll 1
    for (int kk = 0; kk < 8; kk++){
        uint32_t ka = (uint32_t)(kk*32);
        uint32_t ah[4], al_[4];
        ldsm4(ah,  Ah + aro + ((ka + akx) ^ aox));
        ldsm4(al_, Al + aro + ((ka + akx) ^ aox));
        uint32_t bo = bro + ((ka + bkx) ^ aox);
#pragma unroll
        for (int t2 = 0; t2 < 4; t2++){
            uint32_t bh[4], bl[4];
            ldsm4(bh, Bh + bo + (uint32_t)(t2*4096));
            ldsm4(bl, Bl + bo + (uint32_t)(t2*4096));
            mma16816(d[2*t2],   ah,  bh);
            mma16816(d[2*t2],   ah,  bl);
            mma16816(d[2*t2],   al_, bh);
            mma16816(d[2*t2+1], ah,  bh+2);
            mma16816(d[2*t2+1], ah,  bl+2);
            mma16816(d[2*t2+1], al_, bh+2);
        }
    }
}

// K2 quadrant small-K GEMM: K=32, 80B-stride tiles.
__device__ __forceinline__ void gemm32q(uint32_t Ah, uint32_t Al, uint32_t Bh, uint32_t Bl,
                                        int r, int cb, int lane, float d[8][4]){
#pragma unroll
    for (int t = 0; t < 8; t++){ d[t][0]=0.f; d[t][1]=0.f; d[t][2]=0.f; d[t][3]=0.f; }
    const uint32_t aro = (uint32_t)((r*16 + (lane&15))*80 + (lane&16));
    const uint32_t bro = (uint32_t)((cb + (lane&7) + ((lane>>4)<<3))*80 + ((lane&8)<<1));
#pragma unroll
    for (int kk = 0; kk < 2; kk++){
        uint32_t ah[4], al_[4];
        ldsm4(ah,  Ah + aro + (uint32_t)(kk*32));
        ldsm4(al_, Al + aro + (uint32_t)(kk*32));
#pragma unroll
        for (int t2 = 0; t2 < 4; t2++){
            uint32_t bh[4], bl[4];
            ldsm4(bh, Bh + bro + (uint32_t)(kk*32 + t2*1280));
            ldsm4(bl, Bl + bro + (uint32_t)(kk*32 + t2*1280));
            mma16816(d[2*t2],   ah,  bh);
            mma16816(d[2*t2],   ah,  bl);
            mma16816(d[2*t2],   al_, bh);
            mma16816(d[2*t2+1], ah,  bh+2);
            mma16816(d[2*t2+1], ah,  bl+2);
            mma16816(d[2*t2+1], al_, bh+2);
        }
    }
}

// K3 full-width K=32 GEMM (8 warps, 16 rows each, all 128 cols)
__device__ __forceinline__ void gemm32(uint32_t Ah, uint32_t Al, uint32_t Bh, uint32_t Bl,
                                       int warp, int lane, float d[16][4]){
#pragma unroll
    for (int t = 0; t < 16; t++){ d[t][0]=0.f; d[t][1]=0.f; d[t][2]=0.f; d[t][3]=0.f; }
    const uint32_t aro = (uint32_t)((warp*16 + (lane&15))*80 + (lane&16));
    const uint32_t bro = (uint32_t)(((lane&7) + ((lane>>4)<<3))*80 + ((lane&8)<<1));
#pragma unroll
    for (int kk = 0; kk < 2; kk++){
        uint32_t ah[4], al_[4];
        ldsm4(ah,  Ah + aro + (uint32_t)(kk*32));
        ldsm4(al_, Al + aro + (uint32_t)(kk*32));
#pragma unroll
        for (int t2 = 0; t2 < 8; t2++){
            uint32_t bh[4], bl[4];
            ldsm4(bh, Bh + bro + (uint32_t)(kk*32 + t2*1280));
            ldsm4(bl, Bl + bro + (uint32_t)(kk*32 + t2*1280));
            mma16816(d[2*t2],   ah,  bh);
            mma16816(d[2*t2],   ah,  bl);
            mma16816(d[2*t2],   al_, bh);
            mma16816(d[2*t2+1], ah,  bh+2);
            mma16816(d[2*t2+1], ah,  bl+2);
            mma16816(d[2*t2+1], al_, bh+2);
        }
    }
}

// K3 MMA2 with A from registers (y in C-fragment layout), B = x1 tile (32 rows, XOR)
__device__ __forceinline__ void mma2_regA(const float y[16][4], uint32_t Bh, uint32_t Bl,
                                          int lane, float d2[4][4]){
#pragma unroll
    for (int t = 0; t < 4; t++){ d2[t][0]=0.f; d2[t][1]=0.f; d2[t][2]=0.f; d2[t][3]=0.f; }
    const uint32_t aox = (uint32_t)((lane&7)<<4);
    const uint32_t bro = (uint32_t)(((lane&7) + ((lane>>4)<<3))*256);
    const uint32_t bkx = (uint32_t)((lane&8)<<1);
#pragma unroll
    for (int kt = 0; kt < 8; kt++){
        uint32_t ah[4], al_[4];
        split2(y[2*kt][0],   y[2*kt][1],   ah[0], al_[0]);
        split2(y[2*kt][2],   y[2*kt][3],   ah[1], al_[1]);
        split2(y[2*kt+1][0], y[2*kt+1][1], ah[2], al_[2]);
        split2(y[2*kt+1][2], y[2*kt+1][3], ah[3], al_[3]);
        uint32_t bo = bro + (((uint32_t)(kt*32) + bkx) ^ aox);
#pragma unroll
        for (int t2 = 0; t2 < 2; t2++){
            uint32_t bh[4], bl[4];
            ldsm4(bh, Bh + bo + (uint32_t)(t2*4096));
            ldsm4(bl, Bl + bo + (uint32_t)(t2*4096));
            mma16816(d2[2*t2],   ah,  bh);
            mma16816(d2[2*t2],   ah,  bl);
            mma16816(d2[2*t2],   al_, bh);
            mma16816(d2[2*t2+1], ah,  bh+2);
            mma16816(d2[2*t2+1], ah,  bl+2);
            mma16816(d2[2*t2+1], al_, bh+2);
        }
    }
}

// ---------------- K0: weight prep ----------------
__global__ void k0_prep(const float* __restrict__ wq, const float* __restrict__ wk,
                        const float* __restrict__ wv, const float* __restrict__ w1,
                        const float* __restrict__ w2, const float* __restrict__ pe2,
                        const float* __restrict__ e2, const float* __restrict__ x1){
    int idx = blockIdx.x * blockDim.x + threadIdx.x;
    int stride = gridDim.x * blockDim.x;
    for (int t = idx; t < 16384; t += stride){
        int c = t >> 7, m = t & 127;
        uint32_t a = swz(c, m*2) >> 1;
        float v1 = w1[t];
        __nv_bfloat16 h1 = __float2bfloat16(v1);
        ((unsigned short*)g_w1hi)[a] = __bfloat16_as_ushort(h1);
        ((unsigned short*)g_w1lo)[a] = __bfloat16_as_ushort(__float2bfloat16(v1 - __bfloat162float(h1)));
        float v2 = w2[t] * LOG2E;   // pre-scale for ex2 softmax
        __nv_bfloat16 h2 = __float2bfloat16(v2);
        ((unsigned short*)g_w2hi)[a] = __bfloat16_as_ushort(h2);
        ((unsigned short*)g_w2lo)[a] = __bfloat16_as_ushort(__float2bfloat16(v2 - __bfloat162float(h2)));
    }
    for (int t = idx; t < 4096; t += stride){
        int c = t >> 5, m = t & 31;
        uint32_t a80 = (uint32_t)(c*40 + m);
        float vp = pe2[t];
        __nv_bfloat16 hp = __float2bfloat16(vp);
        ((unsigned short*)g_pe2hi)[a80] = __bfloat16_as_ushort(hp);
        ((unsigned short*)g_pe2lo)[a80] = __bfloat16_as_ushort(__float2bfloat16(vp - __bfloat162float(hp)));
        float ve = e2[t];
        __nv_bfloat16 he = __float2bfloat16(ve);
        ((unsigned short*)g_e2hi)[a80] = __bfloat16_as_ushort(he);
        ((unsigned short*)g_e2lo)[a80] = __bfloat16_as_ushort(__float2bfloat16(ve - __bfloat162float(he)));
        int m2 = t >> 7, c2 = t & 127;
        uint32_t ax = swz(m2, c2*2) >> 1;
        float vx = x1[t];
        __nv_bfloat16 hx = __float2bfloat16(vx);
        ((unsigned short*)g_x1hi)[ax] = __bfloat16_as_ushort(hx);
        ((unsigned short*)g_x1lo)[ax] = __bfloat16_as_ushort(__float2bfloat16(vx - __bfloat162float(hx)));
    }
    for (int t = idx; t < 8192; t += stride){
        int c = t >> 6, d = t & 63;
        g_wqT[d*128 + c] = wq[t];
        g_wkT[d*128 + c] = wk[t];
        g_wvT[d*128 + c] = wv[t];
    }
}

// ---------------- K1: q,k,v projections ----------------
__global__ void __launch_bounds__(128) k1_qkv(const float* __restrict__ x,
                                              const float* __restrict__ bq,
                                              const float* __restrict__ bk,
                                              const float* __restrict__ bv){
    __shared__ float sx[64];
    int row = blockIdx.x;
    int c = threadIdx.x;
    if (c < 64) sx[c] = x[(size_t)row*64 + c];
    __syncthreads();
    float aq = bq[c], ak = bk[c], av = bv[c];
#pragma unroll 8
    for (int d = 0; d < 64; d++){
        float xv = sx[d];
        aq = fmaf(xv, g_wqT[d*128 + c], aq);
        ak = fmaf(xv, g_wkT[d*128 + c], ak);
        av = fmaf(xv, g_wvT[d*128 + c], av);
    }
    g_q[(size_t)row*128 + c] = aq;
    g_k[(size_t)row*128 + c] = ak;
    g_v[(size_t)row*128 + c] = av;
}

// ---------------- K2: fused attention per (n,i), 512 threads, pairwise barriers ----------------
__global__ void __launch_bounds__(512) k2_attn(
    const float* __restrict__ U, const float* __restrict__ p,
    const float* __restrict__ ln1_g, const float* __restrict__ ln1_b,
    const float* __restrict__ b1,
    const float* __restrict__ ln2_g, const float* __restrict__ ln2_b,
    const float* __restrict__ b2,
    const float* __restrict__ pe1, const float* __restrict__ e1,
    float* __restrict__ xout)
{
    extern __shared__ char sm8[];
    float*  sxvT = (float*)(sm8 + XVT_B);     // [c][j] stride 130
    float*  sk   = (float*)(sm8 + SK_B);
    float*  sg1  = (float*)(sm8 + SG1_B);
    float*  sb1v = (float*)(sm8 + SB1_B);
    float*  sg2  = (float*)(sm8 + SG2_B);
    float*  sb2v = (float*)(sm8 + SB2_B);
    float*  sbi1 = (float*)(sm8 + SBI1_B);
    float*  sbi2 = (float*)(sm8 + SBI2_B);
    float*  spe1 = (float*)(sm8 + SPE1_B);
    float*  spij = (float*)(sm8 + SPIJ_B);
    float*  sxo  = (float*)(sm8 + SXO_B);
    float2* sp   = (float2*)(sm8 + SP_B);
    float*  spart= (float*)(sm8 + SP_B);      // tail partials (aliases sp, dead by then)
    float2* sp2  = (float2*)(sm8 + SP2_B);
    float2* sdn  = (float2*)(sm8 + SDN_B);

    const uint32_t sbase = smem_u32(sm8);
    const uint32_t Ah = sbase + A_HI_B, Al = sbase + A_LO_B;
    const uint32_t Wh = sbase + W_HI_B, Wl = sbase + W_LO_B;
    const int tid = threadIdx.x;
    const int lane = tid & 31, warp = tid >> 5;
    const int r = warp & 7, ch = warp >> 3;
    const int cb = ch*64;
    const int bid = r + 1;            // pairwise barrier id 1..8
    const int n = blockIdx.x >> 7, i = blockIdx.x & 127;
    const int g4 = lane & 3;
    const int rowA = r*16 + (lane>>2), rowB = rowA + 8;

    const float* Ub = U + (size_t)blockIdx.x * 16384;
    // prefetch this CTA's U slice into L2 (64KB, 128B per thread)
    asm volatile("prefetch.global.L2 [%0];" :: "l"(Ub + (tid << 5)));

    // ----- stage 0 -----
    if (tid < 128){
        size_t rowk = (size_t)(n*128 + i);
        sk[tid]   = g_k[rowk*128 + tid];
        sg1[tid]  = ln1_g[tid];  sb1v[tid] = ln1_b[tid];
        sg2[tid]  = ln2_g[tid];  sb2v[tid] = ln2_b[tid];
        sbi1[tid] = b1[tid];     sbi2[tid] = b2[tid] * LOG2E;
        spe1[tid] = pe1[tid];
        int j = tid;
        float4 pi = *(const float4*)(p + (size_t)(n*128 + i)*4);
        float4 pj = *(const float4*)(p + (size_t)(n*128 + j)*4);
        spij[j*4+0] = pi.x - pj.x;
        spij[j*4+1] = pi.y - pj.y;
        spij[j*4+2] = pi.z - pj.z;
        spij[j*4+3] = pi.w - pj.w;
    }
    for (int t = tid; t < 2560; t += 512){
        ((uint32_t*)(sm8 + PE2H_B))[t] = g_pe2hi[t];
        ((uint32_t*)(sm8 + PE2L_B))[t] = g_pe2lo[t];
    }
    {
        const uint4* whi = (const uint4*)g_w1hi;
        const uint4* wlo = (const uint4*)g_w1lo;
        uint4* dhi = (uint4*)(sm8 + W_HI_B);
        uint4* dlo = (uint4*)(sm8 + W_LO_B);
#pragma unroll
        for (int t = 0; t < 4; t++){
            dhi[tid + 512*t] = whi[tid + 512*t];
            dlo[tid + 512*t] = wlo[tid + 512*t];
        }
    }
    const bool pad_i = (p[(size_t)(n*128 + i)*4] == 0.0f);
    __syncthreads();                                            // FULL B1

    // ----- tn: pair-owned rows r*16+ch*8 .. +7; one-pass LN32 -----
    {
        float4 pe1r = ((const float4*)spe1)[lane];
#pragma unroll 1
        for (int rr = 0; rr < 8; rr++){
            int jj = r*16 + ch*8 + rr;
            float4 pd = *(const float4*)(spij + jj*4);
            float t = pd.x*pe1r.x + pd.y*pe1r.y + pd.z*pe1r.z + pd.w*pe1r.w;
            float s1 = t, s2v = t*t;
#pragma unroll
            for (int k = 16; k > 0; k >>= 1){
                s1  += __shfl_xor_sync(0xffffffffu, s1,  k);
                s2v += __shfl_xor_sync(0xffffffffu, s2v, k);
            }
            float mu = s1 * (1.0f/32.0f);
            float var = fmaxf(s2v*(1.0f/32.0f) - mu*mu, 0.0f);
            float tn = fmaxf((t - mu) * rsqrtf(var + 1e-5f), 0.0f);
            float tn1 = __shfl_down_sync(0xffffffffu, tn, 1);
            if (!(lane & 1)){
                uint32_t hi, lo;
                split2(tn, tn1, hi, lo);
                *(uint32_t*)(sm8 + TNH_B + jj*80 + lane*2) = hi;
                *(uint32_t*)(sm8 + TNL_B + jj*80 + lane*2) = lo;
            }
        }
    }
    barp(bid);                                                  // pair B2

    // ----- GEMM0: eqpe_pre -----
    float d[8][4];
    gemm32q(sbase + TNH_B, sbase + TNL_B, sbase + PE2H_B, sbase + PE2L_B, r, cb, lane, d);

    // ----- epi0 stats -----
    {
        float s1A = 0, s2A = 0, s1B = 0, s2B = 0;
#pragma unroll
        for (int t = 0; t < 8; t++){
            s1A += d[t][0] + d[t][1]; s2A += d[t][0]*d[t][0] + d[t][1]*d[t][1];
            s1B += d[t][2] + d[t][3]; s2B += d[t][2]*d[t][2] + d[t][3]*d[t][3];
        }
        s1A = qsum(s1A); s2A = qsum(s2A); s1B = qsum(s1B); s2B = qsum(s2B);
        if (g4 == 0){
            sp[ch*128 + rowA] = make_float2(s1A, s2A);
            sp[ch*128 + rowB] = make_float2(s1B, s2B);
        }
    }
    barp(bid);                                                  // pair B3

    const float* vb = g_v + (size_t)n*16384;

    if (pad_i){
        // ---- pad short-circuit: x_out = mean_j(xv) ----
        float2 pA0 = sp[rowA], pA1 = sp[128 + rowA];
        float2 pB0 = sp[rowB], pB1 = sp[128 + rowB];
        float muA = (pA0.x + pA1.x)*(1.0f/128.0f);
        float rsA = rsqrtf((pA0.y + pA1.y)*(1.0f/128.0f) - muA*muA + 1e-5f);
        float muB = (pB0.x + pB1.x)*(1.0f/128.0f);
        float rsB = rsqrtf((pB0.y + pB1.y)*(1.0f/128.0f) - muB*muB + 1e-5f);
#pragma unroll
        for (int t = 0; t < 8; t++){
            int c0 = cb + t*8 + g4*2;
            float2 uA = *(const float2*)(Ub + rowA*128 + c0);
            float2 uB = *(const float2*)(Ub + rowB*128 + c0);
            float2 vA = *(const float2*)(vb + rowA*128 + c0);
            float2 vB = *(const float2*)(vb + rowB*128 + c0);
            sxvT[(c0  )*130 + rowA] = vA.x + fmaxf((d[t][0]-muA)*rsA, 0.0f) + uA.x;
            sxvT[(c0+1)*130 + rowA] = vA.y + fmaxf((d[t][1]-muA)*rsA, 0.0f) + uA.y;
            sxvT[(c0  )*130 + rowB] = vB.x + fmaxf((d[t][2]-muB)*rsB, 0.0f) + uB.x;
            sxvT[(c0+1)*130 + rowB] = vB.y + fmaxf((d[t][3]-muB)*rsB, 0.0f) + uB.y;
        }
        __syncthreads();
        if (tid < 128){
            float s = 0.0f;
            const float* row = sxvT + tid*130;
#pragma unroll 8
            for (int j = 0; j < 128; j++) s += row[j];
            float o = s * (1.0f/128.0f);
            sxo[tid] = o;
            xout[(size_t)blockIdx.x*128 + tid] = o;
        }
        __syncthreads();
        // tail spread over 512 threads
        {
            int m = tid & 31, half = (tid>>5)&1, q = tid>>6;
            const float* er = e1 + m*257 + half*128 + q*16;
            const float* xo = sxo + q*16;
            float a = 0;
#pragma unroll
            for (int c2 = 0; c2 < 16; c2++) a = fmaf(xo[c2], er[c2], a);
            spart[(half*32 + m)*8 + q] = a;
        }
        __syncthreads();
        if (tid < 64){
            float a = 0;
#pragma unroll
            for (int q = 0; q < 8; q++) a += spart[tid*8 + q];
            if (tid < 32) g_avec[(size_t)blockIdx.x*32 + tid] = a;
            else          g_bvec[(size_t)blockIdx.x*32 + (tid-32)] = a;
        }
        return;
    }

    // ----- non-pad: full epi0 -----
    {
        float2 pA0 = sp[rowA], pA1 = sp[128 + rowA];
        float2 pB0 = sp[rowB], pB1 = sp[128 + rowB];
        float muA = (pA0.x + pA1.x)*(1.0f/128.0f);
        float rsA = rsqrtf((pA0.y + pA1.y)*(1.0f/128.0f) - muA*muA + 1e-5f);
        float muB = (pB0.x + pB1.x)*(1.0f/128.0f);
        float rsB = rsqrtf((pB0.y + pB1.y)*(1.0f/128.0f) - muB*muB + 1e-5f);

        const float* qb = g_q + (size_t)n*16384;
        float t1A = 0, t2A = 0, t1B = 0, t2B = 0;
#pragma unroll
        for (int t = 0; t < 8; t++){
            int c0 = cb + t*8 + g4*2;
            float2 uA = *(const float2*)(Ub + rowA*128 + c0);
            float2 uB = *(const float2*)(Ub + rowB*128 + c0);
            float2 qA = *(const float2*)(qb + rowA*128 + c0);
            float2 qB = *(const float2*)(qb + rowB*128 + c0);
            float2 vA = *(const float2*)(vb + rowA*128 + c0);
            float2 vB = *(const float2*)(vb + rowB*128 + c0);
            float2 kc = *(const float2*)(sk + c0);
            float eA0 = fmaxf((d[t][0]-muA)*rsA, 0.0f) + uA.x;
            float eA1 = fmaxf((d[t][1]-muA)*rsA, 0.0f) + uA.y;
            float eB0 = fmaxf((d[t][2]-muB)*rsB, 0.0f) + uB.x;
            float eB1 = fmaxf((d[t][3]-muB)*rsB, 0.0f) + uB.y;
            sxvT[(c0  )*130 + rowA] = vA.x + eA0;
            sxvT[(c0+1)*130 + rowA] = vA.y + eA1;
            sxvT[(c0  )*130 + rowB] = vB.x + eB0;
            sxvT[(c0+1)*130 + rowB] = vB.y + eB1;
            float rA0 = kc.x - qA.x + eA0;
            float rA1 = kc.y - qA.y + eA1;
            float rB0 = kc.x - qB.x + eB0;
            float rB1 = kc.y - qB.y + eB1;
            d[t][0] = rA0; d[t][1] = rA1; d[t][2] = rB0; d[t][3] = rB1;
            t1A += rA0 + rA1; t2A += rA0*rA0 + rA1*rA1;
            t1B += rB0 + rB1; t2B += rB0*rB0 + rB1*rB1;
        }
        t1A = qsum(t1A); t2A = qsum(t2A); t1B = qsum(t1B); t2B = qsum(t2B);
        if (g4 == 0){
            sp2[ch*128 + rowA] = make_float2(t1A, t2A);
            sp2[ch*128 + rowB] = make_float2(t1B, t2B);
        }
    }
    barp(bid);                                                  // pair B4
    {
        float2 pA0 = sp2[rowA], pA1 = sp2[128 + rowA];
        float2 pB0 = sp2[rowB], pB1 = sp2[128 + rowB];
        float nuA = (pA0.x + pA1.x)*(1.0f/128.0f);
        float nsA = rsqrtf((pA0.y + pA1.y)*(1.0f/128.0f) - nuA*nuA + 1e-5f);
        float nuB = (pB0.x + pB1.x)*(1.0f/128.0f);
        float nsB = rsqrtf((pB0.y + pB1.y)*(1.0f/128.0f) - nuB*nuB + 1e-5f);
#pragma unroll
        for (int t = 0; t < 8; t++){
            int c0 = cb + t*8 + g4*2;
            float2 gg = *(float2*)(sg1 + c0);
            float2 bb = *(float2*)(sb1v + c0);
            float yA0 = fmaxf(fmaf((d[t][0]-nuA)*nsA, gg.x, bb.x), 0.0f);
            float yA1 = fmaxf(fmaf((d[t][1]-nuA)*nsA, gg.y, bb.y), 0.0f);
            float yB0 = fmaxf(fmaf((d[t][2]-nuB)*nsB, gg.x, bb.x), 0.0f);
            float yB1 = fmaxf(fmaf((d[t][3]-nuB)*nsB, gg.y, bb.y), 0.0f);
            uint32_t hA, lA, hB, lB;
            split2(yA0, yA1, hA, lA);
            split2(yB0, yB1, hB, lB);
            int kb = cb*2 + t*16 + g4*4;
            *(uint32_t*)(sm8 + A_HI_B + swz(rowA, kb)) = hA;
            *(uint32_t*)(sm8 + A_LO_B + swz(rowA, kb)) = lA;
            *(uint32_t*)(sm8 + A_HI_B + swz(rowB, kb)) = hB;
            *(uint32_t*)(sm8 + A_LO_B + swz(rowB, kb)) = lB;
        }
    }
    barp(bid);                                                  // pair B5

    // ----- GEMM1 (A rows pair-owned, W1 loaded at stage0) -----
    gemm128q(Ah, Al, Wh, Wl, r, cb, lane, d);

    // ----- epi1 -----
    {
        float s1A = 0, s2A = 0, s1B = 0, s2B = 0;
#pragma unroll
        for (int t = 0; t < 8; t++){
            int c0 = cb + t*8 + g4*2;
            float2 bb = *(float2*)(sbi1 + c0);
            d[t][0] += bb.x; d[t][1] += bb.y;
            d[t][2] += bb.x; d[t][3] += bb.y;
            s1A += d[t][0] + d[t][1]; s2A += d[t][0]*d[t][0] + d[t][1]*d[t][1];
            s1B += d[t][2] + d[t][3]; s2B += d[t][2]*d[t][2] + d[t][3]*d[t][3];
        }
        s1A = qsum(s1A); s2A = qsum(s2A); s1B = qsum(s1B); s2B = qsum(s2B);
        if (g4 == 0){
            sp[ch*128 + rowA] = make_float2(s1A, s2A);
            sp[ch*128 + rowB] = make_float2(s1B, s2B);
        }
    }
    barp(bid);                                                  // pair B6
    {
        float2 pA0 = sp[rowA], pA1 = sp[128 + rowA];
        float2 pB0 = sp[rowB], pB1 = sp[128 + rowB];
        float muA = (pA0.x + pA1.x)*(1.0f/128.0f);
        float rsA = rsqrtf((pA0.y + pA1.y)*(1.0f/128.0f) - muA*muA + 1e-5f);
        float muB = (pB0.x + pB1.x)*(1.0f/128.0f);
        float rsB = rsqrtf((pB0.y + pB1.y)*(1.0f/128.0f) - muB*muB + 1e-5f);
#pragma unroll
        for (int t = 0; t < 8; t++){
            int c0 = cb + t*8 + g4*2;
            float2 gg = *(float2*)(sg2 + c0);
            float2 bb = *(float2*)(sb2v + c0);
            float yA0 = fmaxf(fmaf((d[t][0]-muA)*rsA, gg.x, bb.x), 0.0f);
            float yA1 = fmaxf(fmaf((d[t][1]-muA)*rsA, gg.y, bb.y), 0.0f);
            float yB0 = fmaxf(fmaf((d[t][2]-muB)*rsB, gg.x, bb.x), 0.0f);
            float yB1 = fmaxf(fmaf((d[t][3]-muB)*rsB, gg.y, bb.y), 0.0f);
            uint32_t hA, lA, hB, lB;
            split2(yA0, yA1, hA, lA);
            split2(yB0, yB1, hB, lB);
            int kb = cb*2 + t*16 + g4*4;
            *(uint32_t*)(sm8 + A_HI_B + swz(rowA, kb)) = hA;
            *(uint32_t*)(sm8 + A_LO_B + swz(rowA, kb)) = lA;
            *(uint32_t*)(sm8 + A_HI_B + swz(rowB, kb)) = hB;
            *(uint32_t*)(sm8 + A_LO_B + swz(rowB, kb)) = lB;
        }
    }
    __syncthreads();                                            // FULL B7 (W1 reads + A2 complete)

    // ----- W2 copy -----
    {
        const uint4* whi = (const uint4*)g_w2hi;
        const uint4* wlo = (const uint4*)g_w2lo;
        uint4* dhi = (uint4*)(sm8 + W_HI_B);
        uint4* dlo = (uint4*)(sm8 + W_LO_B);
#pragma unroll
        for (int t = 0; t < 4; t++){
            dhi[tid + 512*t] = whi[tid + 512*t];
            dlo[tid + 512*t] = wlo[tid + 512*t];
        }
    }
    __syncthreads();                                            // FULL B8

    // ----- GEMM2 transposed: D[c][j] = W2 @ A2^T (pre-scaled by log2e) -----
    gemm128q(Wh, Wl, Ah, Al, r, cb, lane, d);

    // ----- softmax (no max-sub) + weighted xv sum -----
    {
        float bA = sbi2[rowA], bB = sbi2[rowB];
        float denA = 0, numA = 0, denB = 0, numB = 0;
#pragma unroll
        for (int t = 0; t < 8; t++){
            int jj = cb + t*8 + g4*2;
            float w0 = ex2(d[t][0] + bA), w1 = ex2(d[t][1] + bA);
            float w2 = ex2(d[t][2] + bB), w3 = ex2(d[t][3] + bB);
            float2 xA = *(float2*)(sxvT + rowA*130 + jj);
            float2 xB = *(float2*)(sxvT + rowB*130 + jj);
            denA += w0 + w1; numA += w0*xA.x + w1*xA.y;
            denB += w2 + w3; numB += w2*xB.x + w3*xB.y;
        }
        denA = qsum(denA); numA = qsum(numA);
        denB = qsum(denB); numB = qsum(numB);
        if (g4 == 0){
            sdn[ch*128 + rowA] = make_float2(denA, numA);
            sdn[ch*128 + rowB] = make_float2(denB, numB);
        }
        barp(bid);                                              // pair B9
        if (ch == 0 && g4 == 0){
            float2 a0 = sdn[rowA], a1 = sdn[128 + rowA];
            float2 b0 = sdn[rowB], b1 = sdn[128 + rowB];
            float oA = (a0.y + a1.y) / (a0.x + a1.x);
            float oB = (b0.y + b1.y) / (b0.x + b1.x);
            sxo[rowA] = oA; sxo[rowB] = oB;
            xout[(size_t)blockIdx.x*128 + rowA] = oA;
            xout[(size_t)blockIdx.x*128 + rowB] = oB;
        }
    }
    __syncthreads();                                            // FULL B10

    // ----- tail: avec/bvec spread over 512 threads -----
    {
        int m = tid & 31, half = (tid>>5)&1, q = tid>>6;
        const float* er = e1 + m*257 + half*128 + q*16;
        const float* xo = sxo + q*16;
        float a = 0;
#pragma unroll
        for (int c2 = 0; c2 < 16; c2++) a = fmaf(xo[c2], er[c2], a);
        spart[(half*32 + m)*8 + q] = a;
    }
    __syncthreads();                                            // FULL B11
    if (tid < 64){
        float a = 0;
#pragma unroll
        for (int q = 0; q < 8; q++) a += spart[tid*8 + q];
        if (tid < 32) g_avec[(size_t)blockIdx.x*32 + tid] = a;
        else          g_bvec[(size_t)blockIdx.x*32 + (tid-32)] = a;
    }
}

// ---------------- K3: message MLP + position update ----------------
__global__ void __launch_bounds__(256, 2) k3_msg(
    const float* __restrict__ p, const float* __restrict__ e1,
    const float* __restrict__ x1b, const float* __restrict__ x2,
    const float* __restrict__ x2b,
    float* __restrict__ outp)
{
    extern __shared__ char sm8[];
    float* spij  = (float*)(sm8 + K3_SPIJ);
    float* snorm = (float*)(sm8 + K3_SNORM);
    float* ss    = (float*)(sm8 + K3_SS);
    float* spad  = (float*)(sm8 + K3_SPAD);
    float* sa    = (float*)(sm8 + K3_SA);
    float* se1c  = (float*)(sm8 + K3_SE1C);
    float* sx1b_ = (float*)(sm8 + K3_SX1B);
    float* sx2v  = (float*)(sm8 + K3_SX2V);

    const uint32_t sbase = smem_u32(sm8);
    const int tid = threadIdx.x, lane = tid & 31, warp = tid >> 5;
    const int n = blockIdx.x >> 7, i = blockIdx.x & 127;
    const bool pad_i = (p[(size_t)(n*128 + i)*4] == 0.0f);

    if (pad_i){
        if (tid == 0)
            *(float4*)(outp + (size_t)(n*128 + i)*4) = make_float4(0.f, 0.f, 0.f, 0.f);
        return;
    }

    const int g4 = lane & 3;
    const int rowA = warp*16 + (lane>>2), rowB = rowA + 8;

    if (tid < 128){
        int j = tid;
        float4 pi = *(const float4*)(p + (size_t)(n*128 + i)*4);
        float4 pj = *(const float4*)(p + (size_t)(n*128 + j)*4);
        float dx = pi.x - pj.x, dy = pi.y - pj.y, dz = pi.z - pj.z, dw = pi.w - pj.w;
        spij[j*4+0] = dx; spij[j*4+1] = dy; spij[j*4+2] = dz; spij[j*4+3] = dw;
        spad[j] = (pj.x != 0.0f) ? 1.0f : 0.0f;
        snorm[j] = dw*dw - dx*dx - dy*dy - dz*dz;
    }
    if (tid < 32){
        sa[tid]    = g_avec[(size_t)(n*128 + i)*32 + tid];
        se1c[tid]  = e1[tid*257 + 256];
        sx1b_[tid] = x1b[tid];
        sx2v[tid]  = x2[tid];
    }
    for (int t = tid; t < 2560; t += 256){
        ((uint32_t*)(sm8 + K3_B1H))[t] = g_e2hi[t];
        ((uint32_t*)(sm8 + K3_B1L))[t] = g_e2lo[t];
    }
    for (int t = tid; t < 2048; t += 256){
        ((uint32_t*)(sm8 + K3_B2H))[t] = g_x1hi[t];
        ((uint32_t*)(sm8 + K3_B2L))[t] = g_x1lo[t];
    }
    __syncthreads();                                            // FULL: tiles + snorm

    // h32 tile: warp-owned rows warp*16..+15 (no CTA barrier needed before MMA1)
    const float* bv = g_bvec + (size_t)n*4096;
#pragma unroll
    for (int rr = 0; rr < 8; rr++){
        int e = rr*32 + lane;
        int row = warp*16 + (e >> 4);
        int mp = e & 15, m = mp*2;
        float nb = snorm[row];
        float2 bb = *(const float2*)(bv + row*32 + m);
        float h0 = fmaxf(sa[m]   + bb.x + nb*se1c[m],   0.0f);
        float h1 = fmaxf(sa[m+1] + bb.y + nb*se1c[m+1], 0.0f);
        uint32_t hi, lo;
        split2(h0, h1, hi, lo);
        *(uint32_t*)(sm8 + K3_A1H + row*80 + mp*4) = hi;
        *(uint32_t*)(sm8 + K3_A1L + row*80 + mp*4) = lo;
    }
    __syncwarp();

    // MMA1: mij_pre = h32 @ e2^T
    float d[16][4];
    gemm32(sbase + K3_A1H, sbase + K3_A1L, sbase + K3_B1H, sbase + K3_B1L, warp, lane, d);

    // relu -> LN (registers)
    {
        float s1A = 0, s2A = 0, s1B = 0, s2B = 0;
#pragma unroll
        for (int t = 0; t < 16; t++){
            float a0 = fmaxf(d[t][0], 0.0f), a1 = fmaxf(d[t][1], 0.0f);
            float b0 = fmaxf(d[t][2], 0.0f), b1 = fmaxf(d[t][3], 0.0f);
            d[t][0] = a0; d[t][1] = a1; d[t][2] = b0; d[t][3] = b1;
            s1A += a0 + a1; s2A += a0*a0 + a1*a1;
            s1B += b0 + b1; s2B += b0*b0 + b1*b1;
        }
        s1A = qsum(s1A); s2A = qsum(s2A); s1B = qsum(s1B); s2B = qsum(s2B);
        float muA = s1A*(1.0f/128.0f), vA = s2A*(1.0f/128.0f) - muA*muA;
        float muB = s1B*(1.0f/128.0f), vB = s2B*(1.0f/128.0f) - muB*muB;
        float rsA = rsqrtf(fmaxf(vA, 0.0f) + 1e-5f);
        float rsB = rsqrtf(fmaxf(vB, 0.0f) + 1e-5f);
#pragma unroll
        for (int t = 0; t < 16; t++){
            d[t][0] = (d[t][0]-muA)*rsA; d[t][1] = (d[t][1]-muA)*rsA;
            d[t][2] = (d[t][2]-muB)*rsB; d[t][3] = (d[t][3]-muB)*rsB;
        }
    }

    // MMA2: t_pre = y @ x1^T, A from registers
    float d2[4][4];
    mma2_regA(d, sbase + K3_B2H, sbase + K3_B2L, lane, d2);

    // scores
    {
        float x2bv = x2b[0];
        float sA = 0, sB = 0;
#pragma unroll
        for (int t = 0; t < 4; t++){
            int c0 = t*8 + g4*2;
            float2 xb = *(float2*)(sx1b_ + c0);
            float2 xv = *(float2*)(sx2v + c0);
            sA += fmaxf(d2[t][0] + xb.x, 0.0f)*xv.x + fmaxf(d2[t][1] + xb.y, 0.0f)*xv.y;
            sB += fmaxf(d2[t][2] + xb.x, 0.0f)*xv.x + fmaxf(d2[t][3] + xb.y, 0.0f)*xv.y;
        }
        sA = qsum(sA); sB = qsum(sB);
        if (g4 == 0){
            ss[rowA] = fmaxf(sA + x2bv, 0.0f);
            ss[rowB] = fmaxf(sB + x2bv, 0.0f);
        }
    }
    __syncthreads();                                            // FULL: ss ready

    if (warp == 0){
        float m0 = fmaxf(fmaxf(ss[lane], ss[lane+32]), fmaxf(ss[lane+64], ss[lane+96]));
#pragma unroll
        for (int k = 16; k > 0; k >>= 1) m0 = fmaxf(m0, __shfl_xor_sync(0xffffffffu, m0, k));
        float den = 0, dx = 0, dy = 0, dz = 0, dw = 0, cnt = 0;
#pragma unroll
        for (int q2 = 0; q2 < 4; q2++){
            int b = lane + 32*q2;
            float w = __expf(ss[b] - m0);
            den += w;
            dx = fmaf(w, spij[b*4+0], dx);
            dy = fmaf(w, spij[b*4+1], dy);
            dz = fmaf(w, spij[b*4+2], dz);
            dw = fmaf(w, spij[b*4+3], dw);
            cnt += spad[b];
        }
        den = wsum(den); dx = wsum(dx); dy = wsum(dy);
        dz = wsum(dz);   dw = wsum(dw); cnt = wsum(cnt);
        if (lane == 0){
            float inv = 1.0f / (den * cnt);
            const float* pr = p + (size_t)(n*128 + i)*4;
            float* o = outp + (size_t)(n*128 + i)*4;
            float d4[4] = {dx, dy, dz, dw};
#pragma unroll
            for (int dd = 0; dd < 4; dd++){
                float pv = pr[dd];
                o[dd] = (pv == 0.0f) ? 0.0f : pv + d4[dd]*inv;
            }
        }
    }
}

extern "C" void kernel_launch(void* const* d_in, const int* in_sizes, int n_in,
                              void* d_out, int out_size){
    const float* x     = (const float*)d_in[0];
    const float* p     = (const float*)d_in[1];
    const float* U     = (const float*)d_in[2];
    const float* wq    = (const float*)d_in[3];
    const float* bq    = (const float*)d_in[4];
    const float* wk    = (const float*)d_in[5];
    const float* bk    = (const float*)d_in[6];
    const float* wv    = (const float*)d_in[7];
    const float* bv    = (const float*)d_in[8];
    const float* ln1_g = (const float*)d_in[9];
    const float* ln1_b = (const float*)d_in[10];
    const float* w1    = (const float*)d_in[11];
    const float* b1    = (const float*)d_in[12];
    const float* ln2_g = (const float*)d_in[13];
    const float* ln2_b = (const float*)d_in[14];
    const float* w2    = (const float*)d_in[15];
    const float* b2    = (const float*)d_in[16];
    const float* pe1   = (const float*)d_in[17];
    const float* pe2   = (const float*)d_in[18];
    const float* e1    = (const float*)d_in[19];
    const float* e2    = (const float*)d_in[20];
    const float* x1    = (const float*)d_in[21];
    const float* x1b   = (const float*)d_in[22];
    const float* x2    = (const float*)d_in[23];
    const float* x2b   = (const float*)d_in[24];
    float* out  = (float*)d_out;
    float* xout = out;                 // (16,128,128)
    float* newp = out + 16*128*128;    // (16,128,4)

    cudaFuncSetAttribute(k2_attn, cudaFuncAttributeMaxDynamicSharedMemorySize, K2_SMEM);
    cudaFuncSetAttribute(k3_msg,  cudaFuncAttributeMaxDynamicSharedMemorySize, K3_SMEM);

    k0_prep<<<64, 256>>>(wq, wk, wv, w1, w2, pe2, e2, x1);
    k1_qkv<<<2048, 128>>>(x, bq, bk, bv);
    k2_attn<<<2048, 512, K2_SMEM>>>(U, p, ln1_g, ln1_b, b1, ln2_g, ln2_b, b2, pe1, e1, xout);
    k3_msg<<<2048, 256, K3_SMEM>>>(p, e1, x1b, x2, x2b, newp);
}

// round 10
// speedup vs baseline: 3.6298x; 1.0080x over previous
#include <cuda_runtime.h>
#include <cuda_bf16.h>
#include <math.h>
#include <stdint.h>

#define NEGV (-10000.0f)
#define LOG2E 1.44269504088896340736f

// ---------------- K2 smem byte offsets (512-thread version) ----------------
#define XVT_B    0          // fp32 xvT [128][130] (66560B); pe2/tn tiles alias front
#define PE2H_B   0
#define PE2L_B   10240
#define TNH_B    20480
#define TNL_B    30720
#define A_HI_B   67584      // bf16 A tile (XOR swizzle, 32KB each)
#define A_LO_B   100352
#define W_HI_B   133120     // bf16 W tile: w1 -> w2
#define W_LO_B   165888
#define SK_B     198656
#define SG1_B    199168
#define SB1_B    199680
#define SG2_B    200192
#define SB2_B    200704
#define SBI1_B   201216
#define SBI2_B   201728
#define SPE1_B   202240
#define SPIJ_B   202752     // 2048
#define SXO_B    204800     // 512
#define SP_B     205312     // 2048
#define SP2_B    207360     // 2048
#define SDN_B    209408     // 2048
#define K2_SMEM  211456

// ---------------- K3 smem byte offsets ----------------
#define K3_A1H   0
#define K3_A1L   10240
#define K3_B1H   20480
#define K3_B1L   30720
#define K3_B2H   40960
#define K3_B2L   49152
#define K3_SPIJ  57344
#define K3_SNORM 59392
#define K3_SS    59904
#define K3_SPAD  60416
#define K3_SA    60928
#define K3_SE1C  61056
#define K3_SX1B  61184
#define K3_SX2V  61312
#define K3_SMEM  61440

// ---------------- device scratch ----------------
__device__ float g_q[16*128*128];
__device__ float g_k[16*128*128];
__device__ float g_v[16*128*128];
__device__ float g_wqT[64*128];
__device__ float g_wkT[64*128];
__device__ float g_wvT[64*128];
__device__ float g_avec[16*128*32];
__device__ float g_bvec[16*128*32];
__device__ uint32_t g_w1hi[8192];
__device__ uint32_t g_w1lo[8192];
__device__ uint32_t g_w2hi[8192];
__device__ uint32_t g_w2lo[8192];
__device__ uint32_t g_x1hi[2048];
__device__ uint32_t g_x1lo[2048];
__device__ uint32_t g_pe2hi[2560];
__device__ uint32_t g_pe2lo[2560];
__device__ uint32_t g_e2hi[2560];
__device__ uint32_t g_e2lo[2560];

// ---------------- helpers ----------------
__device__ __forceinline__ float wsum(float v){
#pragma unroll
    for (int k = 16; k > 0; k >>= 1) v += __shfl_xor_sync(0xffffffffu, v, k);
    return v;
}
__device__ __forceinline__ float qsum(float v){
    v += __shfl_xor_sync(0xffffffffu, v, 1);
    v += __shfl_xor_sync(0xffffffffu, v, 2);
    return v;
}
__device__ __forceinline__ uint32_t smem_u32(const void* p){
    uint32_t a;
    asm("{ .reg .u64 t; cvta.to.shared.u64 t, %1; cvt.u32.u64 %0, t; }" : "=r"(a) : "l"(p));
    return a;
}
__device__ __forceinline__ uint32_t swz(int row, int kb){
    return (uint32_t)(row*256 + ((kb & 0xF0) ^ ((row & 7) << 4)) + (kb & 15));
}
__device__ __forceinline__ float ex2(float x){
    float r; asm("ex2.approx.ftz.f32 %0, %1;" : "=f"(r) : "f"(x)); return r;
}
__device__ __forceinline__ void barp(int id){
    asm volatile("bar.sync %0, 64;" :: "r"(id) : "memory");
}
__device__ __forceinline__ void split2(float x, float y, uint32_t &hi, uint32_t &lo){
    uint32_t h;
    asm("cvt.rn.bf16x2.f32 %0, %1, %2;" : "=r"(h) : "f"(y), "f"(x));
    float xh = __uint_as_float(h << 16);
    float yh = __uint_as_float(h & 0xFFFF0000u);
    asm("cvt.rn.bf16x2.f32 %0, %1, %2;" : "=r"(lo) : "f"(y - yh), "f"(x - xh));
    hi = h;
}
__device__ __forceinline__ void ldsm4(uint32_t a[4], uint32_t addr){
    asm volatile("ldmatrix.sync.aligned.m8n8.x4.shared.b16 {%0,%1,%2,%3}, [%4];"
        : "=r"(a[0]), "=r"(a[1]), "=r"(a[2]), "=r"(a[3]) : "r"(addr));
}
__device__ __forceinline__ void mma16816(float d[4], const uint32_t a[4], const uint32_t b[2]){
    asm volatile("mma.sync.aligned.m16n8k16.row.col.f32.bf16.bf16.f32 "
        "{%0,%1,%2,%3}, {%4,%5,%6,%7}, {%8,%9}, {%0,%1,%2,%3};"
        : "+f"(d[0]), "+f"(d[1]), "+f"(d[2]), "+f"(d[3])
        : "r"(a[0]), "r"(a[1]), "r"(a[2]), "r"(a[3]), "r"(b[0]), "r"(b[1]));
}

// K2 quadrant GEMM: A rows r*16..+15, B rows cb..cb+63, K=128, XOR tiles.
__device__ __forceinline__ void gemm128q(uint32_t Ah, uint32_t Al, uint32_t Bh, uint32_t Bl,
                                         int r, int cb, int lane, float d[8][4]){
#pragma unroll
    for (int t = 0; t < 8; t++){ d[t][0]=0.f; d[t][1]=0.f; d[t][2]=0.f; d[t][3]=0.f; }
    const uint32_t aro = (uint32_t)((r*16 + (lane&15))*256);
    const uint32_t aox = (uint32_t)((lane&7)<<4);
    const uint32_t akx = (uint32_t)(lane&16);
    const uint32_t bro = (uint32_t)((cb + (lane&7) + ((lane>>4)<<3))*256);
    const uint32_t bkx = (uint32_t)((lane&8)<<1);
#pragma unroll 1
    for (int kk = 0; kk < 8; kk++){
        uint32_t ka = (uint32_t)(kk*32);
        uint32_t ah[4], al_[4];
        ldsm4(ah,  Ah + aro + ((ka + akx) ^ aox));
        ldsm4(al_, Al + aro + ((ka + akx) ^ aox));
        uint32_t bo = bro + ((ka + bkx) ^ aox);
#pragma unroll
        for (int t2 = 0; t2 < 4; t2++){
            uint32_t bh[4], bl[4];
            ldsm4(bh, Bh + bo + (uint32_t)(t2*4096));
            ldsm4(bl, Bl + bo + (uint32_t)(t2*4096));
            mma16816(d[2*t2],   ah,  bh);
            mma16816(d[2*t2],   ah,  bl);
            mma16816(d[2*t2],   al_, bh);
            mma16816(d[2*t2+1], ah,  bh+2);
            mma16816(d[2*t2+1], ah,  bl+2);
            mma16816(d[2*t2+1], al_, bh+2);
        }
    }
}

// K2 quadrant small-K GEMM: K=32, 80B-stride tiles.
__device__ __forceinline__ void gemm32q(uint32_t Ah, uint32_t Al, uint32_t Bh, uint32_t Bl,
                                        int r, int cb, int lane, float d[8][4]){
#pragma unroll
    for (int t = 0; t < 8; t++){ d[t][0]=0.f; d[t][1]=0.f; d[t][2]=0.f; d[t][3]=0.f; }
    const uint32_t aro = (uint32_t)((r*16 + (lane&15))*80 + (lane&16));
    const uint32_t bro = (uint32_t)((cb + (lane&7) + ((lane>>4)<<3))*80 + ((lane&8)<<1));
#pragma unroll
    for (int kk = 0; kk < 2; kk++){
        uint32_t ah[4], al_[4];
        ldsm4(ah,  Ah + aro + (uint32_t)(kk*32));
        ldsm4(al_, Al + aro + (uint32_t)(kk*32));
#pragma unroll
        for (int t2 = 0; t2 < 4; t2++){
            uint32_t bh[4], bl[4];
            ldsm4(bh, Bh + bro + (uint32_t)(kk*32 + t2*1280));
            ldsm4(bl, Bl + bro + (uint32_t)(kk*32 + t2*1280));
            mma16816(d[2*t2],   ah,  bh);
            mma16816(d[2*t2],   ah,  bl);
            mma16816(d[2*t2],   al_, bh);
            mma16816(d[2*t2+1], ah,  bh+2);
            mma16816(d[2*t2+1], ah,  bl+2);
            mma16816(d[2*t2+1], al_, bh+2);
        }
    }
}

// K3 full-width K=32 GEMM (8 warps, 16 rows each, all 128 cols)
__device__ __forceinline__ void gemm32(uint32_t Ah, uint32_t Al, uint32_t Bh, uint32_t Bl,
                                       int warp, int lane, float d[16][4]){
#pragma unroll
    for (int t = 0; t < 16; t++){ d[t][0]=0.f; d[t][1]=0.f; d[t][2]=0.f; d[t][3]=0.f; }
    const uint32_t aro = (uint32_t)((warp*16 + (lane&15))*80 + (lane&16));
    const uint32_t bro = (uint32_t)(((lane&7) + ((lane>>4)<<3))*80 + ((lane&8)<<1));
#pragma unroll
    for (int kk = 0; kk < 2; kk++){
        uint32_t ah[4], al_[4];
        ldsm4(ah,  Ah + aro + (uint32_t)(kk*32));
        ldsm4(al_, Al + aro + (uint32_t)(kk*32));
#pragma unroll
        for (int t2 = 0; t2 < 8; t2++){
            uint32_t bh[4], bl[4];
            ldsm4(bh, Bh + bro + (uint32_t)(kk*32 + t2*1280));
            ldsm4(bl, Bl + bro + (uint32_t)(kk*32 + t2*1280));
            mma16816(d[2*t2],   ah,  bh);
            mma16816(d[2*t2],   ah,  bl);
            mma16816(d[2*t2],   al_, bh);
            mma16816(d[2*t2+1], ah,  bh+2);
            mma16816(d[2*t2+1], ah,  bl+2);
            mma16816(d[2*t2+1], al_, bh+2);
        }
    }
}

// K3 MMA2 with A from registers (y in C-fragment layout), B = x1 tile (32 rows, XOR)
__device__ __forceinline__ void mma2_regA(const float y[16][4], uint32_t Bh, uint32_t Bl,
                                          int lane, float d2[4][4]){
#pragma unroll
    for (int t = 0; t < 4; t++){ d2[t][0]=0.f; d2[t][1]=0.f; d2[t][2]=0.f; d2[t][3]=0.f; }
    const uint32_t aox = (uint32_t)((lane&7)<<4);
    const uint32_t bro = (uint32_t)(((lane&7) + ((lane>>4)<<3))*256);
    const uint32_t bkx = (uint32_t)((lane&8)<<1);
#pragma unroll
    for (int kt = 0; kt < 8; kt++){
        uint32_t ah[4], al_[4];
        split2(y[2*kt][0],   y[2*kt][1],   ah[0], al_[0]);
        split2(y[2*kt][2],   y[2*kt][3],   ah[1], al_[1]);
        split2(y[2*kt+1][0], y[2*kt+1][1], ah[2], al_[2]);
        split2(y[2*kt+1][2], y[2*kt+1][3], ah[3], al_[3]);
        uint32_t bo = bro + (((uint32_t)(kt*32) + bkx) ^ aox);
#pragma unroll
        for (int t2 = 0; t2 < 2; t2++){
            uint32_t bh[4], bl[4];
            ldsm4(bh, Bh + bo + (uint32_t)(t2*4096));
            ldsm4(bl, Bl + bo + (uint32_t)(t2*4096));
            mma16816(d2[2*t2],   ah,  bh);
            mma16816(d2[2*t2],   ah,  bl);
            mma16816(d2[2*t2],   al_, bh);
            mma16816(d2[2*t2+1], ah,  bh+2);
            mma16816(d2[2*t2+1], ah,  bl+2);
            mma16816(d2[2*t2+1], al_, bh+2);
        }
    }
}

// ---------------- K0: weight prep ----------------
__global__ void k0_prep(const float* __restrict__ wq, const float* __restrict__ wk,
                        const float* __restrict__ wv, const float* __restrict__ w1,
                        const float* __restrict__ w2, const float* __restrict__ pe2,
                        const float* __restrict__ e2, const float* __restrict__ x1){
    int idx = blockIdx.x * blockDim.x + threadIdx.x;
    int stride = gridDim.x * blockDim.x;
    for (int t = idx; t < 16384; t += stride){
        int c = t >> 7, m = t & 127;
        uint32_t a = swz(c, m*2) >> 1;
        float v1 = w1[t];
        __nv_bfloat16 h1 = __float2bfloat16(v1);
        ((unsigned short*)g_w1hi)[a] = __bfloat16_as_ushort(h1);
        ((unsigned short*)g_w1lo)[a] = __bfloat16_as_ushort(__float2bfloat16(v1 - __bfloat162float(h1)));
        float v2 = w2[t] * LOG2E;
        __nv_bfloat16 h2 = __float2bfloat16(v2);
        ((unsigned short*)g_w2hi)[a] = __bfloat16_as_ushort(h2);
        ((unsigned short*)g_w2lo)[a] = __bfloat16_as_ushort(__float2bfloat16(v2 - __bfloat162float(h2)));
    }
    for (int t = idx; t < 4096; t += stride){
        int c = t >> 5, m = t & 31;
        uint32_t a80 = (uint32_t)(c*40 + m);
        float vp = pe2[t];
        __nv_bfloat16 hp = __float2bfloat16(vp);
        ((unsigned short*)g_pe2hi)[a80] = __bfloat16_as_ushort(hp);
        ((unsigned short*)g_pe2lo)[a80] = __bfloat16_as_ushort(__float2bfloat16(vp - __bfloat162float(hp)));
        float ve = e2[t];
        __nv_bfloat16 he = __float2bfloat16(ve);
        ((unsigned short*)g_e2hi)[a80] = __bfloat16_as_ushort(he);
        ((unsigned short*)g_e2lo)[a80] = __bfloat16_as_ushort(__float2bfloat16(ve - __bfloat162float(he)));
        int m2 = t >> 7, c2 = t & 127;
        uint32_t ax = swz(m2, c2*2) >> 1;
        float vx = x1[t];
        __nv_bfloat16 hx = __float2bfloat16(vx);
        ((unsigned short*)g_x1hi)[ax] = __bfloat16_as_ushort(hx);
        ((unsigned short*)g_x1lo)[ax] = __bfloat16_as_ushort(__float2bfloat16(vx - __bfloat162float(hx)));
    }
    for (int t = idx; t < 8192; t += stride){
        int c = t >> 6, d = t & 63;
        g_wqT[d*128 + c] = wq[t];
        g_wkT[d*128 + c] = wk[t];
        g_wvT[d*128 + c] = wv[t];
    }
}

// ---------------- K1: q,k,v projections ----------------
__global__ void __launch_bounds__(128) k1_qkv(const float* __restrict__ x,
                                              const float* __restrict__ bq,
                                              const float* __restrict__ bk,
                                              const float* __restrict__ bv){
    __shared__ float sx[64];
    int row = blockIdx.x;
    int c = threadIdx.x;
    if (c < 64) sx[c] = x[(size_t)row*64 + c];
    __syncthreads();
    float aq = bq[c], ak = bk[c], av = bv[c];
#pragma unroll 8
    for (int d = 0; d < 64; d++){
        float xv = sx[d];
        aq = fmaf(xv, g_wqT[d*128 + c], aq);
        ak = fmaf(xv, g_wkT[d*128 + c], ak);
        av = fmaf(xv, g_wvT[d*128 + c], av);
    }
    g_q[(size_t)row*128 + c] = aq;
    g_k[(size_t)row*128 + c] = ak;
    g_v[(size_t)row*128 + c] = av;
}

// ---------------- K2: fused attention per (n,i), 512 threads, pairwise barriers ----------------
__global__ void __launch_bounds__(512) k2_attn(
    const float* __restrict__ U, const float* __restrict__ p,
    const float* __restrict__ ln1_g, const float* __restrict__ ln1_b,
    const float* __restrict__ b1,
    const float* __restrict__ ln2_g, const float* __restrict__ ln2_b,
    const float* __restrict__ b2,
    const float* __restrict__ pe1, const float* __restrict__ e1,
    float* __restrict__ xout)
{
    extern __shared__ char sm8[];
    float*  sxvT = (float*)(sm8 + XVT_B);
    float*  sk   = (float*)(sm8 + SK_B);
    float*  sg1  = (float*)(sm8 + SG1_B);
    float*  sb1v = (float*)(sm8 + SB1_B);
    float*  sg2  = (float*)(sm8 + SG2_B);
    float*  sb2v = (float*)(sm8 + SB2_B);
    float*  sbi1 = (float*)(sm8 + SBI1_B);
    float*  sbi2 = (float*)(sm8 + SBI2_B);
    float*  spe1 = (float*)(sm8 + SPE1_B);
    float*  spij = (float*)(sm8 + SPIJ_B);
    float*  sxo  = (float*)(sm8 + SXO_B);
    float2* sp   = (float2*)(sm8 + SP_B);
    float*  spart= (float*)(sm8 + SP_B);
    float2* sp2  = (float2*)(sm8 + SP2_B);
    float2* sdn  = (float2*)(sm8 + SDN_B);

    const uint32_t sbase = smem_u32(sm8);
    const uint32_t Ah = sbase + A_HI_B, Al = sbase + A_LO_B;
    const uint32_t Wh = sbase + W_HI_B, Wl = sbase + W_LO_B;
    const int tid = threadIdx.x;
    const int lane = tid & 31, warp = tid >> 5;
    const int r = warp & 7, ch = warp >> 3;
    const int cb = ch*64;
    const int bid = r + 1;
    const int n = blockIdx.x >> 7, i = blockIdx.x & 127;
    const int g4 = lane & 3;
    const int rowA = r*16 + (lane>>2), rowB = rowA + 8;

    const float* Ub = U + (size_t)blockIdx.x * 16384;
    asm volatile("prefetch.global.L2 [%0];" :: "l"(Ub + (tid << 5)));

    // ----- stage 0 -----
    if (tid < 128){
        size_t rowk = (size_t)(n*128 + i);
        sk[tid]   = g_k[rowk*128 + tid];
        sg1[tid]  = ln1_g[tid];  sb1v[tid] = ln1_b[tid];
        sg2[tid]  = ln2_g[tid];  sb2v[tid] = ln2_b[tid];
        sbi1[tid] = b1[tid];     sbi2[tid] = b2[tid] * LOG2E;
        spe1[tid] = pe1[tid];
        int j = tid;
        float4 pi = *(const float4*)(p + (size_t)(n*128 + i)*4);
        float4 pj = *(const float4*)(p + (size_t)(n*128 + j)*4);
        spij[j*4+0] = pi.x - pj.x;
        spij[j*4+1] = pi.y - pj.y;
        spij[j*4+2] = pi.z - pj.z;
        spij[j*4+3] = pi.w - pj.w;
    }
    for (int t = tid; t < 2560; t += 512){
        ((uint32_t*)(sm8 + PE2H_B))[t] = g_pe2hi[t];
        ((uint32_t*)(sm8 + PE2L_B))[t] = g_pe2lo[t];
    }
    {
        const uint4* whi = (const uint4*)g_w1hi;
        const uint4* wlo = (const uint4*)g_w1lo;
        uint4* dhi = (uint4*)(sm8 + W_HI_B);
        uint4* dlo = (uint4*)(sm8 + W_LO_B);
#pragma unroll
        for (int t = 0; t < 4; t++){
            dhi[tid + 512*t] = whi[tid + 512*t];
            dlo[tid + 512*t] = wlo[tid + 512*t];
        }
    }
    const bool pad_i = (p[(size_t)(n*128 + i)*4] == 0.0f);
    __syncthreads();                                            // FULL B1

    // ----- prefetch U fragments into registers (hidden under tn + GEMM0) -----
    float rU[8][4];
#pragma unroll
    for (int t = 0; t < 8; t++){
        int c0 = cb + t*8 + g4*2;
        float2 uA = *(const float2*)(Ub + rowA*128 + c0);
        float2 uB = *(const float2*)(Ub + rowB*128 + c0);
        rU[t][0] = uA.x; rU[t][1] = uA.y;
        rU[t][2] = uB.x; rU[t][3] = uB.y;
    }

    // ----- tn: pair-owned rows r*16+ch*8 .. +7; one-pass LN32 -----
    {
        float4 pe1r = ((const float4*)spe1)[lane];
#pragma unroll 1
        for (int rr = 0; rr < 8; rr++){
            int jj = r*16 + ch*8 + rr;
            float4 pd = *(const float4*)(spij + jj*4);
            float t = pd.x*pe1r.x + pd.y*pe1r.y + pd.z*pe1r.z + pd.w*pe1r.w;
            float s1 = t, s2v = t*t;
#pragma unroll
            for (int k = 16; k > 0; k >>= 1){
                s1  += __shfl_xor_sync(0xffffffffu, s1,  k);
                s2v += __shfl_xor_sync(0xffffffffu, s2v, k);
            }
            float mu = s1 * (1.0f/32.0f);
            float var = fmaxf(s2v*(1.0f/32.0f) - mu*mu, 0.0f);
            float tn = fmaxf((t - mu) * rsqrtf(var + 1e-5f), 0.0f);
            float tn1 = __shfl_down_sync(0xffffffffu, tn, 1);
            if (!(lane & 1)){
                uint32_t hi, lo;
                split2(tn, tn1, hi, lo);
                *(uint32_t*)(sm8 + TNH_B + jj*80 + lane*2) = hi;
                *(uint32_t*)(sm8 + TNL_B + jj*80 + lane*2) = lo;
            }
        }
    }
    barp(bid);                                                  // pair B2

    // ----- GEMM0: eqpe_pre -----
    float d[8][4];
    gemm32q(sbase + TNH_B, sbase + TNL_B, sbase + PE2H_B, sbase + PE2L_B, r, cb, lane, d);

    // ----- epi0 stats -----
    {
        float s1A = 0, s2A = 0, s1B = 0, s2B = 0;
#pragma unroll
        for (int t = 0; t < 8; t++){
            s1A += d[t][0] + d[t][1]; s2A += d[t][0]*d[t][0] + d[t][1]*d[t][1];
            s1B += d[t][2] + d[t][3]; s2B += d[t][2]*d[t][2] + d[t][3]*d[t][3];
        }
        s1A = qsum(s1A); s2A = qsum(s2A); s1B = qsum(s1B); s2B = qsum(s2B);
        if (g4 == 0){
            sp[ch*128 + rowA] = make_float2(s1A, s2A);
            sp[ch*128 + rowB] = make_float2(s1B, s2B);
        }
    }
    barp(bid);                                                  // pair B3

    const float* vb = g_v + (size_t)n*16384;

    if (pad_i){
        // ---- pad short-circuit: x_out = mean_j(xv) ----
        float2 pA0 = sp[rowA], pA1 = sp[128 + rowA];
        float2 pB0 = sp[rowB], pB1 = sp[128 + rowB];
        float muA = (pA0.x + pA1.x)*(1.0f/128.0f);
        float rsA = rsqrtf((pA0.y + pA1.y)*(1.0f/128.0f) - muA*muA + 1e-5f);
        float muB = (pB0.x + pB1.x)*(1.0f/128.0f);
        float rsB = rsqrtf((pB0.y + pB1.y)*(1.0f/128.0f) - muB*muB + 1e-5f);
#pragma unroll
        for (int t = 0; t < 8; t++){
            int c0 = cb + t*8 + g4*2;
            float2 vA = *(const float2*)(vb + rowA*128 + c0);
            float2 vB = *(const float2*)(vb + rowB*128 + c0);
            sxvT[(c0  )*130 + rowA] = vA.x + fmaxf((d[t][0]-muA)*rsA, 0.0f) + rU[t][0];
            sxvT[(c0+1)*130 + rowA] = vA.y + fmaxf((d[t][1]-muA)*rsA, 0.0f) + rU[t][1];
            sxvT[(c0  )*130 + rowB] = vB.x + fmaxf((d[t][2]-muB)*rsB, 0.0f) + rU[t][2];
            sxvT[(c0+1)*130 + rowB] = vB.y + fmaxf((d[t][3]-muB)*rsB, 0.0f) + rU[t][3];
        }
        __syncthreads();
        if (tid < 128){
            float s = 0.0f;
            const float* row = sxvT + tid*130;
#pragma unroll 8
            for (int j = 0; j < 128; j++) s += row[j];
            float o = s * (1.0f/128.0f);
            sxo[tid] = o;
            xout[(size_t)blockIdx.x*128 + tid] = o;
        }
        __syncthreads();
        {
            int m = tid & 31, half = (tid>>5)&1, q = tid>>6;
            const float* er = e1 + m*257 + half*128 + q*16;
            const float* xo = sxo + q*16;
            float a = 0;
#pragma unroll
            for (int c2 = 0; c2 < 16; c2++) a = fmaf(xo[c2], er[c2], a);
            spart[(half*32 + m)*8 + q] = a;
        }
        __syncthreads();
        if (tid < 64){
            float a = 0;
#pragma unroll
            for (int q = 0; q < 8; q++) a += spart[tid*8 + q];
            if (tid < 32) g_avec[(size_t)blockIdx.x*32 + tid] = a;
            else          g_bvec[(size_t)blockIdx.x*32 + (tid-32)] = a;
        }
        return;
    }

    // ----- non-pad: full epi0 -----
    {
        float2 pA0 = sp[rowA], pA1 = sp[128 + rowA];
        float2 pB0 = sp[rowB], pB1 = sp[128 + rowB];
        float muA = (pA0.x + pA1.x)*(1.0f/128.0f);
        float rsA = rsqrtf((pA0.y + pA1.y)*(1.0f/128.0f) - muA*muA + 1e-5f);
        float muB = (pB0.x + pB1.x)*(1.0f/128.0f);
        float rsB = rsqrtf((pB0.y + pB1.y)*(1.0f/128.0f) - muB*muB + 1e-5f);

        const float* qb = g_q + (size_t)n*16384;
        float t1A = 0, t2A = 0, t1B = 0, t2B = 0;
#pragma unroll
        for (int t = 0; t < 8; t++){
            int c0 = cb + t*8 + g4*2;
            float2 qA = *(const float2*)(qb + rowA*128 + c0);
            float2 qB = *(const float2*)(qb + rowB*128 + c0);
            float2 vA = *(const float2*)(vb + rowA*128 + c0);
            float2 vB = *(const float2*)(vb + rowB*128 + c0);
            float2 kc = *(const float2*)(sk + c0);
            float eA0 = fmaxf((d[t][0]-muA)*rsA, 0.0f) + rU[t][0];
            float eA1 = fmaxf((d[t][1]-muA)*rsA, 0.0f) + rU[t][1];
            float eB0 = fmaxf((d[t][2]-muB)*rsB, 0.0f) + rU[t][2];
            float eB1 = fmaxf((d[t][3]-muB)*rsB, 0.0f) + rU[t][3];
            sxvT[(c0  )*130 + rowA] = vA.x + eA0;
            sxvT[(c0+1)*130 + rowA] = vA.y + eA1;
            sxvT[(c0  )*130 + rowB] = vB.x + eB0;
            sxvT[(c0+1)*130 + rowB] = vB.y + eB1;
            float rA0 = kc.x - qA.x + eA0;
            float rA1 = kc.y - qA.y + eA1;
            float rB0 = kc.x - qB.x + eB0;
            float rB1 = kc.y - qB.y + eB1;
            d[t][0] = rA0; d[t][1] = rA1; d[t][2] = rB0; d[t][3] = rB1;
            t1A += rA0 + rA1; t2A += rA0*rA0 + rA1*rA1;
            t1B += rB0 + rB1; t2B += rB0*rB0 + rB1*rB1;
        }
        t1A = qsum(t1A); t2A = qsum(t2A); t1B = qsum(t1B); t2B = qsum(t2B);
        if (g4 == 0){
            sp2[ch*128 + rowA] = make_float2(t1A, t2A);
            sp2[ch*128 + rowB] = make_float2(t1B, t2B);
        }
    }
    barp(bid);                                                  // pair B4
    {
        float2 pA0 = sp2[rowA], pA1 = sp2[128 + rowA];
        float2 pB0 = sp2[rowB], pB1 = sp2[128 + rowB];
        float nuA = (pA0.x + pA1.x)*(1.0f/128.0f);
        float nsA = rsqrtf((pA0.y + pA1.y)*(1.0f/128.0f) - nuA*nuA + 1e-5f);
        float nuB = (pB0.x + pB1.x)*(1.0f/128.0f);
        float nsB = rsqrtf((pB0.y + pB1.y)*(1.0f/128.0f) - nuB*nuB + 1e-5f);
#pragma unroll
        for (int t = 0; t < 8; t++){
            int c0 = cb + t*8 + g4*2;
            float2 gg = *(float2*)(sg1 + c0);
            float2 bb = *(float2*)(sb1v + c0);
            float yA0 = fmaxf(fmaf((d[t][0]-nuA)*nsA, gg.x, bb.x), 0.0f);
            float yA1 = fmaxf(fmaf((d[t][1]-nuA)*nsA, gg.y, bb.y), 0.0f);
            float yB0 = fmaxf(fmaf((d[t][2]-nuB)*nsB, gg.x, bb.x), 0.0f);
            float yB1 = fmaxf(fmaf((d[t][3]-nuB)*nsB, gg.y, bb.y), 0.0f);
            uint32_t hA, lA, hB, lB;
            split2(yA0, yA1, hA, lA);
            split2(yB0, yB1, hB, lB);
            int kb = cb*2 + t*16 + g4*4;
            *(uint32_t*)(sm8 + A_HI_B + swz(rowA, kb)) = hA;
            *(uint32_t*)(sm8 + A_LO_B + swz(rowA, kb)) = lA;
            *(uint32_t*)(sm8 + A_HI_B + swz(rowB, kb)) = hB;
            *(uint32_t*)(sm8 + A_LO_B + swz(rowB, kb)) = lB;
        }
    }
    barp(bid);                                                  // pair B5

    // ----- GEMM1 -----
    gemm128q(Ah, Al, Wh, Wl, r, cb, lane, d);

    // ----- epi1 -----
    {
        float s1A = 0, s2A = 0, s1B = 0, s2B = 0;
#pragma unroll
        for (int t = 0; t < 8; t++){
            int c0 = cb + t*8 + g4*2;
            float2 bb = *(float2*)(sbi1 + c0);
            d[t][0] += bb.x; d[t][1] += bb.y;
            d[t][2] += bb.x; d[t][3] += bb.y;
            s1A += d[t][0] + d[t][1]; s2A += d[t][0]*d[t][0] + d[t][1]*d[t][1];
            s1B += d[t][2] + d[t][3]; s2B += d[t][2]*d[t][2] + d[t][3]*d[t][3];
        }
        s1A = qsum(s1A); s2A = qsum(s2A); s1B = qsum(s1B); s2B = qsum(s2B);
        if (g4 == 0){
            sp[ch*128 + rowA] = make_float2(s1A, s2A);
            sp[ch*128 + rowB] = make_float2(s1B, s2B);
        }
    }
    barp(bid);                                                  // pair B6
    {
        float2 pA0 = sp[rowA], pA1 = sp[128 + rowA];
        float2 pB0 = sp[rowB], pB1 = sp[128 + rowB];
        float muA = (pA0.x + pA1.x)*(1.0f/128.0f);
        float rsA = rsqrtf((pA0.y + pA1.y)*(1.0f/128.0f) - muA*muA + 1e-5f);
        float muB = (pB0.x + pB1.x)*(1.0f/128.0f);
        float rsB = rsqrtf((pB0.y + pB1.y)*(1.0f/128.0f) - muB*muB + 1e-5f);
#pragma unroll
        for (int t = 0; t < 8; t++){
            int c0 = cb + t*8 + g4*2;
            float2 gg = *(float2*)(sg2 + c0);
            float2 bb = *(float2*)(sb2v + c0);
            float yA0 = fmaxf(fmaf((d[t][0]-muA)*rsA, gg.x, bb.x), 0.0f);
            float yA1 = fmaxf(fmaf((d[t][1]-muA)*rsA, gg.y, bb.y), 0.0f);
            float yB0 = fmaxf(fmaf((d[t][2]-muB)*rsB, gg.x, bb.x), 0.0f);
            float yB1 = fmaxf(fmaf((d[t][3]-muB)*rsB, gg.y, bb.y), 0.0f);
            uint32_t hA, lA, hB, lB;
            split2(yA0, yA1, hA, lA);
            split2(yB0, yB1, hB, lB);
            int kb = cb*2 + t*16 + g4*4;
            *(uint32_t*)(sm8 + A_HI_B + swz(rowA, kb)) = hA;
            *(uint32_t*)(sm8 + A_LO_B + swz(rowA, kb)) = lA;
            *(uint32_t*)(sm8 + A_HI_B + swz(rowB, kb)) = hB;
            *(uint32_t*)(sm8 + A_LO_B + swz(rowB, kb)) = lB;
        }
    }
    __syncthreads();                                            // FULL B7 (W1 reads + A2 complete)

    // ----- pair-local W2 copy: pair r owns W2 rows r*16..+15 (8KB hi+lo) -----
    {
        int pt = ch*32 + lane;                 // 0..63 within pair
        const uint4* whi = (const uint4*)g_w2hi;
        const uint4* wlo = (const uint4*)g_w2lo;
        uint4* dhi = (uint4*)(sm8 + W_HI_B);
        uint4* dlo = (uint4*)(sm8 + W_LO_B);
#pragma unroll
        for (int t = 0; t < 4; t++){
            int idx = r*256 + pt + 64*t;
            dhi[idx] = whi[idx];
            dlo[idx] = wlo[idx];
        }
    }
    barp(bid);                                                  // pair B8

    // ----- GEMM2 transposed: D[c][j] = W2 @ A2^T -----
    gemm128q(Wh, Wl, Ah, Al, r, cb, lane, d);

    // ----- softmax (no max-sub) + weighted xv sum -----
    {
        float bA = sbi2[rowA], bB = sbi2[rowB];
        float denA = 0, numA = 0, denB = 0, numB = 0;
#pragma unroll
        for (int t = 0; t < 8; t++){
            int jj = cb + t*8 + g4*2;
            float w0 = ex2(d[t][0] + bA), w1 = ex2(d[t][1] + bA);
            float w2 = ex2(d[t][2] + bB), w3 = ex2(d[t][3] + bB);
            float2 xA = *(float2*)(sxvT + rowA*130 + jj);
            float2 xB = *(float2*)(sxvT + rowB*130 + jj);
            denA += w0 + w1; numA += w0*xA.x + w1*xA.y;
            denB += w2 + w3; numB += w2*xB.x + w3*xB.y;
        }
        denA = qsum(denA); numA = qsum(numA);
        denB = qsum(denB); numB = qsum(numB);
        if (g4 == 0){
            sdn[ch*128 + rowA] = make_float2(denA, numA);
            sdn[ch*128 + rowB] = make_float2(denB, numB);
        }
        barp(bid);                                              // pair B9
        if (ch == 0 && g4 == 0){
            float2 a0 = sdn[rowA], a1 = sdn[128 + rowA];
            float2 b0 = sdn[rowB], b1 = sdn[128 + rowB];
            float oA = (a0.y + a1.y) / (a0.x + a1.x);
            float oB = (b0.y + b1.y) / (b0.x + b1.x);
            sxo[rowA] = oA; sxo[rowB] = oB;
            xout[(size_t)blockIdx.x*128 + rowA] = oA;
            xout[(size_t)blockIdx.x*128 + rowB] = oB;
        }
    }
    __syncthreads();                                            // FULL B10

    // ----- tail: avec/bvec spread over 512 threads -----
    {
        int m = tid & 31, half = (tid>>5)&1, q = tid>>6;
        const float* er = e1 + m*257 + half*128 + q*16;
        const float* xo = sxo + q*16;
        float a = 0;
#pragma unroll
        for (int c2 = 0; c2 < 16; c2++) a = fmaf(xo[c2], er[c2], a);
        spart[(half*32 + m)*8 + q] = a;
    }
    __syncthreads();                                            // FULL B11
    if (tid < 64){
        float a = 0;
#pragma unroll
        for (int q = 0; q < 8; q++) a += spart[tid*8 + q];
        if (tid < 32) g_avec[(size_t)blockIdx.x*32 + tid] = a;
        else          g_bvec[(size_t)blockIdx.x*32 + (tid-32)] = a;
    }
}

// ---------------- K3: message MLP + position update ----------------
__global__ void __launch_bounds__(256, 2) k3_msg(
    const float* __restrict__ p, const float* __restrict__ e1,
    const float* __restrict__ x1b, const float* __restrict__ x2,
    const float* __restrict__ x2b,
    float* __restrict__ outp)
{
    extern __shared__ char sm8[];
    float* spij  = (float*)(sm8 + K3_SPIJ);
    float* snorm = (float*)(sm8 + K3_SNORM);
    float* ss    = (float*)(sm8 + K3_SS);
    float* spad  = (float*)(sm8 + K3_SPAD);
    float* sa    = (float*)(sm8 + K3_SA);
    float* se1c  = (float*)(sm8 + K3_SE1C);
    float* sx1b_ = (float*)(sm8 + K3_SX1B);
    float* sx2v  = (float*)(sm8 + K3_SX2V);

    const uint32_t sbase = smem_u32(sm8);
    const int tid = threadIdx.x, lane = tid & 31, warp = tid >> 5;
    const int n = blockIdx.x >> 7, i = blockIdx.x & 127;
    const bool pad_i = (p[(size_t)(n*128 + i)*4] == 0.0f);

    if (pad_i){
        if (tid == 0)
            *(float4*)(outp + (size_t)(n*128 + i)*4) = make_float4(0.f, 0.f, 0.f, 0.f);
        return;
    }

    const int g4 = lane & 3;
    const int rowA = warp*16 + (lane>>2), rowB = rowA + 8;

    if (tid < 128){
        int j = tid;
        float4 pi = *(const float4*)(p + (size_t)(n*128 + i)*4);
        float4 pj = *(const float4*)(p + (size_t)(n*128 + j)*4);
        float dx = pi.x - pj.x, dy = pi.y - pj.y, dz = pi.z - pj.z, dw = pi.w - pj.w;
        spij[j*4+0] = dx; spij[j*4+1] = dy; spij[j*4+2] = dz; spij[j*4+3] = dw;
        spad[j] = (pj.x != 0.0f) ? 1.0f : 0.0f;
        snorm[j] = dw*dw - dx*dx - dy*dy - dz*dz;
    }
    if (tid < 32){
        sa[tid]    = g_avec[(size_t)(n*128 + i)*32 + tid];
        se1c[tid]  = e1[tid*257 + 256];
        sx1b_[tid] = x1b[tid];
        sx2v[tid]  = x2[tid];
    }
    for (int t = tid; t < 2560; t += 256){
        ((uint32_t*)(sm8 + K3_B1H))[t] = g_e2hi[t];
        ((uint32_t*)(sm8 + K3_B1L))[t] = g_e2lo[t];
    }
    for (int t = tid; t < 2048; t += 256){
        ((uint32_t*)(sm8 + K3_B2H))[t] = g_x1hi[t];
        ((uint32_t*)(sm8 + K3_B2L))[t] = g_x1lo[t];
    }
    __syncthreads();

    // h32 tile: warp-owned rows warp*16..+15
    const float* bv = g_bvec + (size_t)n*4096;
#pragma unroll
    for (int rr = 0; rr < 8; rr++){
        int e = rr*32 + lane;
        int row = warp*16 + (e >> 4);
        int mp = e & 15, m = mp*2;
        float nb = snorm[row];
        float2 bb = *(const float2*)(bv + row*32 + m);
        float h0 = fmaxf(sa[m]   + bb.x + nb*se1c[m],   0.0f);
        float h1 = fmaxf(sa[m+1] + bb.y + nb*se1c[m+1], 0.0f);
        uint32_t hi, lo;
        split2(h0, h1, hi, lo);
        *(uint32_t*)(sm8 + K3_A1H + row*80 + mp*4) = hi;
        *(uint32_t*)(sm8 + K3_A1L + row*80 + mp*4) = lo;
    }
    __syncwarp();

    // MMA1
    float d[16][4];
    gemm32(sbase + K3_A1H, sbase + K3_A1L, sbase + K3_B1H, sbase + K3_B1L, warp, lane, d);

    // relu -> LN (registers)
    {
        float s1A = 0, s2A = 0, s1B = 0, s2B = 0;
#pragma unroll
        for (int t = 0; t < 16; t++){
            float a0 = fmaxf(d[t][0], 0.0f), a1 = fmaxf(d[t][1], 0.0f);
            float b0 = fmaxf(d[t][2], 0.0f), b1 = fmaxf(d[t][3], 0.0f);
            d[t][0] = a0; d[t][1] = a1; d[t][2] = b0; d[t][3] = b1;
            s1A += a0 + a1; s2A += a0*a0 + a1*a1;
            s1B += b0 + b1; s2B += b0*b0 + b1*b1;
        }
        s1A = qsum(s1A); s2A = qsum(s2A); s1B = qsum(s1B); s2B = qsum(s2B);
        float muA = s1A*(1.0f/128.0f), vA = s2A*(1.0f/128.0f) - muA*muA;
        float muB = s1B*(1.0f/128.0f), vB = s2B*(1.0f/128.0f) - muB*muB;
        float rsA = rsqrtf(fmaxf(vA, 0.0f) + 1e-5f);
        float rsB = rsqrtf(fmaxf(vB, 0.0f) + 1e-5f);
#pragma unroll
        for (int t = 0; t < 16; t++){
            d[t][0] = (d[t][0]-muA)*rsA; d[t][1] = (d[t][1]-muA)*rsA;
            d[t][2] = (d[t][2]-muB)*rsB; d[t][3] = (d[t][3]-muB)*rsB;
        }
    }

    // MMA2: A from registers
    float d2[4][4];
    mma2_regA(d, sbase + K3_B2H, sbase + K3_B2L, lane, d2);

    // scores
    {
        float x2bv = x2b[0];
        float sA = 0, sB = 0;
#pragma unroll
        for (int t = 0; t < 4; t++){
            int c0 = t*8 + g4*2;
            float2 xb = *(float2*)(sx1b_ + c0);
            float2 xv = *(float2*)(sx2v + c0);
            sA += fmaxf(d2[t][0] + xb.x, 0.0f)*xv.x + fmaxf(d2[t][1] + xb.y, 0.0f)*xv.y;
            sB += fmaxf(d2[t][2] + xb.x, 0.0f)*xv.x + fmaxf(d2[t][3] + xb.y, 0.0f)*xv.y;
        }
        sA = qsum(sA); sB = qsum(sB);
        if (g4 == 0){
            ss[rowA] = fmaxf(sA + x2bv, 0.0f);
            ss[rowB] = fmaxf(sB + x2bv, 0.0f);
        }
    }
    __syncthreads();

    if (warp == 0){
        float m0 = fmaxf(fmaxf(ss[lane], ss[lane+32]), fmaxf(ss[lane+64], ss[lane+96]));
#pragma unroll
        for (int k = 16; k > 0; k >>= 1) m0 = fmaxf(m0, __shfl_xor_sync(0xffffffffu, m0, k));
        float den = 0, dx = 0, dy = 0, dz = 0, dw = 0, cnt = 0;
#pragma unroll
        for (int q2 = 0; q2 < 4; q2++){
            int b = lane + 32*q2;
            float w = __expf(ss[b] - m0);
            den += w;
            dx = fmaf(w, spij[b*4+0], dx);
            dy = fmaf(w, spij[b*4+1], dy);
            dz = fmaf(w, spij[b*4+2], dz);
            dw = fmaf(w, spij[b*4+3], dw);
            cnt += spad[b];
        }
        den = wsum(den); dx = wsum(dx); dy = wsum(dy);
        dz = wsum(dz);   dw = wsum(dw); cnt = wsum(cnt);
        if (lane == 0){
            float inv = 1.0f / (den * cnt);
            const float* pr = p + (size_t)(n*128 + i)*4;
            float* o = outp + (size_t)(n*128 + i)*4;
            float d4[4] = {dx, dy, dz, dw};
#pragma unroll
            for (int dd = 0; dd < 4; dd++){
                float pv = pr[dd];
                o[dd] = (pv == 0.0f) ? 0.0f : pv + d4[dd]*inv;
            }
        }
    }
}

extern "C" void kernel_launch(void* const* d_in, const int* in_sizes, int n_in,
                              void* d_out, int out_size){
    const float* x     = (const float*)d_in[0];
    const float* p     = (const float*)d_in[1];
    const float* U     = (const float*)d_in[2];
    const float* wq    = (const float*)d_in[3];
    const float* bq    = (const float*)d_in[4];
    const float* wk    = (const float*)d_in[5];
    const float* bk    = (const float*)d_in[6];
    const float* wv    = (const float*)d_in[7];
    const float* bv    = (const float*)d_in[8];
    const float* ln1_g = (const float*)d_in[9];
    const float* ln1_b = (const float*)d_in[10];
    const float* w1    = (const float*)d_in[11];
    const float* b1    = (const float*)d_in[12];
    const float* ln2_g = (const float*)d_in[13];
    const float* ln2_b = (const float*)d_in[14];
    const float* w2    = (const float*)d_in[15];
    const float* b2    = (const float*)d_in[16];
    const float* pe1   = (const float*)d_in[17];
    const float* pe2   = (const float*)d_in[18];
    const float* e1    = (const float*)d_in[19];
    const float* e2    = (const float*)d_in[20];
    const float* x1    = (const float*)d_in[21];
    const float* x1b   = (const float*)d_in[22];
    const float* x2    = (const float*)d_in[23];
    const float* x2b   = (const float*)d_in[24];
    float* out  = (float*)d_out;
    float* xout = out;
    float* newp = out + 16*128*128;

    cudaFuncSetAttribute(k2_attn, cudaFuncAttributeMaxDynamicSharedMemorySize, K2_SMEM);
    cudaFuncSetAttribute(k3_msg,  cudaFuncAttributeMaxDynamicSharedMemorySize, K3_SMEM);

    k0_prep<<<64, 256>>>(wq, wk, wv, w1, w2, pe2, e2, x1);
    k1_qkv<<<2048, 128>>>(x, bq, bk, bv);
    k2_attn<<<2048, 512, K2_SMEM>>>(U, p, ln1_g, ln1_b, b1, ln2_g, ln2_b, b2, pe1, e1, xout);
    k3_msg<<<2048, 256, K3_SMEM>>>(p, e1, x1b, x2, x2b, newp);
}